// round 8
// baseline (speedup 1.0000x reference)
#include <cuda_runtime.h>
#include <cstdint>

#define NN 10000
#define EE 300000
#define WD 32
#define DEPTH 4
#define ACOLS 8224           // 8192 (A) + 32 (bias part)
#define KST 260              // k2 smem row stride (float4-aligned, conflict-free)
#define MST 36               // m smem row stride
#define HST 68               // Hs stride: multiple of 4 (float4-aligned)

// ---------------- scratch (static __device__) ----------------
__device__ __align__(16) float g_K2[EE * 256];          // relu MLP out, PERMUTED by col-bucket
__device__ __align__(16) float g_A[NN * ACOLS];         // per-node A|bias
__device__ __align__(16) float g_AW[32 * ACOLS];        // transposed ker3 weights
__device__ __align__(16) float g_H[NN * WD];
__device__ __align__(16) float g_AGG[NN * WD];
__device__ __align__(16) float g_COORD[NN * 3];
__device__ __align__(16) float g_CD[NN * 3];
__device__ float g_CNT[NN];
__device__ int   g_colcnt[NN];
__device__ int   g_rowcnt[NN];
__device__ int   g_coloff[NN + 1];
__device__ int   g_cur[NN];
__device__ int   g_pos[EE];     // edge -> sorted position
__device__ int   g_rows[EE];    // sorted position -> row node

// ---------------- setup ----------------
__global__ void k_init(const float* __restrict__ x, const float* __restrict__ coords,
                       const float* __restrict__ fc1w, const float* __restrict__ fc1b) {
    int i = blockIdx.x * blockDim.x + threadIdx.x;
    if (i < NN * 3) g_COORD[i] = coords[i];
    if (i < NN * WD) {
        int n = i / WD, o = i % WD;
        float a = fc1b[o];
        #pragma unroll
        for (int j = 0; j < 3; j++) a += x[n * 3 + j] * fc1w[j * WD + o];
        g_H[i] = a;
    }
}

__global__ void k_hist(const int* __restrict__ ei) {
    int e = blockIdx.x * blockDim.x + threadIdx.x;
    if (e < EE) {
        atomicAdd(&g_rowcnt[ei[e]], 1);
        atomicAdd(&g_colcnt[ei[EE + e]], 1);
    }
}

// scan over colcnt -> coloff/cur; also CNT from rowcnt (moved here from k_init)
__global__ void k_scan() {
    __shared__ int sh[1024];
    __shared__ int carry;
    int t = threadIdx.x;
    if (t == 0) carry = 0;
    __syncthreads();
    for (int base = 0; base < NN; base += 1024) {
        int v = (base + t < NN) ? g_colcnt[base + t] : 0;
        sh[t] = v;
        __syncthreads();
        for (int off = 1; off < 1024; off <<= 1) {
            int y = (t >= off) ? sh[t - off] : 0;
            __syncthreads();
            sh[t] += y;
            __syncthreads();
        }
        int incl = sh[t];
        if (base + t < NN) {
            int ex = carry + incl - v;
            g_coloff[base + t] = ex;
            g_cur[base + t] = ex;
            g_CNT[base + t] = fmaxf(1.f, (float)g_rowcnt[base + t]);
        }
        int tot = sh[1023];
        __syncthreads();
        if (t == 0) carry += tot;
        __syncthreads();
    }
    if (t == 0) g_coloff[NN] = carry;
}

__global__ void k_scatter(const int* __restrict__ ei) {
    int e = blockIdx.x * blockDim.x + threadIdx.x;
    if (e < EE) {
        int r = ei[e], c = ei[EE + e];
        int p = atomicAdd(&g_cur[c], 1);
        g_pos[e] = p;
        g_rows[p] = r;
    }
}

__global__ void k_cleanup() {
    int i = blockIdx.x * blockDim.x + threadIdx.x;
    if (i < NN) { g_colcnt[i] = 0; g_rowcnt[i] = 0; }
}

// ---------------- fused kernel MLP: K2 = relu(relu(ea@W1+b1)@W2+b2), permuted write ----
// Double-buffered B stages: one sync per k-step, loads overlap compute.
__global__ void __launch_bounds__(256) k_gemm2(const float* __restrict__ ea,
                                               const float* __restrict__ w1,
                                               const float* __restrict__ b1,
                                               const float* __restrict__ w2,
                                               const float* __restrict__ b2) {
    extern __shared__ float s2[];
    float* R1t = s2;                 // [128][64] k-major
    float* Bs0 = s2 + 8192;          // [16][256] stage 0
    float* Bs1 = s2 + 8192 + 4096;   // [16][256] stage 1
    __shared__ float eas[64 * 6];
    __shared__ float w1s[6 * 128];
    __shared__ float b1s[128];
    int tid = threadIdx.x;
    int m0 = blockIdx.x * 64;

    for (int i = tid; i < 64 * 6; i += 256) {
        int g = m0 * 6 + i;
        eas[i] = (g < EE * 6) ? ea[g] : 0.f;
    }
    for (int i = tid; i < 768; i += 256) w1s[i] = w1[i];
    if (tid < 128) b1s[tid] = b1[tid];
    // preload B stage 0 (independent of eas/w1s)
    {
        int idx0 = tid;
        #pragma unroll
        for (int i = 0; i < 4; i++) {
            int idx = idx0 + i * 256;
            int kk = idx >> 6, c4 = idx & 63;
            *(float4*)&Bs0[kk * 256 + c4 * 4] = *(const float4*)&w2[kk * 256 + c4 * 4];
        }
    }
    __syncthreads();

    // R1 tile: thread handles row r = tid&63, k-group tid>>6 (32 k's)
    {
        int r = tid & 63, kg = tid >> 6;
        float ev[6];
        #pragma unroll
        for (int j = 0; j < 6; j++) ev[j] = eas[r * 6 + j];
        #pragma unroll
        for (int q = 0; q < 32; q++) {
            int k = kg * 32 + q;
            float a = b1s[k];
            #pragma unroll
            for (int j = 0; j < 6; j++) a += ev[j] * w1s[j * 128 + k];
            R1t[k * 64 + r] = fmaxf(a, 0.f);
        }
    }
    __syncthreads();

    int tx = tid & 31, ty = tid >> 5;
    int r0 = ty * 4, r1 = 32 + ty * 4;       // row groups
    int c0 = tx * 4, c1 = 128 + tx * 4;      // col groups
    float acc[8][8];
    #pragma unroll
    for (int i = 0; i < 8; i++)
        #pragma unroll
        for (int j = 0; j < 8; j++) acc[i][j] = 0.f;

    #pragma unroll
    for (int step = 0; step < 8; step++) {
        float* cur = (step & 1) ? Bs1 : Bs0;
        float* nxt = (step & 1) ? Bs0 : Bs1;
        if (step < 7) {
            int kcn = (step + 1) * 16;
            #pragma unroll
            for (int i = 0; i < 4; i++) {
                int idx = tid + i * 256;
                int kk = idx >> 6, c4 = idx & 63;
                *(float4*)&nxt[kk * 256 + c4 * 4] =
                    *(const float4*)&w2[(kcn + kk) * 256 + c4 * 4];
            }
        }
        int kc = step * 16;
        #pragma unroll
        for (int kk = 0; kk < 16; kk++) {
            float a[8], b[8];
            *(float4*)a       = *(float4*)&R1t[(kc + kk) * 64 + r0];
            *(float4*)(a + 4) = *(float4*)&R1t[(kc + kk) * 64 + r1];
            *(float4*)b       = *(float4*)&cur[kk * 256 + c0];
            *(float4*)(b + 4) = *(float4*)&cur[kk * 256 + c1];
            #pragma unroll
            for (int i = 0; i < 8; i++)
                #pragma unroll
                for (int j = 0; j < 8; j++) acc[i][j] += a[i] * b[j];
        }
        __syncthreads();
    }
    float bb[8];
    #pragma unroll
    for (int j = 0; j < 4; j++) { bb[j] = b2[c0 + j]; bb[4 + j] = b2[c1 + j]; }
    #pragma unroll
    for (int half = 0; half < 2; half++) {
        int rbase = (half == 0) ? r0 : r1;
        #pragma unroll
        for (int i = 0; i < 4; i++) {
            int e = m0 + rbase + i;
            if (e >= EE) continue;
            int pos = g_pos[e];
            int ai = half * 4 + i;
            float o[8];
            #pragma unroll
            for (int j = 0; j < 8; j++) o[j] = fmaxf(acc[ai][j] + bb[j], 0.f);
            *(float4*)&g_K2[pos * 256 + c0] = *(float4*)o;
            *(float4*)&g_K2[pos * 256 + c1] = *(float4*)(o + 4);
        }
    }
}

// AW[j][c*32+i] = ker3_w[c][i*32+j]; AW[j][8192+i] = ker3_b[i*32+j]
__global__ void k_aw(const float* __restrict__ w3, const float* __restrict__ b3) {
    int idx = blockIdx.x * blockDim.x + threadIdx.x;
    if (idx >= 32 * ACOLS) return;
    int j = idx / ACOLS, r = idx % ACOLS;
    if (r < 8192) {
        int c = r >> 5, i = r & 31;
        g_AW[idx] = w3[c * 1024 + i * 32 + j];
    } else {
        int i = r - 8192;
        g_AW[idx] = b3[i * 32 + j];
    }
}

// A = H @ AW   [N,32]@[32,8224] — 64x256 tile, conflict-free thread tiling
__global__ void __launch_bounds__(256) k_gemmA() {
    __shared__ float Hs[32 * HST];    // [k][node], stride 68 (float4-aligned)
    __shared__ float AWs[32 * 256];
    int tid = threadIdx.x;
    int m0 = blockIdx.y * 64;
    int n0 = blockIdx.x * 256;
    for (int i = tid; i < 2048; i += 256) {
        int node = i >> 5, k = i & 31;
        Hs[k * HST + node] = (m0 + node < NN) ? g_H[(m0 + node) * 32 + k] : 0.f;
    }
    const float4* AWf4 = (const float4*)g_AW;
    #pragma unroll
    for (int i = 0; i < 8; i++) {
        int idx = tid + i * 256;
        int kk = idx >> 6, c4 = idx & 63;
        int col = n0 + c4 * 4;
        float4 v = make_float4(0.f, 0.f, 0.f, 0.f);
        if (col < ACOLS) v = AWf4[kk * (ACOLS / 4) + (n0 >> 2) + c4];
        *(float4*)&AWs[kk * 256 + c4 * 4] = v;
    }
    __syncthreads();
    int tx = tid & 31, ty = tid >> 5;
    int r0 = ty * 4, r1 = 32 + ty * 4;
    int c0 = tx * 4, c1 = 128 + tx * 4;
    float acc[8][8];
    #pragma unroll
    for (int i = 0; i < 8; i++)
        #pragma unroll
        for (int j = 0; j < 8; j++) acc[i][j] = 0.f;
    #pragma unroll
    for (int kk = 0; kk < 32; kk++) {
        float a[8], b[8];
        *(float4*)a       = *(float4*)&Hs[kk * HST + r0];
        *(float4*)(a + 4) = *(float4*)&Hs[kk * HST + r1];
        *(float4*)b       = *(float4*)&AWs[kk * 256 + c0];
        *(float4*)(b + 4) = *(float4*)&AWs[kk * 256 + c1];
        #pragma unroll
        for (int i = 0; i < 8; i++)
            #pragma unroll
            for (int j = 0; j < 8; j++) acc[i][j] += a[i] * b[j];
    }
    #pragma unroll
    for (int half = 0; half < 2; half++) {
        int rbase = (half == 0) ? r0 : r1;
        #pragma unroll
        for (int i = 0; i < 4; i++) {
            int node = m0 + rbase + i;
            if (node >= NN) continue;
            int ai = half * 4 + i;
            if (n0 + c0 < ACOLS)
                *(float4*)&g_A[node * ACOLS + n0 + c0] = *(float4*)acc[ai];
            if (n0 + c1 < ACOLS)
                *(float4*)&g_A[node * ACOLS + n0 + c1] = *(float4*)(acc[ai] + 4);
        }
    }
}

// fused M + coord-MLP + scatter: per col-bucket node (K2 staged once in smem)
__global__ void __launch_bounds__(128) k_m(const float* __restrict__ cm1w,
                                           const float* __restrict__ cm1b,
                                           const float* __restrict__ cm2w,
                                           const float* __restrict__ cm2b) {
    extern __shared__ float sm[];
    float* As = sm;                  // ACOLS
    float* Ks = sm + ACOLS;          // 32*KST
    float* Ms = Ks + 32 * KST;       // 32*MST
    __shared__ float c1s[1024];
    __shared__ float c1bs[32], c2s[32];
    __shared__ float cn[3];
    __shared__ float cm2bv;
    int n = blockIdx.x;
    int beg = g_coloff[n];
    int nE = g_coloff[n + 1] - beg;
    if (nE == 0) return;
    int tid = threadIdx.x;
    for (int i = tid; i < 1024; i += 128) c1s[i] = cm1w[i];
    if (tid < 32) { c1bs[tid] = cm1b[tid]; c2s[tid] = cm2w[tid]; }
    if (tid < 3) cn[tid] = g_COORD[n * 3 + tid];
    if (tid == 4) cm2bv = cm2b[0];
    const float4* Af4 = (const float4*)&g_A[n * ACOLS];
    for (int i = tid; i < ACOLS / 4; i += 128) ((float4*)As)[i] = Af4[i];
    int colgrp = tid & 3, eslot = tid >> 2;
    int lane = tid & 31, wrp = tid >> 5;

    for (int base = 0; base < nE; base += 32) {
        int cnt = min(32, nE - base);
        const float4* Kf4 = (const float4*)&g_K2[(size_t)(beg + base) * 256];
        for (int i = tid; i < cnt * 64; i += 128) {
            int el = i >> 6, c4 = i & 63;
            *(float4*)&Ks[el * KST + c4 * 4] = Kf4[i];
        }
        __syncthreads();
        if (eslot < cnt) {
            float acc[8];
            *(float4*)acc       = *(float4*)&As[8192 + colgrp * 8];
            *(float4*)(acc + 4) = *(float4*)&As[8192 + colgrp * 8 + 4];
            const float4* kr4 = (const float4*)&Ks[eslot * KST];
            #pragma unroll 8
            for (int c4i = 0; c4i < 64; c4i++) {
                float4 kv = kr4[c4i];
                #pragma unroll
                for (int q = 0; q < 4; q++) {
                    float kq = (q == 0) ? kv.x : (q == 1) ? kv.y : (q == 2) ? kv.z : kv.w;
                    float4 a0 = *(float4*)&As[(c4i * 4 + q) * 32 + colgrp * 8];
                    float4 a1 = *(float4*)&As[(c4i * 4 + q) * 32 + colgrp * 8 + 4];
                    acc[0] += kq * a0.x; acc[1] += kq * a0.y;
                    acc[2] += kq * a0.z; acc[3] += kq * a0.w;
                    acc[4] += kq * a1.x; acc[5] += kq * a1.y;
                    acc[6] += kq * a1.z; acc[7] += kq * a1.w;
                }
            }
            *(float4*)&Ms[eslot * MST + colgrp * 8]     = *(float4*)acc;
            *(float4*)&Ms[eslot * MST + colgrp * 8 + 4] = *(float4*)(acc + 4);
        }
        __syncthreads();
        // MLP + scatter: 4 warps x 8 edges
        #pragma unroll 2
        for (int q = 0; q < 8; q++) {
            int es_ = wrp * 8 + q;
            if (es_ < cnt) {
                float mv = Ms[es_ * MST + lane];
                float t = c1bs[lane];
                #pragma unroll
                for (int j = 0; j < 32; j++)
                    t += __shfl_sync(0xffffffffu, mv, j) * c1s[j * 32 + lane];
                t = fmaxf(t, 0.f);
                float p = t * c2s[lane];
                #pragma unroll
                for (int off = 16; off > 0; off >>= 1)
                    p += __shfl_xor_sync(0xffffffffu, p, off);
                float we = p + cm2bv;
                int row = g_rows[beg + base + es_];
                atomicAdd(&g_AGG[row * 32 + lane], mv);
                if (lane < 3) {
                    float d = g_COORD[row * 3 + lane] - cn[lane];
                    atomicAdd(&g_CD[row * 3 + lane], d * we);
                }
            }
        }
        __syncthreads();
    }
}

__global__ void k_update() {
    int i = blockIdx.x * blockDim.x + threadIdx.x;
    if (i < NN * WD) {
        int n = i >> 5;
        float inv = 1.f / g_CNT[n];
        g_H[i] = fmaxf(g_H[i] + g_AGG[i] * inv, 0.f);
        g_AGG[i] = 0.f;
    }
    if (i < NN * 3) {
        int n = i / 3;
        g_COORD[i] += g_CD[i] / g_CNT[n];
        g_CD[i] = 0.f;
    }
}

__global__ void k_final(const float* __restrict__ f2aw, const float* __restrict__ f2ab,
                        const float* __restrict__ f2bw, const float* __restrict__ f2bb,
                        float* __restrict__ out) {
    __shared__ float wa[2048];
    __shared__ float ba[64];
    __shared__ float wb[64];
    int tid = threadIdx.x;
    for (int i = tid; i < 2048; i += 256) wa[i] = f2aw[i];
    if (tid < 64) { ba[tid] = f2ab[tid]; wb[tid] = f2bw[tid]; }
    __syncthreads();
    int n = blockIdx.x * blockDim.x + tid;
    if (n < NN) {
        float h[32];
        #pragma unroll
        for (int j = 0; j < 32; j++) h[j] = g_H[n * 32 + j];
        float o = f2bb[0];
        #pragma unroll 4
        for (int u = 0; u < 64; u++) {
            float s = ba[u];
            #pragma unroll
            for (int j = 0; j < 32; j++) s += h[j] * wa[j * 64 + u];
            o += fmaxf(s, 0.f) * wb[u];
        }
        out[n] = o;
    }
    int tot = gridDim.x * blockDim.x;
    for (int i = n; i < NN * 3; i += tot) out[NN + i] = g_COORD[i];
}

// ---------------- host ----------------
extern "C" void kernel_launch(void* const* d_in, const int* in_sizes, int n_in,
                              void* d_out, int out_size) {
    const float* x      = (const float*)d_in[0];
    const int*   ei     = (const int*)d_in[1];     // int32 (JAX x64 disabled)
    const float* ea     = (const float*)d_in[2];
    const float* coords = (const float*)d_in[3];
    const float* fc1w   = (const float*)d_in[4];
    const float* fc1b   = (const float*)d_in[5];
    const float* k1w    = (const float*)d_in[6];
    const float* k1b    = (const float*)d_in[7];
    const float* k2w    = (const float*)d_in[8];
    const float* k2b    = (const float*)d_in[9];
    const float* k3w    = (const float*)d_in[10];
    const float* k3b    = (const float*)d_in[11];
    const float* cm1w   = (const float*)d_in[12];
    const float* cm1b   = (const float*)d_in[13];
    const float* cm2w   = (const float*)d_in[14];
    const float* cm2b   = (const float*)d_in[15];
    const float* f2aw   = (const float*)d_in[16];
    const float* f2ab   = (const float*)d_in[17];
    const float* f2bw   = (const float*)d_in[18];
    const float* f2bb   = (const float*)d_in[19];

    const int smemM  = (ACOLS + 32 * KST + 32 * MST) * 4;   // 70784 B
    const int smemG2 = (8192 + 2 * 4096) * 4;               // 65536 B
    cudaFuncSetAttribute(k_m, cudaFuncAttributeMaxDynamicSharedMemorySize, smemM);
    cudaFuncSetAttribute(k_gemm2, cudaFuncAttributeMaxDynamicSharedMemorySize, smemG2);

    // launch order chosen so slot 4 = k_gemmA (profiler capture target)
    k_init<<<(NN * WD + 255) / 256, 256>>>(x, coords, fc1w, fc1b);      // 1
    k_aw<<<(32 * ACOLS + 255) / 256, 256>>>(k3w, k3b);                  // 2
    k_hist<<<(EE + 255) / 256, 256>>>(ei);                              // 3
    k_gemmA<<<dim3((ACOLS + 255) / 256, (NN + 63) / 64), 256>>>();      // 4 (layer-0 A)
    k_scan<<<1, 1024>>>();                                              // 5
    k_scatter<<<(EE + 255) / 256, 256>>>(ei);                           // 6
    k_gemm2<<<(EE + 63) / 64, 256, smemG2>>>(ea, k1w, k1b, k2w, k2b);   // 7

    for (int d = 0; d < DEPTH; d++) {
        if (d > 0)
            k_gemmA<<<dim3((ACOLS + 255) / 256, (NN + 63) / 64), 256>>>();
        k_m<<<NN, 128, smemM>>>(cm1w, cm1b, cm2w, cm2b);
        k_update<<<(NN * WD + 255) / 256, 256>>>();
    }
    k_final<<<(NN + 255) / 256, 256>>>(f2aw, f2ab, f2bw, f2bb, (float*)d_out);
    k_cleanup<<<(NN + 255) / 256, 256>>>();
}

// round 9
// speedup vs baseline: 1.0622x; 1.0622x over previous
#include <cuda_runtime.h>
#include <cstdint>

#define NN 10000
#define EE 300000
#define WD 32
#define DEPTH 4
#define ACOLS 8224           // 8192 (A) + 32 (bias part)
#define KST 260              // k2 smem row stride (float4-aligned, conflict-free)
#define MST 36               // m smem row stride
#define HST 68               // Hs stride: multiple of 4 (float4-aligned)
#define NBLK 296             // persistent k_m blocks (2 per SM x 148)

// ---------------- scratch (static __device__) ----------------
__device__ __align__(16) float g_K2[EE * 256];          // relu MLP out, PERMUTED by col-bucket
__device__ __align__(16) float g_A[NN * ACOLS];         // per-node A|bias
__device__ __align__(16) float g_AW[32 * ACOLS];        // transposed ker3 weights
__device__ __align__(16) float g_H[NN * WD];
__device__ __align__(16) float g_AGG[NN * WD];
__device__ __align__(16) float g_COORD[NN * 3];
__device__ __align__(16) float g_CD[NN * 3];
__device__ float g_CNT[NN];
__device__ int   g_colcnt[NN];
__device__ int   g_rowcnt[NN];
__device__ int   g_coloff[NN + 1];
__device__ int   g_cur[NN];
__device__ int   g_pos[EE];     // edge -> sorted position
__device__ int   g_rows[EE];    // sorted position -> row node

__device__ __forceinline__ void cpa16(float* smem_dst, const float4* gsrc) {
    unsigned s = (unsigned)__cvta_generic_to_shared(smem_dst);
    asm volatile("cp.async.cg.shared.global [%0], [%1], 16;\n" :: "r"(s), "l"(gsrc));
}
__device__ __forceinline__ void cpa_commit() { asm volatile("cp.async.commit_group;\n"); }
__device__ __forceinline__ void cpa_wait0()  { asm volatile("cp.async.wait_group 0;\n"); }

// ---------------- setup ----------------
__global__ void k_init(const float* __restrict__ x, const float* __restrict__ coords,
                       const float* __restrict__ fc1w, const float* __restrict__ fc1b) {
    int i = blockIdx.x * blockDim.x + threadIdx.x;
    if (i < NN * 3) g_COORD[i] = coords[i];
    if (i < NN * WD) {
        int n = i / WD, o = i % WD;
        float a = fc1b[o];
        #pragma unroll
        for (int j = 0; j < 3; j++) a += x[n * 3 + j] * fc1w[j * WD + o];
        g_H[i] = a;
    }
}

__global__ void k_hist(const int* __restrict__ ei) {
    int e = blockIdx.x * blockDim.x + threadIdx.x;
    if (e < EE) {
        atomicAdd(&g_rowcnt[ei[e]], 1);
        atomicAdd(&g_colcnt[ei[EE + e]], 1);
    }
}

// scan over colcnt -> coloff/cur; also CNT from rowcnt
__global__ void k_scan() {
    __shared__ int sh[1024];
    __shared__ int carry;
    int t = threadIdx.x;
    if (t == 0) carry = 0;
    __syncthreads();
    for (int base = 0; base < NN; base += 1024) {
        int v = (base + t < NN) ? g_colcnt[base + t] : 0;
        sh[t] = v;
        __syncthreads();
        for (int off = 1; off < 1024; off <<= 1) {
            int y = (t >= off) ? sh[t - off] : 0;
            __syncthreads();
            sh[t] += y;
            __syncthreads();
        }
        int incl = sh[t];
        if (base + t < NN) {
            int ex = carry + incl - v;
            g_coloff[base + t] = ex;
            g_cur[base + t] = ex;
            g_CNT[base + t] = fmaxf(1.f, (float)g_rowcnt[base + t]);
        }
        int tot = sh[1023];
        __syncthreads();
        if (t == 0) carry += tot;
        __syncthreads();
    }
    if (t == 0) g_coloff[NN] = carry;
}

__global__ void k_scatter(const int* __restrict__ ei) {
    int e = blockIdx.x * blockDim.x + threadIdx.x;
    if (e < EE) {
        int r = ei[e], c = ei[EE + e];
        int p = atomicAdd(&g_cur[c], 1);
        g_pos[e] = p;
        g_rows[p] = r;
    }
}

__global__ void k_cleanup() {
    int i = blockIdx.x * blockDim.x + threadIdx.x;
    if (i < NN) { g_colcnt[i] = 0; g_rowcnt[i] = 0; }
}

// ---------------- fused kernel MLP: K2 = relu(relu(ea@W1+b1)@W2+b2), permuted write ----
// Double-buffered B stages.
__global__ void __launch_bounds__(256) k_gemm2(const float* __restrict__ ea,
                                               const float* __restrict__ w1,
                                               const float* __restrict__ b1,
                                               const float* __restrict__ w2,
                                               const float* __restrict__ b2) {
    extern __shared__ float s2[];
    float* R1t = s2;                 // [128][64] k-major
    float* Bs0 = s2 + 8192;          // [16][256] stage 0
    float* Bs1 = s2 + 8192 + 4096;   // [16][256] stage 1
    __shared__ float eas[64 * 6];
    __shared__ float w1s[6 * 128];
    __shared__ float b1s[128];
    int tid = threadIdx.x;
    int m0 = blockIdx.x * 64;

    for (int i = tid; i < 64 * 6; i += 256) {
        int g = m0 * 6 + i;
        eas[i] = (g < EE * 6) ? ea[g] : 0.f;
    }
    for (int i = tid; i < 768; i += 256) w1s[i] = w1[i];
    if (tid < 128) b1s[tid] = b1[tid];
    {
        #pragma unroll
        for (int i = 0; i < 4; i++) {
            int idx = tid + i * 256;
            int kk = idx >> 6, c4 = idx & 63;
            *(float4*)&Bs0[kk * 256 + c4 * 4] = *(const float4*)&w2[kk * 256 + c4 * 4];
        }
    }
    __syncthreads();

    {
        int r = tid & 63, kg = tid >> 6;
        float ev[6];
        #pragma unroll
        for (int j = 0; j < 6; j++) ev[j] = eas[r * 6 + j];
        #pragma unroll
        for (int q = 0; q < 32; q++) {
            int k = kg * 32 + q;
            float a = b1s[k];
            #pragma unroll
            for (int j = 0; j < 6; j++) a += ev[j] * w1s[j * 128 + k];
            R1t[k * 64 + r] = fmaxf(a, 0.f);
        }
    }
    __syncthreads();

    int tx = tid & 31, ty = tid >> 5;
    int r0 = ty * 4, r1 = 32 + ty * 4;
    int c0 = tx * 4, c1 = 128 + tx * 4;
    float acc[8][8];
    #pragma unroll
    for (int i = 0; i < 8; i++)
        #pragma unroll
        for (int j = 0; j < 8; j++) acc[i][j] = 0.f;

    #pragma unroll
    for (int step = 0; step < 8; step++) {
        float* cur = (step & 1) ? Bs1 : Bs0;
        float* nxt = (step & 1) ? Bs0 : Bs1;
        if (step < 7) {
            int kcn = (step + 1) * 16;
            #pragma unroll
            for (int i = 0; i < 4; i++) {
                int idx = tid + i * 256;
                int kk = idx >> 6, c4 = idx & 63;
                *(float4*)&nxt[kk * 256 + c4 * 4] =
                    *(const float4*)&w2[(kcn + kk) * 256 + c4 * 4];
            }
        }
        int kc = step * 16;
        #pragma unroll
        for (int kk = 0; kk < 16; kk++) {
            float a[8], b[8];
            *(float4*)a       = *(float4*)&R1t[(kc + kk) * 64 + r0];
            *(float4*)(a + 4) = *(float4*)&R1t[(kc + kk) * 64 + r1];
            *(float4*)b       = *(float4*)&cur[kk * 256 + c0];
            *(float4*)(b + 4) = *(float4*)&cur[kk * 256 + c1];
            #pragma unroll
            for (int i = 0; i < 8; i++)
                #pragma unroll
                for (int j = 0; j < 8; j++) acc[i][j] += a[i] * b[j];
        }
        __syncthreads();
    }
    float bb[8];
    #pragma unroll
    for (int j = 0; j < 4; j++) { bb[j] = b2[c0 + j]; bb[4 + j] = b2[c1 + j]; }
    #pragma unroll
    for (int half = 0; half < 2; half++) {
        int rbase = (half == 0) ? r0 : r1;
        #pragma unroll
        for (int i = 0; i < 4; i++) {
            int e = m0 + rbase + i;
            if (e >= EE) continue;
            int pos = g_pos[e];
            int ai = half * 4 + i;
            float o[8];
            #pragma unroll
            for (int j = 0; j < 8; j++) o[j] = fmaxf(acc[ai][j] + bb[j], 0.f);
            *(float4*)&g_K2[pos * 256 + c0] = *(float4*)o;
            *(float4*)&g_K2[pos * 256 + c1] = *(float4*)(o + 4);
        }
    }
}

// AW[j][c*32+i] = ker3_w[c][i*32+j]; AW[j][8192+i] = ker3_b[i*32+j]
__global__ void k_aw(const float* __restrict__ w3, const float* __restrict__ b3) {
    int idx = blockIdx.x * blockDim.x + threadIdx.x;
    if (idx >= 32 * ACOLS) return;
    int j = idx / ACOLS, r = idx % ACOLS;
    if (r < 8192) {
        int c = r >> 5, i = r & 31;
        g_AW[idx] = w3[c * 1024 + i * 32 + j];
    } else {
        int i = r - 8192;
        g_AW[idx] = b3[i * 32 + j];
    }
}

// A = H @ AW   [N,32]@[32,8224] — 64x256 tile, conflict-free thread tiling
__global__ void __launch_bounds__(256) k_gemmA() {
    __shared__ float Hs[32 * HST];
    __shared__ float AWs[32 * 256];
    int tid = threadIdx.x;
    int m0 = blockIdx.y * 64;
    int n0 = blockIdx.x * 256;
    for (int i = tid; i < 2048; i += 256) {
        int node = i >> 5, k = i & 31;
        Hs[k * HST + node] = (m0 + node < NN) ? g_H[(m0 + node) * 32 + k] : 0.f;
    }
    const float4* AWf4 = (const float4*)g_AW;
    #pragma unroll
    for (int i = 0; i < 8; i++) {
        int idx = tid + i * 256;
        int kk = idx >> 6, c4 = idx & 63;
        int col = n0 + c4 * 4;
        float4 v = make_float4(0.f, 0.f, 0.f, 0.f);
        if (col < ACOLS) v = AWf4[kk * (ACOLS / 4) + (n0 >> 2) + c4];
        *(float4*)&AWs[kk * 256 + c4 * 4] = v;
    }
    __syncthreads();
    int tx = tid & 31, ty = tid >> 5;
    int r0 = ty * 4, r1 = 32 + ty * 4;
    int c0 = tx * 4, c1 = 128 + tx * 4;
    float acc[8][8];
    #pragma unroll
    for (int i = 0; i < 8; i++)
        #pragma unroll
        for (int j = 0; j < 8; j++) acc[i][j] = 0.f;
    #pragma unroll
    for (int kk = 0; kk < 32; kk++) {
        float a[8], b[8];
        *(float4*)a       = *(float4*)&Hs[kk * HST + r0];
        *(float4*)(a + 4) = *(float4*)&Hs[kk * HST + r1];
        *(float4*)b       = *(float4*)&AWs[kk * 256 + c0];
        *(float4*)(b + 4) = *(float4*)&AWs[kk * 256 + c1];
        #pragma unroll
        for (int i = 0; i < 8; i++)
            #pragma unroll
            for (int j = 0; j < 8; j++) acc[i][j] += a[i] * b[j];
    }
    #pragma unroll
    for (int half = 0; half < 2; half++) {
        int rbase = (half == 0) ? r0 : r1;
        #pragma unroll
        for (int i = 0; i < 4; i++) {
            int node = m0 + rbase + i;
            if (node >= NN) continue;
            int ai = half * 4 + i;
            if (n0 + c0 < ACOLS)
                *(float4*)&g_A[node * ACOLS + n0 + c0] = *(float4*)acc[ai];
            if (n0 + c1 < ACOLS)
                *(float4*)&g_A[node * ACOLS + n0 + c1] = *(float4*)(acc[ai] + 4);
        }
    }
}

// persistent fused M + coord-MLP + scatter: each block owns an edge-balanced
// contiguous node range; A slabs double-buffered via cp.async.
__global__ void __launch_bounds__(128) k_m(const float* __restrict__ cm1w,
                                           const float* __restrict__ cm1b,
                                           const float* __restrict__ cm2w,
                                           const float* __restrict__ cm2b) {
    extern __shared__ float sm[];
    float* A0 = sm;                  // ACOLS
    float* A1 = sm + ACOLS;          // ACOLS
    float* Ks = sm + 2 * ACOLS;      // 32*KST
    float* Ms = Ks + 32 * KST;       // 32*MST
    __shared__ float c1s[1024];
    __shared__ float c1bs[32], c2s[32];
    __shared__ float cm2bv;
    __shared__ int nsS, neS;
    int tid = threadIdx.x;
    int b = blockIdx.x;
    if (tid == 0) {
        long long t1 = (long long)b * EE;
        int lo = 0, hi = NN;
        while (lo < hi) {
            int mid = (lo + hi) >> 1;
            if ((long long)g_coloff[mid] * NBLK >= t1) hi = mid; else lo = mid + 1;
        }
        nsS = lo;
        long long t2 = (long long)(b + 1) * EE;
        hi = NN;
        while (lo < hi) {
            int mid = (lo + hi) >> 1;
            if ((long long)g_coloff[mid] * NBLK >= t2) hi = mid; else lo = mid + 1;
        }
        neS = lo;
        cm2bv = cm2b[0];
    }
    for (int i = tid; i < 1024; i += 128) c1s[i] = cm1w[i];
    if (tid < 32) { c1bs[tid] = cm1b[tid]; c2s[tid] = cm2w[tid]; }
    __syncthreads();
    int ns = nsS, ne = neS;
    if (ns >= ne) return;

    // preload first A slab
    {
        const float4* src = (const float4*)&g_A[(size_t)ns * ACOLS];
        for (int i = tid; i < ACOLS / 4; i += 128) cpa16(&A0[i * 4], src + i);
        cpa_commit();
        cpa_wait0();
    }
    __syncthreads();

    float* cur = A0;
    float* nxt = A1;
    int colgrp = tid & 3, eslot = tid >> 2;
    int lane = tid & 31, wrp = tid >> 5;

    for (int n = ns; n < ne; n++) {
        if (n + 1 < ne) {
            const float4* src = (const float4*)&g_A[(size_t)(n + 1) * ACOLS];
            for (int i = tid; i < ACOLS / 4; i += 128) cpa16(&nxt[i * 4], src + i);
            cpa_commit();
        }
        int beg = g_coloff[n];
        int nE = g_coloff[n + 1] - beg;

        for (int base = 0; base < nE; base += 32) {
            int cnt = min(32, nE - base);
            const float4* Kf4 = (const float4*)&g_K2[(size_t)(beg + base) * 256];
            for (int i = tid; i < cnt * 64; i += 128) {
                int el = i >> 6, c4 = i & 63;
                *(float4*)&Ks[el * KST + c4 * 4] = Kf4[i];
            }
            __syncthreads();
            if (eslot < cnt) {
                float acc[8];
                *(float4*)acc       = *(float4*)&cur[8192 + colgrp * 8];
                *(float4*)(acc + 4) = *(float4*)&cur[8192 + colgrp * 8 + 4];
                const float4* kr4 = (const float4*)&Ks[eslot * KST];
                #pragma unroll 8
                for (int c4i = 0; c4i < 64; c4i++) {
                    float4 kv = kr4[c4i];
                    #pragma unroll
                    for (int q = 0; q < 4; q++) {
                        float kq = (q == 0) ? kv.x : (q == 1) ? kv.y : (q == 2) ? kv.z : kv.w;
                        float4 a0 = *(float4*)&cur[(c4i * 4 + q) * 32 + colgrp * 8];
                        float4 a1 = *(float4*)&cur[(c4i * 4 + q) * 32 + colgrp * 8 + 4];
                        acc[0] += kq * a0.x; acc[1] += kq * a0.y;
                        acc[2] += kq * a0.z; acc[3] += kq * a0.w;
                        acc[4] += kq * a1.x; acc[5] += kq * a1.y;
                        acc[6] += kq * a1.z; acc[7] += kq * a1.w;
                    }
                }
                *(float4*)&Ms[eslot * MST + colgrp * 8]     = *(float4*)acc;
                *(float4*)&Ms[eslot * MST + colgrp * 8 + 4] = *(float4*)(acc + 4);
            }
            __syncthreads();
            #pragma unroll 2
            for (int q = 0; q < 8; q++) {
                int es_ = wrp * 8 + q;
                if (es_ < cnt) {
                    float mv = Ms[es_ * MST + lane];
                    float t = c1bs[lane];
                    #pragma unroll
                    for (int j = 0; j < 32; j++)
                        t += __shfl_sync(0xffffffffu, mv, j) * c1s[j * 32 + lane];
                    t = fmaxf(t, 0.f);
                    float p = t * c2s[lane];
                    #pragma unroll
                    for (int off = 16; off > 0; off >>= 1)
                        p += __shfl_xor_sync(0xffffffffu, p, off);
                    float we = p + cm2bv;
                    int row = g_rows[beg + base + es_];
                    atomicAdd(&g_AGG[row * 32 + lane], mv);
                    if (lane < 3) {
                        float d = g_COORD[row * 3 + lane] - g_COORD[n * 3 + lane];
                        atomicAdd(&g_CD[row * 3 + lane], d * we);
                    }
                }
            }
            __syncthreads();
        }
        cpa_wait0();
        __syncthreads();
        float* t = cur; cur = nxt; nxt = t;
    }
}

__global__ void k_update() {
    int i = blockIdx.x * blockDim.x + threadIdx.x;
    if (i < NN * WD) {
        int n = i >> 5;
        float inv = 1.f / g_CNT[n];
        g_H[i] = fmaxf(g_H[i] + g_AGG[i] * inv, 0.f);
        g_AGG[i] = 0.f;
    }
    if (i < NN * 3) {
        int n = i / 3;
        g_COORD[i] += g_CD[i] / g_CNT[n];
        g_CD[i] = 0.f;
    }
}

__global__ void k_final(const float* __restrict__ f2aw, const float* __restrict__ f2ab,
                        const float* __restrict__ f2bw, const float* __restrict__ f2bb,
                        float* __restrict__ out) {
    __shared__ float wa[2048];
    __shared__ float ba[64];
    __shared__ float wb[64];
    int tid = threadIdx.x;
    for (int i = tid; i < 2048; i += 256) wa[i] = f2aw[i];
    if (tid < 64) { ba[tid] = f2ab[tid]; wb[tid] = f2bw[tid]; }
    __syncthreads();
    int n = blockIdx.x * blockDim.x + tid;
    if (n < NN) {
        float h[32];
        #pragma unroll
        for (int j = 0; j < 32; j++) h[j] = g_H[n * 32 + j];
        float o = f2bb[0];
        #pragma unroll 4
        for (int u = 0; u < 64; u++) {
            float s = ba[u];
            #pragma unroll
            for (int j = 0; j < 32; j++) s += h[j] * wa[j * 64 + u];
            o += fmaxf(s, 0.f) * wb[u];
        }
        out[n] = o;
    }
    int tot = gridDim.x * blockDim.x;
    for (int i = n; i < NN * 3; i += tot) out[NN + i] = g_COORD[i];
}

// ---------------- host ----------------
extern "C" void kernel_launch(void* const* d_in, const int* in_sizes, int n_in,
                              void* d_out, int out_size) {
    const float* x      = (const float*)d_in[0];
    const int*   ei     = (const int*)d_in[1];     // int32 (JAX x64 disabled)
    const float* ea     = (const float*)d_in[2];
    const float* coords = (const float*)d_in[3];
    const float* fc1w   = (const float*)d_in[4];
    const float* fc1b   = (const float*)d_in[5];
    const float* k1w    = (const float*)d_in[6];
    const float* k1b    = (const float*)d_in[7];
    const float* k2w    = (const float*)d_in[8];
    const float* k2b    = (const float*)d_in[9];
    const float* k3w    = (const float*)d_in[10];
    const float* k3b    = (const float*)d_in[11];
    const float* cm1w   = (const float*)d_in[12];
    const float* cm1b   = (const float*)d_in[13];
    const float* cm2w   = (const float*)d_in[14];
    const float* cm2b   = (const float*)d_in[15];
    const float* f2aw   = (const float*)d_in[16];
    const float* f2ab   = (const float*)d_in[17];
    const float* f2bw   = (const float*)d_in[18];
    const float* f2bb   = (const float*)d_in[19];

    const int smemM  = (2 * ACOLS + 32 * KST + 32 * MST) * 4;  // 103680 B
    const int smemG2 = (8192 + 2 * 4096) * 4;                  // 65536 B
    cudaFuncSetAttribute(k_m, cudaFuncAttributeMaxDynamicSharedMemorySize, smemM);
    cudaFuncSetAttribute(k_gemm2, cudaFuncAttributeMaxDynamicSharedMemorySize, smemG2);

    // launch order: slot 4 = k_gemm2 (profiler capture target)
    k_hist<<<(EE + 255) / 256, 256>>>(ei);                              // 1
    k_scan<<<1, 1024>>>();                                              // 2
    k_scatter<<<(EE + 255) / 256, 256>>>(ei);                           // 3
    k_gemm2<<<(EE + 63) / 64, 256, smemG2>>>(ea, k1w, k1b, k2w, k2b);   // 4
    k_init<<<(NN * WD + 255) / 256, 256>>>(x, coords, fc1w, fc1b);      // 5
    k_aw<<<(32 * ACOLS + 255) / 256, 256>>>(k3w, k3b);                  // 6

    for (int d = 0; d < DEPTH; d++) {
        k_gemmA<<<dim3((ACOLS + 255) / 256, (NN + 63) / 64), 256>>>();
        k_m<<<NBLK, 128, smemM>>>(cm1w, cm1b, cm2w, cm2b);
        k_update<<<(NN * WD + 255) / 256, 256>>>();
    }
    k_final<<<(NN + 255) / 256, 256>>>(f2aw, f2ab, f2bw, f2bb, (float*)d_out);
    k_cleanup<<<(NN + 255) / 256, 256>>>();
}

// round 10
// speedup vs baseline: 1.3244x; 1.2469x over previous
#include <cuda_runtime.h>
#include <cstdint>

#define NN 10000
#define EE 300000
#define WD 32
#define DEPTH 4
#define ACOLS 8224           // 8192 (A) + 32 (bias part)
#define KST 260              // k2 smem row stride (float4-aligned, conflict-free)
#define MST 36               // m smem row stride
#define HST 68               // Hs stride: multiple of 4 (float4-aligned)
#define NBLK 296             // persistent k_m blocks (2 per SM x 148)

// ---------------- scratch (static __device__) ----------------
__device__ __align__(16) float g_K2[EE * 256];          // relu MLP out, PERMUTED by col-bucket
__device__ __align__(16) float g_A[NN * ACOLS];         // per-node A|bias
__device__ __align__(16) float g_AW[32 * ACOLS];        // transposed ker3 weights
__device__ __align__(16) float g_H[NN * WD];
__device__ __align__(16) float g_AGG[NN * WD];
__device__ __align__(16) float g_COORD[NN * 3];
__device__ __align__(16) float g_CD[NN * 3];
__device__ float g_CNT[NN];
__device__ int   g_colcnt[NN];
__device__ int   g_rowcnt[NN];
__device__ int   g_coloff[NN + 1];
__device__ int   g_cur[NN];
__device__ int   g_pos[EE];     // edge -> sorted position
__device__ int   g_rows[EE];    // sorted position -> row node

__device__ __forceinline__ void cpa16(float* smem_dst, const float4* gsrc) {
    unsigned s = (unsigned)__cvta_generic_to_shared(smem_dst);
    asm volatile("cp.async.cg.shared.global [%0], [%1], 16;\n" :: "r"(s), "l"(gsrc));
}
__device__ __forceinline__ void cpa_commit() { asm volatile("cp.async.commit_group;\n"); }
__device__ __forceinline__ void cpa_wait1()  { asm volatile("cp.async.wait_group 1;\n"); }

// ---------------- setup ----------------
__global__ void k_init(const float* __restrict__ x, const float* __restrict__ coords,
                       const float* __restrict__ fc1w, const float* __restrict__ fc1b) {
    int i = blockIdx.x * blockDim.x + threadIdx.x;
    if (i < NN * 3) g_COORD[i] = coords[i];
    if (i < NN * WD) {
        int n = i / WD, o = i % WD;
        float a = fc1b[o];
        #pragma unroll
        for (int j = 0; j < 3; j++) a += x[n * 3 + j] * fc1w[j * WD + o];
        g_H[i] = a;
    }
}

__global__ void k_hist(const int* __restrict__ ei) {
    int e = blockIdx.x * blockDim.x + threadIdx.x;
    if (e < EE) {
        atomicAdd(&g_rowcnt[ei[e]], 1);
        atomicAdd(&g_colcnt[ei[EE + e]], 1);
    }
}

__global__ void k_scan() {
    __shared__ int sh[1024];
    __shared__ int carry;
    int t = threadIdx.x;
    if (t == 0) carry = 0;
    __syncthreads();
    for (int base = 0; base < NN; base += 1024) {
        int v = (base + t < NN) ? g_colcnt[base + t] : 0;
        sh[t] = v;
        __syncthreads();
        for (int off = 1; off < 1024; off <<= 1) {
            int y = (t >= off) ? sh[t - off] : 0;
            __syncthreads();
            sh[t] += y;
            __syncthreads();
        }
        int incl = sh[t];
        if (base + t < NN) {
            int ex = carry + incl - v;
            g_coloff[base + t] = ex;
            g_cur[base + t] = ex;
            g_CNT[base + t] = fmaxf(1.f, (float)g_rowcnt[base + t]);
        }
        int tot = sh[1023];
        __syncthreads();
        if (t == 0) carry += tot;
        __syncthreads();
    }
    if (t == 0) g_coloff[NN] = carry;
}

__global__ void k_scatter(const int* __restrict__ ei) {
    int e = blockIdx.x * blockDim.x + threadIdx.x;
    if (e < EE) {
        int r = ei[e], c = ei[EE + e];
        int p = atomicAdd(&g_cur[c], 1);
        g_pos[e] = p;
        g_rows[p] = r;
    }
}

__global__ void k_cleanup() {
    int i = blockIdx.x * blockDim.x + threadIdx.x;
    if (i < NN) { g_colcnt[i] = 0; g_rowcnt[i] = 0; }
}

// ---------------- fused kernel MLP: K2 = relu(relu(ea@W1+b1)@W2+b2), permuted write ----
__global__ void __launch_bounds__(256) k_gemm2(const float* __restrict__ ea,
                                               const float* __restrict__ w1,
                                               const float* __restrict__ b1,
                                               const float* __restrict__ w2,
                                               const float* __restrict__ b2) {
    extern __shared__ float s2[];
    float* R1t = s2;                 // [128][64] k-major
    float* Bs0 = s2 + 8192;          // [16][256] stage 0
    float* Bs1 = s2 + 8192 + 4096;   // [16][256] stage 1
    __shared__ float eas[64 * 6];
    __shared__ float w1s[6 * 128];
    __shared__ float b1s[128];
    int tid = threadIdx.x;
    int m0 = blockIdx.x * 64;

    for (int i = tid; i < 64 * 6; i += 256) {
        int g = m0 * 6 + i;
        eas[i] = (g < EE * 6) ? ea[g] : 0.f;
    }
    for (int i = tid; i < 768; i += 256) w1s[i] = w1[i];
    if (tid < 128) b1s[tid] = b1[tid];
    {
        #pragma unroll
        for (int i = 0; i < 4; i++) {
            int idx = tid + i * 256;
            int kk = idx >> 6, c4 = idx & 63;
            *(float4*)&Bs0[kk * 256 + c4 * 4] = *(const float4*)&w2[kk * 256 + c4 * 4];
        }
    }
    __syncthreads();

    {
        int r = tid & 63, kg = tid >> 6;
        float ev[6];
        #pragma unroll
        for (int j = 0; j < 6; j++) ev[j] = eas[r * 6 + j];
        #pragma unroll
        for (int q = 0; q < 32; q++) {
            int k = kg * 32 + q;
            float a = b1s[k];
            #pragma unroll
            for (int j = 0; j < 6; j++) a += ev[j] * w1s[j * 128 + k];
            R1t[k * 64 + r] = fmaxf(a, 0.f);
        }
    }
    __syncthreads();

    int tx = tid & 31, ty = tid >> 5;
    int r0 = ty * 4, r1 = 32 + ty * 4;
    int c0 = tx * 4, c1 = 128 + tx * 4;
    float acc[8][8];
    #pragma unroll
    for (int i = 0; i < 8; i++)
        #pragma unroll
        for (int j = 0; j < 8; j++) acc[i][j] = 0.f;

    #pragma unroll
    for (int step = 0; step < 8; step++) {
        float* cur = (step & 1) ? Bs1 : Bs0;
        float* nxt = (step & 1) ? Bs0 : Bs1;
        if (step < 7) {
            int kcn = (step + 1) * 16;
            #pragma unroll
            for (int i = 0; i < 4; i++) {
                int idx = tid + i * 256;
                int kk = idx >> 6, c4 = idx & 63;
                *(float4*)&nxt[kk * 256 + c4 * 4] =
                    *(const float4*)&w2[(kcn + kk) * 256 + c4 * 4];
            }
        }
        int kc = step * 16;
        #pragma unroll
        for (int kk = 0; kk < 16; kk++) {
            float a[8], b[8];
            *(float4*)a       = *(float4*)&R1t[(kc + kk) * 64 + r0];
            *(float4*)(a + 4) = *(float4*)&R1t[(kc + kk) * 64 + r1];
            *(float4*)b       = *(float4*)&cur[kk * 256 + c0];
            *(float4*)(b + 4) = *(float4*)&cur[kk * 256 + c1];
            #pragma unroll
            for (int i = 0; i < 8; i++)
                #pragma unroll
                for (int j = 0; j < 8; j++) acc[i][j] += a[i] * b[j];
        }
        __syncthreads();
    }
    float bb[8];
    #pragma unroll
    for (int j = 0; j < 4; j++) { bb[j] = b2[c0 + j]; bb[4 + j] = b2[c1 + j]; }
    #pragma unroll
    for (int half = 0; half < 2; half++) {
        int rbase = (half == 0) ? r0 : r1;
        #pragma unroll
        for (int i = 0; i < 4; i++) {
            int e = m0 + rbase + i;
            if (e >= EE) continue;
            int pos = g_pos[e];
            int ai = half * 4 + i;
            float o[8];
            #pragma unroll
            for (int j = 0; j < 8; j++) o[j] = fmaxf(acc[ai][j] + bb[j], 0.f);
            *(float4*)&g_K2[pos * 256 + c0] = *(float4*)o;
            *(float4*)&g_K2[pos * 256 + c1] = *(float4*)(o + 4);
        }
    }
}

// AW[j][c*32+i] = ker3_w[c][i*32+j]; AW[j][8192+i] = ker3_b[i*32+j]
__global__ void k_aw(const float* __restrict__ w3, const float* __restrict__ b3) {
    int idx = blockIdx.x * blockDim.x + threadIdx.x;
    if (idx >= 32 * ACOLS) return;
    int j = idx / ACOLS, r = idx % ACOLS;
    if (r < 8192) {
        int c = r >> 5, i = r & 31;
        g_AW[idx] = w3[c * 1024 + i * 32 + j];
    } else {
        int i = r - 8192;
        g_AW[idx] = b3[i * 32 + j];
    }
}

// A = H @ AW   [N,32]@[32,8224] — 64x256 tile, conflict-free thread tiling
__global__ void __launch_bounds__(256) k_gemmA() {
    __shared__ float Hs[32 * HST];
    __shared__ float AWs[32 * 256];
    int tid = threadIdx.x;
    int m0 = blockIdx.y * 64;
    int n0 = blockIdx.x * 256;
    for (int i = tid; i < 2048; i += 256) {
        int node = i >> 5, k = i & 31;
        Hs[k * HST + node] = (m0 + node < NN) ? g_H[(m0 + node) * 32 + k] : 0.f;
    }
    const float4* AWf4 = (const float4*)g_AW;
    #pragma unroll
    for (int i = 0; i < 8; i++) {
        int idx = tid + i * 256;
        int kk = idx >> 6, c4 = idx & 63;
        int col = n0 + c4 * 4;
        float4 v = make_float4(0.f, 0.f, 0.f, 0.f);
        if (col < ACOLS) v = AWf4[kk * (ACOLS / 4) + (n0 >> 2) + c4];
        *(float4*)&AWs[kk * 256 + c4 * 4] = v;
    }
    __syncthreads();
    int tx = tid & 31, ty = tid >> 5;
    int r0 = ty * 4, r1 = 32 + ty * 4;
    int c0 = tx * 4, c1 = 128 + tx * 4;
    float acc[8][8];
    #pragma unroll
    for (int i = 0; i < 8; i++)
        #pragma unroll
        for (int j = 0; j < 8; j++) acc[i][j] = 0.f;
    #pragma unroll
    for (int kk = 0; kk < 32; kk++) {
        float a[8], b[8];
        *(float4*)a       = *(float4*)&Hs[kk * HST + r0];
        *(float4*)(a + 4) = *(float4*)&Hs[kk * HST + r1];
        *(float4*)b       = *(float4*)&AWs[kk * 256 + c0];
        *(float4*)(b + 4) = *(float4*)&AWs[kk * 256 + c1];
        #pragma unroll
        for (int i = 0; i < 8; i++)
            #pragma unroll
            for (int j = 0; j < 8; j++) acc[i][j] += a[i] * b[j];
    }
    #pragma unroll
    for (int half = 0; half < 2; half++) {
        int rbase = (half == 0) ? r0 : r1;
        #pragma unroll
        for (int i = 0; i < 4; i++) {
            int node = m0 + rbase + i;
            if (node >= NN) continue;
            int ai = half * 4 + i;
            if (n0 + c0 < ACOLS)
                *(float4*)&g_A[node * ACOLS + n0 + c0] = *(float4*)acc[ai];
            if (n0 + c1 < ACOLS)
                *(float4*)&g_A[node * ACOLS + n0 + c1] = *(float4*)(acc[ai] + 4);
        }
    }
}

// persistent fused M + coord-MLP + scatter.
// 256 threads: gemm as 32 eslots x 8 colgrps; Ks double-buffered via cp.async.
__global__ void __launch_bounds__(256, 2) k_m(const float* __restrict__ cm1w,
                                              const float* __restrict__ cm1b,
                                              const float* __restrict__ cm2w,
                                              const float* __restrict__ cm2b) {
    extern __shared__ float sm[];
    float* As = sm;                  // ACOLS
    float* K0 = sm + ACOLS;          // 32*KST
    float* K1 = K0 + 32 * KST;       // 32*KST
    float* Ms = K1 + 32 * KST;       // 32*MST
    __shared__ float c1s[1024];
    __shared__ float c1bs[32], c2s[32];
    __shared__ float cm2bv;
    __shared__ int nsS, neS;
    int tid = threadIdx.x;
    int b = blockIdx.x;
    if (tid == 0) {
        long long t1 = (long long)b * EE;
        int lo = 0, hi = NN;
        while (lo < hi) {
            int mid = (lo + hi) >> 1;
            if ((long long)g_coloff[mid] * NBLK >= t1) hi = mid; else lo = mid + 1;
        }
        nsS = lo;
        long long t2 = (long long)(b + 1) * EE;
        hi = NN;
        while (lo < hi) {
            int mid = (lo + hi) >> 1;
            if ((long long)g_coloff[mid] * NBLK >= t2) hi = mid; else lo = mid + 1;
        }
        neS = lo;
        cm2bv = cm2b[0];
    }
    for (int i = tid; i < 1024; i += 256) c1s[i] = cm1w[i];
    if (tid < 32) { c1bs[tid] = cm1b[tid]; c2s[tid] = cm2w[tid]; }
    __syncthreads();
    int ns = nsS, ne = neS;

    // skip leading empty nodes
    int n = ns;
    int begN = (n < ne) ? g_coloff[n] : 0, endN = begN;
    while (n < ne) {
        endN = g_coloff[n + 1];
        if (endN > begN) break;
        n++; begN = endN;
    }
    if (n >= ne) return;

    int lane = tid & 31, wrp = tid >> 5;
    int eslot = tid >> 3, colgrp = tid & 7;
    float c1r[32];
    #pragma unroll
    for (int j = 0; j < 32; j++) c1r[j] = c1s[j * 32 + lane];

    // prologue: prefetch A(n) and Ks(first batch), one group each
    {
        const float4* src = (const float4*)&g_A[(size_t)n * ACOLS];
        for (int i = tid; i < ACOLS / 4; i += 256) cpa16(&As[i * 4], src + i);
        cpa_commit();
        int cnt0 = min(32, endN - begN);
        const float4* kf = (const float4*)&g_K2[(size_t)begN * 256];
        for (int i = tid; i < cnt0 * 64; i += 256)
            cpa16(&K0[(i >> 6) * KST + (i & 63) * 4], kf + i);
        cpa_commit();
    }

    int base = 0, kpar = 0, prevn = n;
    while (n < ne) {
        int nE = endN - begN;
        int cnt = min(32, nE - base);
        if (n != prevn) {   // entering new node: issue A(n) (single buffer; reads done)
            const float4* src = (const float4*)&g_A[(size_t)n * ACOLS];
            for (int i = tid; i < ACOLS / 4; i += 256) cpa16(&As[i * 4], src + i);
            cpa_commit();
            prevn = n;
        }
        // next batch coords; issue its Ks into the other buffer
        int n2 = n, base2 = base + 32, beg2 = begN, end2 = endN;
        if (base2 >= nE) {
            base2 = 0; n2 = n + 1; beg2 = endN;
            while (n2 < ne) {
                end2 = g_coloff[n2 + 1];
                if (end2 > beg2) break;
                n2++; beg2 = end2;
            }
        }
        if (n2 < ne) {
            int cnt2 = min(32, end2 - beg2 - base2);
            const float4* kf = (const float4*)&g_K2[(size_t)(beg2 + base2) * 256];
            float* Kn = kpar ? K0 : K1;
            for (int i = tid; i < cnt2 * 64; i += 256)
                cpa16(&Kn[(i >> 6) * KST + (i & 63) * 4], kf + i);
        }
        cpa_commit();
        cpa_wait1();         // waits: this batch's Ks (+ A if new node); leaves next Ks flying
        __syncthreads();

        const float* Kc = kpar ? K1 : K0;
        if (eslot < cnt) {
            float4 acc = *(float4*)&As[8192 + colgrp * 4];
            const float4* kr4 = (const float4*)&Kc[eslot * KST];
            #pragma unroll 8
            for (int c4i = 0; c4i < 64; c4i++) {
                float4 kv = kr4[c4i];
                float4 av;
                av = *(float4*)&As[(c4i * 4 + 0) * 32 + colgrp * 4];
                acc.x += kv.x * av.x; acc.y += kv.x * av.y; acc.z += kv.x * av.z; acc.w += kv.x * av.w;
                av = *(float4*)&As[(c4i * 4 + 1) * 32 + colgrp * 4];
                acc.x += kv.y * av.x; acc.y += kv.y * av.y; acc.z += kv.y * av.z; acc.w += kv.y * av.w;
                av = *(float4*)&As[(c4i * 4 + 2) * 32 + colgrp * 4];
                acc.x += kv.z * av.x; acc.y += kv.z * av.y; acc.z += kv.z * av.z; acc.w += kv.z * av.w;
                av = *(float4*)&As[(c4i * 4 + 3) * 32 + colgrp * 4];
                acc.x += kv.w * av.x; acc.y += kv.w * av.y; acc.z += kv.w * av.z; acc.w += kv.w * av.w;
            }
            *(float4*)&Ms[eslot * MST + colgrp * 4] = acc;
        }
        __syncthreads();

        // MLP + scatter: warp wrp handles edges wrp*4 .. wrp*4+3
        #pragma unroll
        for (int q = 0; q < 4; q++) {
            int es = wrp * 4 + q;
            if (es < cnt) {
                const float* mrow = &Ms[es * MST];
                float t0 = 0.f, t1 = 0.f, t2 = 0.f, t3 = 0.f;
                #pragma unroll
                for (int j = 0; j < 32; j += 4) {
                    t0 += mrow[j]     * c1r[j];
                    t1 += mrow[j + 1] * c1r[j + 1];
                    t2 += mrow[j + 2] * c1r[j + 2];
                    t3 += mrow[j + 3] * c1r[j + 3];
                }
                float t = fmaxf(c1bs[lane] + ((t0 + t1) + (t2 + t3)), 0.f);
                float p = t * c2s[lane];
                #pragma unroll
                for (int off = 16; off > 0; off >>= 1)
                    p += __shfl_xor_sync(0xffffffffu, p, off);
                float we = p + cm2bv;
                int row = g_rows[begN + base + es];
                float mv = mrow[lane];
                atomicAdd(&g_AGG[row * 32 + lane], mv);
                if (lane < 3) {
                    float d = g_COORD[row * 3 + lane] - g_COORD[n * 3 + lane];
                    atomicAdd(&g_CD[row * 3 + lane], d * we);
                }
            }
        }
        n = n2; base = base2; begN = beg2; endN = end2;
        kpar ^= 1;
    }
}

__global__ void k_update() {
    int i = blockIdx.x * blockDim.x + threadIdx.x;
    if (i < NN * WD) {
        int n = i >> 5;
        float inv = 1.f / g_CNT[n];
        g_H[i] = fmaxf(g_H[i] + g_AGG[i] * inv, 0.f);
        g_AGG[i] = 0.f;
    }
    if (i < NN * 3) {
        int n = i / 3;
        g_COORD[i] += g_CD[i] / g_CNT[n];
        g_CD[i] = 0.f;
    }
}

__global__ void k_final(const float* __restrict__ f2aw, const float* __restrict__ f2ab,
                        const float* __restrict__ f2bw, const float* __restrict__ f2bb,
                        float* __restrict__ out) {
    __shared__ float wa[2048];
    __shared__ float ba[64];
    __shared__ float wb[64];
    int tid = threadIdx.x;
    for (int i = tid; i < 2048; i += 256) wa[i] = f2aw[i];
    if (tid < 64) { ba[tid] = f2ab[tid]; wb[tid] = f2bw[tid]; }
    __syncthreads();
    int n = blockIdx.x * blockDim.x + tid;
    if (n < NN) {
        float h[32];
        #pragma unroll
        for (int j = 0; j < 32; j++) h[j] = g_H[n * 32 + j];
        float o = f2bb[0];
        #pragma unroll 4
        for (int u = 0; u < 64; u++) {
            float s = ba[u];
            #pragma unroll
            for (int j = 0; j < 32; j++) s += h[j] * wa[j * 64 + u];
            o += fmaxf(s, 0.f) * wb[u];
        }
        out[n] = o;
    }
    int tot = gridDim.x * blockDim.x;
    for (int i = n; i < NN * 3; i += tot) out[NN + i] = g_COORD[i];
}

// ---------------- host ----------------
extern "C" void kernel_launch(void* const* d_in, const int* in_sizes, int n_in,
                              void* d_out, int out_size) {
    const float* x      = (const float*)d_in[0];
    const int*   ei     = (const int*)d_in[1];     // int32 (JAX x64 disabled)
    const float* ea     = (const float*)d_in[2];
    const float* coords = (const float*)d_in[3];
    const float* fc1w   = (const float*)d_in[4];
    const float* fc1b   = (const float*)d_in[5];
    const float* k1w    = (const float*)d_in[6];
    const float* k1b    = (const float*)d_in[7];
    const float* k2w    = (const float*)d_in[8];
    const float* k2b    = (const float*)d_in[9];
    const float* k3w    = (const float*)d_in[10];
    const float* k3b    = (const float*)d_in[11];
    const float* cm1w   = (const float*)d_in[12];
    const float* cm1b   = (const float*)d_in[13];
    const float* cm2w   = (const float*)d_in[14];
    const float* cm2b   = (const float*)d_in[15];
    const float* f2aw   = (const float*)d_in[16];
    const float* f2ab   = (const float*)d_in[17];
    const float* f2bw   = (const float*)d_in[18];
    const float* f2bb   = (const float*)d_in[19];

    const int smemM  = (ACOLS + 2 * 32 * KST + 32 * MST) * 4;  // 104064 B
    const int smemG2 = (8192 + 2 * 4096) * 4;                  // 65536 B
    cudaFuncSetAttribute(k_m, cudaFuncAttributeMaxDynamicSharedMemorySize, smemM);
    cudaFuncSetAttribute(k_gemm2, cudaFuncAttributeMaxDynamicSharedMemorySize, smemG2);

    // slot 4 = k_gemm2 (profiler capture target)
    k_hist<<<(EE + 255) / 256, 256>>>(ei);                              // 1
    k_scan<<<1, 1024>>>();                                              // 2
    k_scatter<<<(EE + 255) / 256, 256>>>(ei);                           // 3
    k_gemm2<<<(EE + 63) / 64, 256, smemG2>>>(ea, k1w, k1b, k2w, k2b);   // 4
    k_init<<<(NN * WD + 255) / 256, 256>>>(x, coords, fc1w, fc1b);      // 5
    k_aw<<<(32 * ACOLS + 255) / 256, 256>>>(k3w, k3b);                  // 6

    for (int d = 0; d < DEPTH; d++) {
        k_gemmA<<<dim3((ACOLS + 255) / 256, (NN + 63) / 64), 256>>>();
        k_m<<<NBLK, 256, smemM>>>(cm1w, cm1b, cm2w, cm2b);
        k_update<<<(NN * WD + 255) / 256, 256>>>();
    }
    k_final<<<(NN + 255) / 256, 256>>>(f2aw, f2ab, f2bw, f2bb, (float*)d_out);
    k_cleanup<<<(NN + 255) / 256, 256>>>();
}

// round 12
// speedup vs baseline: 1.3913x; 1.0506x over previous
#include <cuda_runtime.h>
#include <cuda_bf16.h>
#include <cstdint>

#define NN 10000
#define EE 300000
#define WD 32
#define DEPTH 4
#define ACOLS 8224           // 8192 (A) + 32 (bias part)
#define KST 260              // k2 smem row stride (float4-aligned, conflict-free)
#define MST 36               // m smem row stride
#define NBLK 296             // persistent k_m blocks (2 per SM x 148)
#define RST 136              // R1 bf16 smem row stride
#define WST 264              // W2/AW bf16 smem row stride

// ---------------- scratch (static __device__) ----------------
__device__ __align__(16) float g_K2[EE * 256];          // relu MLP out, PERMUTED by col-bucket
__device__ __align__(16) float g_A[NN * ACOLS];         // per-node A|bias (fp32)
__device__ __align__(16) unsigned short g_AWhi[32 * ACOLS];  // ker3 weights bf16 hi
__device__ __align__(16) unsigned short g_AWlo[32 * ACOLS];  // ker3 weights bf16 lo
__device__ __align__(16) float g_H[NN * WD];
__device__ __align__(16) float g_AGG[NN * WD];
__device__ __align__(16) float g_COORD[NN * 3];
__device__ __align__(16) float g_CD[NN * 3];
__device__ float g_CNT[NN];
__device__ int   g_colcnt[NN];
__device__ int   g_rowcnt[NN];
__device__ int   g_coloff[NN + 1];
__device__ int   g_cur[NN];
__device__ int   g_pos[EE];     // edge -> sorted position
__device__ int   g_rows[EE];    // sorted position -> row node

// ---------------- helpers ----------------
__device__ __forceinline__ void cpa16(float* smem_dst, const float4* gsrc) {
    unsigned s = (unsigned)__cvta_generic_to_shared(smem_dst);
    asm volatile("cp.async.cg.shared.global [%0], [%1], 16;\n" :: "r"(s), "l"(gsrc));
}
__device__ __forceinline__ void cpa_commit() { asm volatile("cp.async.commit_group;\n"); }
__device__ __forceinline__ void cpa_wait1()  { asm volatile("cp.async.wait_group 1;\n"); }

__device__ __forceinline__ void bfsplit(float x, unsigned short& h, unsigned short& l) {
    __nv_bfloat16 bh = __float2bfloat16(x);
    h = *reinterpret_cast<unsigned short*>(&bh);
    float r = x - __bfloat162float(bh);
    __nv_bfloat16 bl = __float2bfloat16(r);
    l = *reinterpret_cast<unsigned short*>(&bl);
}
__device__ __forceinline__ unsigned sptr(const void* p) {
    return (unsigned)__cvta_generic_to_shared(p);
}
__device__ __forceinline__ void ldsm4(unsigned* r, unsigned a) {
    asm volatile("ldmatrix.sync.aligned.m8n8.x4.shared.b16 {%0,%1,%2,%3}, [%4];"
        : "=r"(r[0]), "=r"(r[1]), "=r"(r[2]), "=r"(r[3]) : "r"(a));
}
__device__ __forceinline__ void ldsm4t(unsigned* r, unsigned a) {
    asm volatile("ldmatrix.sync.aligned.m8n8.x4.trans.shared.b16 {%0,%1,%2,%3}, [%4];"
        : "=r"(r[0]), "=r"(r[1]), "=r"(r[2]), "=r"(r[3]) : "r"(a));
}
__device__ __forceinline__ void mma_bf16(float* c, const unsigned* a, unsigned b0, unsigned b1) {
    asm volatile("mma.sync.aligned.m16n8k16.row.col.f32.bf16.bf16.f32 "
        "{%0,%1,%2,%3},{%4,%5,%6,%7},{%8,%9},{%0,%1,%2,%3};"
        : "+f"(c[0]), "+f"(c[1]), "+f"(c[2]), "+f"(c[3])
        : "r"(a[0]), "r"(a[1]), "r"(a[2]), "r"(a[3]), "r"(b0), "r"(b1));
}

// ---------------- setup ----------------
__global__ void k_init(const float* __restrict__ x, const float* __restrict__ coords,
                       const float* __restrict__ fc1w, const float* __restrict__ fc1b) {
    int i = blockIdx.x * blockDim.x + threadIdx.x;
    if (i < NN * 3) g_COORD[i] = coords[i];
    if (i < NN * WD) {
        int n = i / WD, o = i % WD;
        float a = fc1b[o];
        #pragma unroll
        for (int j = 0; j < 3; j++) a += x[n * 3 + j] * fc1w[j * WD + o];
        g_H[i] = a;
    }
}

__global__ void k_hist(const int* __restrict__ ei) {
    int e = blockIdx.x * blockDim.x + threadIdx.x;
    if (e < EE) {
        atomicAdd(&g_rowcnt[ei[e]], 1);
        atomicAdd(&g_colcnt[ei[EE + e]], 1);
    }
}

__global__ void k_scan() {
    __shared__ int sh[1024];
    __shared__ int carry;
    int t = threadIdx.x;
    if (t == 0) carry = 0;
    __syncthreads();
    for (int base = 0; base < NN; base += 1024) {
        int v = (base + t < NN) ? g_colcnt[base + t] : 0;
        sh[t] = v;
        __syncthreads();
        for (int off = 1; off < 1024; off <<= 1) {
            int y = (t >= off) ? sh[t - off] : 0;
            __syncthreads();
            sh[t] += y;
            __syncthreads();
        }
        int incl = sh[t];
        if (base + t < NN) {
            int ex = carry + incl - v;
            g_coloff[base + t] = ex;
            g_cur[base + t] = ex;
            g_CNT[base + t] = fmaxf(1.f, (float)g_rowcnt[base + t]);
        }
        int tot = sh[1023];
        __syncthreads();
        if (t == 0) carry += tot;
        __syncthreads();
    }
    if (t == 0) g_coloff[NN] = carry;
}

__global__ void k_scatter(const int* __restrict__ ei) {
    int e = blockIdx.x * blockDim.x + threadIdx.x;
    if (e < EE) {
        int r = ei[e], c = ei[EE + e];
        int p = atomicAdd(&g_cur[c], 1);
        g_pos[e] = p;
        g_rows[p] = r;
    }
}

__global__ void k_cleanup() {
    int i = blockIdx.x * blockDim.x + threadIdx.x;
    if (i < NN) { g_colcnt[i] = 0; g_rowcnt[i] = 0; }
}

// ---------------- gemm2: K2 = relu(relu(ea@W1+b1)@W2+b2) via 3-term split-bf16 mma ------
__global__ void __launch_bounds__(256) k_gemm2(const float* __restrict__ ea,
                                               const float* __restrict__ w1,
                                               const float* __restrict__ b1,
                                               const float* __restrict__ w2,
                                               const float* __restrict__ b2) {
    extern __shared__ unsigned short s2u[];
    unsigned short* R1h = s2u;                       // [64][RST]
    unsigned short* R1l = s2u + 64 * RST;            // [64][RST]
    unsigned short* W2h = s2u + 2 * 64 * RST;        // [128][WST]
    unsigned short* W2l = W2h + 128 * WST;           // [128][WST]
    float* b2s = (float*)(W2l + 128 * WST);          // [256]
    __shared__ float eas[64 * 6];
    __shared__ float w1s[6 * 128];
    __shared__ float b1s[128];
    int tid = threadIdx.x;
    int m0 = blockIdx.x * 64;

    // stage W2 fp32 -> split bf16 smem
    for (int i = tid; i < 16384; i += 256) {
        int k = i >> 7, n2 = i & 127;
        float2 v = *(const float2*)&w2[k * 256 + n2 * 2];
        unsigned short hx, lx, hy, ly;
        bfsplit(v.x, hx, lx);
        bfsplit(v.y, hy, ly);
        *(unsigned*)&W2h[k * WST + n2 * 2] = ((unsigned)hy << 16) | hx;
        *(unsigned*)&W2l[k * WST + n2 * 2] = ((unsigned)ly << 16) | lx;
    }
    for (int i = tid; i < 64 * 6; i += 256) {
        int g = m0 * 6 + i;
        eas[i] = (g < EE * 6) ? ea[g] : 0.f;
    }
    for (int i = tid; i < 768; i += 256) w1s[i] = w1[i];
    if (tid < 128) b1s[tid] = b1[tid];
    b2s[tid] = b2[tid];
    __syncthreads();

    // R1 tile fp32 compute -> split bf16 smem, row-major [edge][k]
    {
        int r = tid & 63, kg = tid >> 6;
        float ev[6];
        #pragma unroll
        for (int j = 0; j < 6; j++) ev[j] = eas[r * 6 + j];
        #pragma unroll
        for (int q = 0; q < 32; q += 2) {
            int k0 = kg * 32 + q;
            float a0 = b1s[k0], a1 = b1s[k0 + 1];
            #pragma unroll
            for (int j = 0; j < 6; j++) {
                a0 += ev[j] * w1s[j * 128 + k0];
                a1 += ev[j] * w1s[j * 128 + k0 + 1];
            }
            a0 = fmaxf(a0, 0.f); a1 = fmaxf(a1, 0.f);
            unsigned short h0, l0, h1, l1;
            bfsplit(a0, h0, l0);
            bfsplit(a1, h1, l1);
            *(unsigned*)&R1h[r * RST + k0] = ((unsigned)h1 << 16) | h0;
            *(unsigned*)&R1l[r * RST + k0] = ((unsigned)l1 << 16) | l0;
        }
    }
    __syncthreads();

    int lane = tid & 31, warp = tid >> 5;
    int mb = (warp >> 2) * 32, nb = (warp & 3) * 64;
    unsigned aH0 = sptr(&R1h[(mb + (lane & 15)) * RST]) + (lane >> 4) * 16;
    unsigned aH1 = aH0 + 16 * RST * 2;
    unsigned aL0 = sptr(&R1l[(mb + (lane & 15)) * RST]) + (lane >> 4) * 16;
    unsigned aL1 = aL0 + 16 * RST * 2;
    unsigned bH  = sptr(&W2h[(lane & 15) * WST + nb + (lane >> 4) * 8]);
    unsigned bL  = sptr(&W2l[(lane & 15) * WST + nb + (lane >> 4) * 8]);
    float acc[2][8][4];
    #pragma unroll
    for (int i = 0; i < 2; i++)
        #pragma unroll
        for (int j = 0; j < 8; j++)
            #pragma unroll
            for (int q = 0; q < 4; q++) acc[i][j][q] = 0.f;

    #pragma unroll
    for (int ks = 0; ks < 8; ks++) {
        unsigned ah0[4], ah1[4], al0[4], al1[4];
        ldsm4(ah0, aH0 + ks * 32);
        ldsm4(ah1, aH1 + ks * 32);
        ldsm4(al0, aL0 + ks * 32);
        ldsm4(al1, aL1 + ks * 32);
        unsigned bHA = bH + ks * 16 * WST * 2;
        unsigned bLA = bL + ks * 16 * WST * 2;
        #pragma unroll
        for (int p = 0; p < 4; p++) {
            unsigned bh[4], bl[4];
            ldsm4t(bh, bHA + p * 32);
            ldsm4t(bl, bLA + p * 32);
            mma_bf16(acc[0][2 * p],     ah0, bh[0], bh[1]);
            mma_bf16(acc[0][2 * p],     ah0, bl[0], bl[1]);
            mma_bf16(acc[0][2 * p],     al0, bh[0], bh[1]);
            mma_bf16(acc[0][2 * p + 1], ah0, bh[2], bh[3]);
            mma_bf16(acc[0][2 * p + 1], ah0, bl[2], bl[3]);
            mma_bf16(acc[0][2 * p + 1], al0, bh[2], bh[3]);
            mma_bf16(acc[1][2 * p],     ah1, bh[0], bh[1]);
            mma_bf16(acc[1][2 * p],     ah1, bl[0], bl[1]);
            mma_bf16(acc[1][2 * p],     al1, bh[0], bh[1]);
            mma_bf16(acc[1][2 * p + 1], ah1, bh[2], bh[3]);
            mma_bf16(acc[1][2 * p + 1], ah1, bl[2], bl[3]);
            mma_bf16(acc[1][2 * p + 1], al1, bh[2], bh[3]);
        }
    }

    int grp = lane >> 2, tig = lane & 3;
    #pragma unroll
    for (int mt = 0; mt < 2; mt++) {
        #pragma unroll
        for (int half = 0; half < 2; half++) {
            int e = m0 + mb + mt * 16 + grp + half * 8;
            if (e < EE) {
                int pos = g_pos[e];
                float* dst = &g_K2[(size_t)pos * 256];
                #pragma unroll
                for (int n8 = 0; n8 < 8; n8++) {
                    int col = nb + n8 * 8 + tig * 2;
                    float v0 = fmaxf(acc[mt][n8][half * 2]     + b2s[col],     0.f);
                    float v1 = fmaxf(acc[mt][n8][half * 2 + 1] + b2s[col + 1], 0.f);
                    *(float2*)&dst[col] = make_float2(v0, v1);
                }
            }
        }
    }
}

// AW split bf16: AW[j][c*32+i] = ker3_w[c][i*32+j]; AW[j][8192+i] = ker3_b[i*32+j]
__global__ void k_aw(const float* __restrict__ w3, const float* __restrict__ b3) {
    int idx = blockIdx.x * blockDim.x + threadIdx.x;
    if (idx >= 32 * ACOLS) return;
    int j = idx / ACOLS, r = idx % ACOLS;
    float v;
    if (r < 8192) {
        int c = r >> 5, i = r & 31;
        v = w3[c * 1024 + i * 32 + j];
    } else {
        v = b3[(r - 8192) * 32 + j];
    }
    unsigned short h, l;
    bfsplit(v, h, l);
    g_AWhi[idx] = h;
    g_AWlo[idx] = l;
}

// A = H @ AW via 3-term split-bf16 mma — 64x256 tile, K=32
__global__ void __launch_bounds__(256) k_gemmA() {
    __shared__ unsigned short Hh[64 * 40];
    __shared__ unsigned short Hl[64 * 40];
    __shared__ unsigned short AWh[32 * WST];
    __shared__ unsigned short AWl[32 * WST];
    int tid = threadIdx.x;
    int m0 = blockIdx.y * 64;
    int n0 = blockIdx.x * 256;

    for (int i = tid; i < 1024; i += 256) {
        int node = i >> 4, kp = i & 15;
        float2 v = make_float2(0.f, 0.f);
        if (m0 + node < NN) v = *(const float2*)&g_H[(m0 + node) * 32 + kp * 2];
        unsigned short hx, lx, hy, ly;
        bfsplit(v.x, hx, lx);
        bfsplit(v.y, hy, ly);
        *(unsigned*)&Hh[node * 40 + kp * 2] = ((unsigned)hy << 16) | hx;
        *(unsigned*)&Hl[node * 40 + kp * 2] = ((unsigned)ly << 16) | lx;
    }
    const unsigned* awh = (const unsigned*)g_AWhi;
    const unsigned* awl = (const unsigned*)g_AWlo;
    for (int i = tid; i < 4096; i += 256) {
        int j = i >> 7, n2 = i & 127;
        int col = n0 + n2 * 2;
        unsigned vh = 0u, vl = 0u;
        if (col < ACOLS) {
            vh = awh[j * (ACOLS / 2) + (col >> 1)];
            vl = awl[j * (ACOLS / 2) + (col >> 1)];
        }
        *(unsigned*)&AWh[j * WST + n2 * 2] = vh;
        *(unsigned*)&AWl[j * WST + n2 * 2] = vl;
    }
    __syncthreads();

    int lane = tid & 31, warp = tid >> 5;
    int mb = (warp >> 2) * 32, nb = (warp & 3) * 64;
    unsigned aH0 = sptr(&Hh[(mb + (lane & 15)) * 40]) + (lane >> 4) * 16;
    unsigned aH1 = aH0 + 16 * 40 * 2;
    unsigned aL0 = sptr(&Hl[(mb + (lane & 15)) * 40]) + (lane >> 4) * 16;
    unsigned aL1 = aL0 + 16 * 40 * 2;
    unsigned bH  = sptr(&AWh[(lane & 15) * WST + nb + (lane >> 4) * 8]);
    unsigned bL  = sptr(&AWl[(lane & 15) * WST + nb + (lane >> 4) * 8]);
    float acc[2][8][4];
    #pragma unroll
    for (int i = 0; i < 2; i++)
        #pragma unroll
        for (int j = 0; j < 8; j++)
            #pragma unroll
            for (int q = 0; q < 4; q++) acc[i][j][q] = 0.f;

    #pragma unroll
    for (int ks = 0; ks < 2; ks++) {
        unsigned ah0[4], ah1[4], al0[4], al1[4];
        ldsm4(ah0, aH0 + ks * 32);
        ldsm4(ah1, aH1 + ks * 32);
        ldsm4(al0, aL0 + ks * 32);
        ldsm4(al1, aL1 + ks * 32);
        unsigned bHA = bH + ks * 16 * WST * 2;
        unsigned bLA = bL + ks * 16 * WST * 2;
        #pragma unroll
        for (int p = 0; p < 4; p++) {
            unsigned bh[4], bl[4];
            ldsm4t(bh, bHA + p * 32);
            ldsm4t(bl, bLA + p * 32);
            mma_bf16(acc[0][2 * p],     ah0, bh[0], bh[1]);
            mma_bf16(acc[0][2 * p],     ah0, bl[0], bl[1]);
            mma_bf16(acc[0][2 * p],     al0, bh[0], bh[1]);
            mma_bf16(acc[0][2 * p + 1], ah0, bh[2], bh[3]);
            mma_bf16(acc[0][2 * p + 1], ah0, bl[2], bl[3]);
            mma_bf16(acc[0][2 * p + 1], al0, bh[2], bh[3]);
            mma_bf16(acc[1][2 * p],     ah1, bh[0], bh[1]);
            mma_bf16(acc[1][2 * p],     ah1, bl[0], bl[1]);
            mma_bf16(acc[1][2 * p],     al1, bh[0], bh[1]);
            mma_bf16(acc[1][2 * p + 1], ah1, bh[2], bh[3]);
            mma_bf16(acc[1][2 * p + 1], ah1, bl[2], bl[3]);
            mma_bf16(acc[1][2 * p + 1], al1, bh[2], bh[3]);
        }
    }

    int grp = lane >> 2, tig = lane & 3;
    #pragma unroll
    for (int mt = 0; mt < 2; mt++) {
        #pragma unroll
        for (int half = 0; half < 2; half++) {
            int node = m0 + mb + mt * 16 + grp + half * 8;
            if (node < NN) {
                float* dst = &g_A[(size_t)node * ACOLS];
                #pragma unroll
                for (int n8 = 0; n8 < 8; n8++) {
                    int col = n0 + nb + n8 * 8 + tig * 2;
                    if (col < ACOLS)
                        *(float2*)&dst[col] =
                            make_float2(acc[mt][n8][half * 2], acc[mt][n8][half * 2 + 1]);
                }
            }
        }
    }
}

// persistent fused M + coord-MLP + scatter (unchanged from R10 winner)
__global__ void __launch_bounds__(256, 2) k_m(const float* __restrict__ cm1w,
                                              const float* __restrict__ cm1b,
                                              const float* __restrict__ cm2w,
                                              const float* __restrict__ cm2b) {
    extern __shared__ float sm[];
    float* As = sm;                  // ACOLS
    float* K0 = sm + ACOLS;          // 32*KST
    float* K1 = K0 + 32 * KST;       // 32*KST
    float* Ms = K1 + 32 * KST;       // 32*MST
    __shared__ float c1s[1024];
    __shared__ float c1bs[32], c2s[32];
    __shared__ float cm2bv;
    __shared__ int nsS, neS;
    int tid = threadIdx.x;
    int b = blockIdx.x;
    if (tid == 0) {
        long long t1 = (long long)b * EE;
        int lo = 0, hi = NN;
        while (lo < hi) {
            int mid = (lo + hi) >> 1;
            if ((long long)g_coloff[mid] * NBLK >= t1) hi = mid; else lo = mid + 1;
        }
        nsS = lo;
        long long t2 = (long long)(b + 1) * EE;
        hi = NN;
        while (lo < hi) {
            int mid = (lo + hi) >> 1;
            if ((long long)g_coloff[mid] * NBLK >= t2) hi = mid; else lo = mid + 1;
        }
        neS = lo;
        cm2bv = cm2b[0];
    }
    for (int i = tid; i < 1024; i += 256) c1s[i] = cm1w[i];
    if (tid < 32) { c1bs[tid] = cm1b[tid]; c2s[tid] = cm2w[tid]; }
    __syncthreads();
    int ns = nsS, ne = neS;

    int n = ns;
    int begN = (n < ne) ? g_coloff[n] : 0, endN = begN;
    while (n < ne) {
        endN = g_coloff[n + 1];
        if (endN > begN) break;
        n++; begN = endN;
    }
    if (n >= ne) return;

    int lane = tid & 31, wrp = tid >> 5;
    int eslot = tid >> 3, colgrp = tid & 7;
    float c1r[32];
    #pragma unroll
    for (int j = 0; j < 32; j++) c1r[j] = c1s[j * 32 + lane];

    {
        const float4* src = (const float4*)&g_A[(size_t)n * ACOLS];
        for (int i = tid; i < ACOLS / 4; i += 256) cpa16(&As[i * 4], src + i);
        cpa_commit();
        int cnt0 = min(32, endN - begN);
        const float4* kf = (const float4*)&g_K2[(size_t)begN * 256];
        for (int i = tid; i < cnt0 * 64; i += 256)
            cpa16(&K0[(i >> 6) * KST + (i & 63) * 4], kf + i);
        cpa_commit();
    }

    int base = 0, kpar = 0, prevn = n;
    while (n < ne) {
        int nE = endN - begN;
        int cnt = min(32, nE - base);
        if (n != prevn) {
            const float4* src = (const float4*)&g_A[(size_t)n * ACOLS];
            for (int i = tid; i < ACOLS / 4; i += 256) cpa16(&As[i * 4], src + i);
            cpa_commit();
            prevn = n;
        }
        int n2 = n, base2 = base + 32, beg2 = begN, end2 = endN;
        if (base2 >= nE) {
            base2 = 0; n2 = n + 1; beg2 = endN;
            while (n2 < ne) {
                end2 = g_coloff[n2 + 1];
                if (end2 > beg2) break;
                n2++; beg2 = end2;
            }
        }
        if (n2 < ne) {
            int cnt2 = min(32, end2 - beg2 - base2);
            const float4* kf = (const float4*)&g_K2[(size_t)(beg2 + base2) * 256];
            float* Kn = kpar ? K0 : K1;
            for (int i = tid; i < cnt2 * 64; i += 256)
                cpa16(&Kn[(i >> 6) * KST + (i & 63) * 4], kf + i);
        }
        cpa_commit();
        cpa_wait1();
        __syncthreads();

        const float* Kc = kpar ? K1 : K0;
        if (eslot < cnt) {
            float4 acc = *(float4*)&As[8192 + colgrp * 4];
            const float4* kr4 = (const float4*)&Kc[eslot * KST];
            #pragma unroll 8
            for (int c4i = 0; c4i < 64; c4i++) {
                float4 kv = kr4[c4i];
                float4 av;
                av = *(float4*)&As[(c4i * 4 + 0) * 32 + colgrp * 4];
                acc.x += kv.x * av.x; acc.y += kv.x * av.y; acc.z += kv.x * av.z; acc.w += kv.x * av.w;
                av = *(float4*)&As[(c4i * 4 + 1) * 32 + colgrp * 4];
                acc.x += kv.y * av.x; acc.y += kv.y * av.y; acc.z += kv.y * av.z; acc.w += kv.y * av.w;
                av = *(float4*)&As[(c4i * 4 + 2) * 32 + colgrp * 4];
                acc.x += kv.z * av.x; acc.y += kv.z * av.y; acc.z += kv.z * av.z; acc.w += kv.z * av.w;
                av = *(float4*)&As[(c4i * 4 + 3) * 32 + colgrp * 4];
                acc.x += kv.w * av.x; acc.y += kv.w * av.y; acc.z += kv.w * av.z; acc.w += kv.w * av.w;
            }
            *(float4*)&Ms[eslot * MST + colgrp * 4] = acc;
        }
        __syncthreads();

        #pragma unroll
        for (int q = 0; q < 4; q++) {
            int es = wrp * 4 + q;
            if (es < cnt) {
                const float* mrow = &Ms[es * MST];
                float t0 = 0.f, t1 = 0.f, t2 = 0.f, t3 = 0.f;
                #pragma unroll
                for (int j = 0; j < 32; j += 4) {
                    t0 += mrow[j]     * c1r[j];
                    t1 += mrow[j + 1] * c1r[j + 1];
                    t2 += mrow[j + 2] * c1r[j + 2];
                    t3 += mrow[j + 3] * c1r[j + 3];
                }
                float t = fmaxf(c1bs[lane] + ((t0 + t1) + (t2 + t3)), 0.f);
                float p = t * c2s[lane];
                #pragma unroll
                for (int off = 16; off > 0; off >>= 1)
                    p += __shfl_xor_sync(0xffffffffu, p, off);
                float we = p + cm2bv;
                int row = g_rows[begN + base + es];
                float mv = mrow[lane];
                atomicAdd(&g_AGG[row * 32 + lane], mv);
                if (lane < 3) {
                    float d = g_COORD[row * 3 + lane] - g_COORD[n * 3 + lane];
                    atomicAdd(&g_CD[row * 3 + lane], d * we);
                }
            }
        }
        n = n2; base = base2; begN = beg2; endN = end2;
        kpar ^= 1;
    }
}

__global__ void k_update() {
    int i = blockIdx.x * blockDim.x + threadIdx.x;
    if (i < NN * WD) {
        int n = i >> 5;
        float inv = 1.f / g_CNT[n];
        g_H[i] = fmaxf(g_H[i] + g_AGG[i] * inv, 0.f);
        g_AGG[i] = 0.f;
    }
    if (i < NN * 3) {
        int n = i / 3;
        g_COORD[i] += g_CD[i] / g_CNT[n];
        g_CD[i] = 0.f;
    }
}

__global__ void k_final(const float* __restrict__ f2aw, const float* __restrict__ f2ab,
                        const float* __restrict__ f2bw, const float* __restrict__ f2bb,
                        float* __restrict__ out) {
    __shared__ float wa[2048];
    __shared__ float ba[64];
    __shared__ float wb[64];
    int tid = threadIdx.x;
    for (int i = tid; i < 2048; i += 256) wa[i] = f2aw[i];
    if (tid < 64) { ba[tid] = f2ab[tid]; wb[tid] = f2bw[tid]; }
    __syncthreads();
    int n = blockIdx.x * blockDim.x + tid;
    if (n < NN) {
        float h[32];
        #pragma unroll
        for (int j = 0; j < 32; j++) h[j] = g_H[n * 32 + j];
        float o = f2bb[0];
        #pragma unroll 4
        for (int u = 0; u < 64; u++) {
            float s = ba[u];
            #pragma unroll
            for (int j = 0; j < 32; j++) s += h[j] * wa[j * 64 + u];
            o += fmaxf(s, 0.f) * wb[u];
        }
        out[n] = o;
    }
    int tot = gridDim.x * blockDim.x;
    for (int i = n; i < NN * 3; i += tot) out[NN + i] = g_COORD[i];
}

// ---------------- host ----------------
extern "C" void kernel_launch(void* const* d_in, const int* in_sizes, int n_in,
                              void* d_out, int out_size) {
    const float* x      = (const float*)d_in[0];
    const int*   ei     = (const int*)d_in[1];     // int32 (JAX x64 disabled)
    const float* ea     = (const float*)d_in[2];
    const float* coords = (const float*)d_in[3];
    const float* fc1w   = (const float*)d_in[4];
    const float* fc1b   = (const float*)d_in[5];
    const float* k1w    = (const float*)d_in[6];
    const float* k1b    = (const float*)d_in[7];
    const float* k2w    = (const float*)d_in[8];
    const float* k2b    = (const float*)d_in[9];
    const float* k3w    = (const float*)d_in[10];
    const float* k3b    = (const float*)d_in[11];
    const float* cm1w   = (const float*)d_in[12];
    const float* cm1b   = (const float*)d_in[13];
    const float* cm2w   = (const float*)d_in[14];
    const float* cm2b   = (const float*)d_in[15];
    const float* f2aw   = (const float*)d_in[16];
    const float* f2ab   = (const float*)d_in[17];
    const float* f2bw   = (const float*)d_in[18];
    const float* f2bb   = (const float*)d_in[19];

    const int smemM  = (ACOLS + 2 * 32 * KST + 32 * MST) * 4;        // 104064 B
    const int smemG2 = (2 * 64 * RST + 2 * 128 * WST) * 2 + 256 * 4; // 171008 B
    cudaFuncSetAttribute(k_m, cudaFuncAttributeMaxDynamicSharedMemorySize, smemM);
    cudaFuncSetAttribute(k_gemm2, cudaFuncAttributeMaxDynamicSharedMemorySize, smemG2);

    // slot 4 = k_gemm2 (profiler capture target — verify tensor-pipe utilization)
    k_hist<<<(EE + 255) / 256, 256>>>(ei);                              // 1
    k_scan<<<1, 1024>>>();                                              // 2
    k_scatter<<<(EE + 255) / 256, 256>>>(ei);                           // 3
    k_gemm2<<<(EE + 63) / 64, 256, smemG2>>>(ea, k1w, k1b, k2w, k2b);   // 4
    k_init<<<(NN * WD + 255) / 256, 256>>>(x, coords, fc1w, fc1b);      // 5
    k_aw<<<(32 * ACOLS + 255) / 256, 256>>>(k3w, k3b);                  // 6

    for (int d = 0; d < DEPTH; d++) {
        k_gemmA<<<dim3((ACOLS + 255) / 256, (NN + 63) / 64), 256>>>();
        k_m<<<NBLK, 256, smemM>>>(cm1w, cm1b, cm2w, cm2b);
        k_update<<<(NN * WD + 255) / 256, 256>>>();
    }
    k_final<<<(NN + 255) / 256, 256>>>(f2aw, f2ab, f2bw, f2bb, (float*)d_out);
    k_cleanup<<<(NN + 255) / 256, 256>>>();
}

// round 13
// speedup vs baseline: 1.5336x; 1.1022x over previous
#include <cuda_runtime.h>
#include <cuda_bf16.h>
#include <cstdint>

#define NN 10000
#define EE 300000
#define WD 32
#define DEPTH 4
#define ACOLS 8224           // 8192 (A) + 32 (bias part)
#define NBLK 148             // persistent k_m blocks (1 per SM)
#define RST 136              // R1 bf16 smem row stride (ushort)
#define WST 264              // W2/AW bf16 smem row stride (ushort)
#define KSB 264              // k_m K2 smem row stride (ushort), banks 4r%32 conflict-free
#define AST 40               // k_m A-slab smem row stride (ushort), banks 20r%32 conflict-free
#define MST 34               // Ms row stride (float)

// ---------------- scratch (static __device__) ----------------
__device__ __align__(16) unsigned short g_K2h[(size_t)EE * 256];  // K2 split bf16 hi, PERMUTED
__device__ __align__(16) unsigned short g_K2l[(size_t)EE * 256];  // K2 split bf16 lo
__device__ __align__(16) unsigned short g_Ah[(size_t)NN * ACOLS]; // A slab split bf16 hi
__device__ __align__(16) unsigned short g_Al[(size_t)NN * ACOLS]; // A slab split bf16 lo
__device__ __align__(16) unsigned short g_AWhi[32 * ACOLS];
__device__ __align__(16) unsigned short g_AWlo[32 * ACOLS];
__device__ __align__(16) float g_H[NN * WD];
__device__ __align__(16) float g_AGG[NN * WD];
__device__ __align__(16) float g_COORD[NN * 3];
__device__ __align__(16) float g_CD[NN * 3];
__device__ float g_CNT[NN];
__device__ int   g_colcnt[NN];
__device__ int   g_rowcnt[NN];
__device__ int   g_coloff[NN + 1];
__device__ int   g_cur[NN];
__device__ int   g_pos[EE];
__device__ int   g_rows[EE];

// ---------------- helpers ----------------
__device__ __forceinline__ void cpa16(void* smem_dst, const void* gsrc) {
    unsigned s = (unsigned)__cvta_generic_to_shared(smem_dst);
    asm volatile("cp.async.cg.shared.global [%0], [%1], 16;\n" :: "r"(s), "l"(gsrc));
}
__device__ __forceinline__ void cpa_commit() { asm volatile("cp.async.commit_group;\n"); }
__device__ __forceinline__ void cpa_wait1()  { asm volatile("cp.async.wait_group 1;\n"); }

__device__ __forceinline__ void bfsplit(float x, unsigned short& h, unsigned short& l) {
    __nv_bfloat16 bh = __float2bfloat16(x);
    h = *reinterpret_cast<unsigned short*>(&bh);
    float r = x - __bfloat162float(bh);
    __nv_bfloat16 bl = __float2bfloat16(r);
    l = *reinterpret_cast<unsigned short*>(&bl);
}
__device__ __forceinline__ float bf2f(unsigned short u) {
    __nv_bfloat16 b = *reinterpret_cast<__nv_bfloat16*>(&u);
    return __bfloat162float(b);
}
__device__ __forceinline__ unsigned sptr(const void* p) {
    return (unsigned)__cvta_generic_to_shared(p);
}
__device__ __forceinline__ void ldsm4(unsigned* r, unsigned a) {
    asm volatile("ldmatrix.sync.aligned.m8n8.x4.shared.b16 {%0,%1,%2,%3}, [%4];"
        : "=r"(r[0]), "=r"(r[1]), "=r"(r[2]), "=r"(r[3]) : "r"(a));
}
__device__ __forceinline__ void ldsm4t(unsigned* r, unsigned a) {
    asm volatile("ldmatrix.sync.aligned.m8n8.x4.trans.shared.b16 {%0,%1,%2,%3}, [%4];"
        : "=r"(r[0]), "=r"(r[1]), "=r"(r[2]), "=r"(r[3]) : "r"(a));
}
__device__ __forceinline__ void mma_bf16(float* c, const unsigned* a, unsigned b0, unsigned b1) {
    asm volatile("mma.sync.aligned.m16n8k16.row.col.f32.bf16.bf16.f32 "
        "{%0,%1,%2,%3},{%4,%5,%6,%7},{%8,%9},{%0,%1,%2,%3};"
        : "+f"(c[0]), "+f"(c[1]), "+f"(c[2]), "+f"(c[3])
        : "r"(a[0]), "r"(a[1]), "r"(a[2]), "r"(a[3]), "r"(b0), "r"(b1));
}

// ---------------- setup ----------------
__global__ void k_init(const float* __restrict__ x, const float* __restrict__ coords,
                       const float* __restrict__ fc1w, const float* __restrict__ fc1b) {
    int i = blockIdx.x * blockDim.x + threadIdx.x;
    if (i < NN * 3) g_COORD[i] = coords[i];
    if (i < NN * WD) {
        int n = i / WD, o = i % WD;
        float a = fc1b[o];
        #pragma unroll
        for (int j = 0; j < 3; j++) a += x[n * 3 + j] * fc1w[j * WD + o];
        g_H[i] = a;
    }
}

__global__ void k_hist(const int* __restrict__ ei) {
    int e = blockIdx.x * blockDim.x + threadIdx.x;
    if (e < EE) {
        atomicAdd(&g_rowcnt[ei[e]], 1);
        atomicAdd(&g_colcnt[ei[EE + e]], 1);
    }
}

__global__ void k_scan() {
    __shared__ int sh[1024];
    __shared__ int carry;
    int t = threadIdx.x;
    if (t == 0) carry = 0;
    __syncthreads();
    for (int base = 0; base < NN; base += 1024) {
        int v = (base + t < NN) ? g_colcnt[base + t] : 0;
        sh[t] = v;
        __syncthreads();
        for (int off = 1; off < 1024; off <<= 1) {
            int y = (t >= off) ? sh[t - off] : 0;
            __syncthreads();
            sh[t] += y;
            __syncthreads();
        }
        int incl = sh[t];
        if (base + t < NN) {
            int ex = carry + incl - v;
            g_coloff[base + t] = ex;
            g_cur[base + t] = ex;
            g_CNT[base + t] = fmaxf(1.f, (float)g_rowcnt[base + t]);
        }
        int tot = sh[1023];
        __syncthreads();
        if (t == 0) carry += tot;
        __syncthreads();
    }
    if (t == 0) g_coloff[NN] = carry;
}

__global__ void k_scatter(const int* __restrict__ ei) {
    int e = blockIdx.x * blockDim.x + threadIdx.x;
    if (e < EE) {
        int r = ei[e], c = ei[EE + e];
        int p = atomicAdd(&g_cur[c], 1);
        g_pos[e] = p;
        g_rows[p] = r;
    }
}

__global__ void k_cleanup() {
    int i = blockIdx.x * blockDim.x + threadIdx.x;
    if (i < NN) { g_colcnt[i] = 0; g_rowcnt[i] = 0; }
}

// ---------------- gemm2: K2 = relu(relu(ea@W1+b1)@W2+b2), 3-term split-bf16 mma ------
__global__ void __launch_bounds__(256) k_gemm2(const float* __restrict__ ea,
                                               const float* __restrict__ w1,
                                               const float* __restrict__ b1,
                                               const float* __restrict__ w2,
                                               const float* __restrict__ b2) {
    extern __shared__ unsigned short s2u[];
    unsigned short* R1h = s2u;
    unsigned short* R1l = s2u + 64 * RST;
    unsigned short* W2h = s2u + 2 * 64 * RST;
    unsigned short* W2l = W2h + 128 * WST;
    float* b2s = (float*)(W2l + 128 * WST);
    __shared__ float eas[64 * 6];
    __shared__ float w1s[6 * 128];
    __shared__ float b1s[128];
    int tid = threadIdx.x;
    int m0 = blockIdx.x * 64;

    for (int i = tid; i < 16384; i += 256) {
        int k = i >> 7, n2 = i & 127;
        float2 v = *(const float2*)&w2[k * 256 + n2 * 2];
        unsigned short hx, lx, hy, ly;
        bfsplit(v.x, hx, lx);
        bfsplit(v.y, hy, ly);
        *(unsigned*)&W2h[k * WST + n2 * 2] = ((unsigned)hy << 16) | hx;
        *(unsigned*)&W2l[k * WST + n2 * 2] = ((unsigned)ly << 16) | lx;
    }
    for (int i = tid; i < 64 * 6; i += 256) {
        int g = m0 * 6 + i;
        eas[i] = (g < EE * 6) ? ea[g] : 0.f;
    }
    for (int i = tid; i < 768; i += 256) w1s[i] = w1[i];
    if (tid < 128) b1s[tid] = b1[tid];
    b2s[tid] = b2[tid];
    __syncthreads();

    {
        int r = tid & 63, kg = tid >> 6;
        float ev[6];
        #pragma unroll
        for (int j = 0; j < 6; j++) ev[j] = eas[r * 6 + j];
        #pragma unroll
        for (int q = 0; q < 32; q += 2) {
            int k0 = kg * 32 + q;
            float a0 = b1s[k0], a1 = b1s[k0 + 1];
            #pragma unroll
            for (int j = 0; j < 6; j++) {
                a0 += ev[j] * w1s[j * 128 + k0];
                a1 += ev[j] * w1s[j * 128 + k0 + 1];
            }
            a0 = fmaxf(a0, 0.f); a1 = fmaxf(a1, 0.f);
            unsigned short h0, l0, h1, l1;
            bfsplit(a0, h0, l0);
            bfsplit(a1, h1, l1);
            *(unsigned*)&R1h[r * RST + k0] = ((unsigned)h1 << 16) | h0;
            *(unsigned*)&R1l[r * RST + k0] = ((unsigned)l1 << 16) | l0;
        }
    }
    __syncthreads();

    int lane = tid & 31, warp = tid >> 5;
    int mb = (warp >> 2) * 32, nb = (warp & 3) * 64;
    unsigned aH0 = sptr(&R1h[(mb + (lane & 15)) * RST]) + (lane >> 4) * 16;
    unsigned aH1 = aH0 + 16 * RST * 2;
    unsigned aL0 = sptr(&R1l[(mb + (lane & 15)) * RST]) + (lane >> 4) * 16;
    unsigned aL1 = aL0 + 16 * RST * 2;
    unsigned bH  = sptr(&W2h[(lane & 15) * WST + nb + (lane >> 4) * 8]);
    unsigned bL  = sptr(&W2l[(lane & 15) * WST + nb + (lane >> 4) * 8]);
    float acc[2][8][4];
    #pragma unroll
    for (int i = 0; i < 2; i++)
        #pragma unroll
        for (int j = 0; j < 8; j++)
            #pragma unroll
            for (int q = 0; q < 4; q++) acc[i][j][q] = 0.f;

    #pragma unroll
    for (int ks = 0; ks < 8; ks++) {
        unsigned ah0[4], ah1[4], al0[4], al1[4];
        ldsm4(ah0, aH0 + ks * 32);
        ldsm4(ah1, aH1 + ks * 32);
        ldsm4(al0, aL0 + ks * 32);
        ldsm4(al1, aL1 + ks * 32);
        unsigned bHA = bH + ks * 16 * WST * 2;
        unsigned bLA = bL + ks * 16 * WST * 2;
        #pragma unroll
        for (int p = 0; p < 4; p++) {
            unsigned bh[4], bl[4];
            ldsm4t(bh, bHA + p * 32);
            ldsm4t(bl, bLA + p * 32);
            mma_bf16(acc[0][2 * p],     ah0, bh[0], bh[1]);
            mma_bf16(acc[0][2 * p],     ah0, bl[0], bl[1]);
            mma_bf16(acc[0][2 * p],     al0, bh[0], bh[1]);
            mma_bf16(acc[0][2 * p + 1], ah0, bh[2], bh[3]);
            mma_bf16(acc[0][2 * p + 1], ah0, bl[2], bl[3]);
            mma_bf16(acc[0][2 * p + 1], al0, bh[2], bh[3]);
            mma_bf16(acc[1][2 * p],     ah1, bh[0], bh[1]);
            mma_bf16(acc[1][2 * p],     ah1, bl[0], bl[1]);
            mma_bf16(acc[1][2 * p],     al1, bh[0], bh[1]);
            mma_bf16(acc[1][2 * p + 1], ah1, bh[2], bh[3]);
            mma_bf16(acc[1][2 * p + 1], ah1, bl[2], bl[3]);
            mma_bf16(acc[1][2 * p + 1], al1, bh[2], bh[3]);
        }
    }

    int grp = lane >> 2, tig = lane & 3;
    #pragma unroll
    for (int mt = 0; mt < 2; mt++) {
        #pragma unroll
        for (int half = 0; half < 2; half++) {
            int e = m0 + mb + mt * 16 + grp + half * 8;
            if (e < EE) {
                size_t prow = (size_t)g_pos[e] * 256;
                #pragma unroll
                for (int n8 = 0; n8 < 8; n8++) {
                    int col = nb + n8 * 8 + tig * 2;
                    float v0 = fmaxf(acc[mt][n8][half * 2]     + b2s[col],     0.f);
                    float v1 = fmaxf(acc[mt][n8][half * 2 + 1] + b2s[col + 1], 0.f);
                    unsigned short h0, l0, h1, l1;
                    bfsplit(v0, h0, l0);
                    bfsplit(v1, h1, l1);
                    *(unsigned*)&g_K2h[prow + col] = ((unsigned)h1 << 16) | h0;
                    *(unsigned*)&g_K2l[prow + col] = ((unsigned)l1 << 16) | l0;
                }
            }
        }
    }
}

// AW split bf16
__global__ void k_aw(const float* __restrict__ w3, const float* __restrict__ b3) {
    int idx = blockIdx.x * blockDim.x + threadIdx.x;
    if (idx >= 32 * ACOLS) return;
    int j = idx / ACOLS, r = idx % ACOLS;
    float v;
    if (r < 8192) {
        int c = r >> 5, i = r & 31;
        v = w3[c * 1024 + i * 32 + j];
    } else {
        v = b3[(r - 8192) * 32 + j];
    }
    unsigned short h, l;
    bfsplit(v, h, l);
    g_AWhi[idx] = h;
    g_AWlo[idx] = l;
}

// A = H @ AW via 3-term split-bf16 mma — outputs split bf16 g_Ah/g_Al
__global__ void __launch_bounds__(256) k_gemmA() {
    __shared__ unsigned short Hh[64 * 40];
    __shared__ unsigned short Hl[64 * 40];
    __shared__ unsigned short AWh[32 * WST];
    __shared__ unsigned short AWl[32 * WST];
    int tid = threadIdx.x;
    int m0 = blockIdx.y * 64;
    int n0 = blockIdx.x * 256;

    for (int i = tid; i < 1024; i += 256) {
        int node = i >> 4, kp = i & 15;
        float2 v = make_float2(0.f, 0.f);
        if (m0 + node < NN) v = *(const float2*)&g_H[(m0 + node) * 32 + kp * 2];
        unsigned short hx, lx, hy, ly;
        bfsplit(v.x, hx, lx);
        bfsplit(v.y, hy, ly);
        *(unsigned*)&Hh[node * 40 + kp * 2] = ((unsigned)hy << 16) | hx;
        *(unsigned*)&Hl[node * 40 + kp * 2] = ((unsigned)ly << 16) | lx;
    }
    const unsigned* awh = (const unsigned*)g_AWhi;
    const unsigned* awl = (const unsigned*)g_AWlo;
    for (int i = tid; i < 4096; i += 256) {
        int j = i >> 7, n2 = i & 127;
        int col = n0 + n2 * 2;
        unsigned vh = 0u, vl = 0u;
        if (col < ACOLS) {
            vh = awh[j * (ACOLS / 2) + (col >> 1)];
            vl = awl[j * (ACOLS / 2) + (col >> 1)];
        }
        *(unsigned*)&AWh[j * WST + n2 * 2] = vh;
        *(unsigned*)&AWl[j * WST + n2 * 2] = vl;
    }
    __syncthreads();

    int lane = tid & 31, warp = tid >> 5;
    int mb = (warp >> 2) * 32, nb = (warp & 3) * 64;
    unsigned aH0 = sptr(&Hh[(mb + (lane & 15)) * 40]) + (lane >> 4) * 16;
    unsigned aH1 = aH0 + 16 * 40 * 2;
    unsigned aL0 = sptr(&Hl[(mb + (lane & 15)) * 40]) + (lane >> 4) * 16;
    unsigned aL1 = aL0 + 16 * 40 * 2;
    unsigned bH  = sptr(&AWh[(lane & 15) * WST + nb + (lane >> 4) * 8]);
    unsigned bL  = sptr(&AWl[(lane & 15) * WST + nb + (lane >> 4) * 8]);
    float acc[2][8][4];
    #pragma unroll
    for (int i = 0; i < 2; i++)
        #pragma unroll
        for (int j = 0; j < 8; j++)
            #pragma unroll
            for (int q = 0; q < 4; q++) acc[i][j][q] = 0.f;

    #pragma unroll
    for (int ks = 0; ks < 2; ks++) {
        unsigned ah0[4], ah1[4], al0[4], al1[4];
        ldsm4(ah0, aH0 + ks * 32);
        ldsm4(ah1, aH1 + ks * 32);
        ldsm4(al0, aL0 + ks * 32);
        ldsm4(al1, aL1 + ks * 32);
        unsigned bHA = bH + ks * 16 * WST * 2;
        unsigned bLA = bL + ks * 16 * WST * 2;
        #pragma unroll
        for (int p = 0; p < 4; p++) {
            unsigned bh[4], bl[4];
            ldsm4t(bh, bHA + p * 32);
            ldsm4t(bl, bLA + p * 32);
            mma_bf16(acc[0][2 * p],     ah0, bh[0], bh[1]);
            mma_bf16(acc[0][2 * p],     ah0, bl[0], bl[1]);
            mma_bf16(acc[0][2 * p],     al0, bh[0], bh[1]);
            mma_bf16(acc[0][2 * p + 1], ah0, bh[2], bh[3]);
            mma_bf16(acc[0][2 * p + 1], ah0, bl[2], bl[3]);
            mma_bf16(acc[0][2 * p + 1], al0, bh[2], bh[3]);
            mma_bf16(acc[1][2 * p],     ah1, bh[0], bh[1]);
            mma_bf16(acc[1][2 * p],     ah1, bl[0], bl[1]);
            mma_bf16(acc[1][2 * p],     al1, bh[0], bh[1]);
            mma_bf16(acc[1][2 * p + 1], ah1, bh[2], bh[3]);
            mma_bf16(acc[1][2 * p + 1], ah1, bl[2], bl[3]);
            mma_bf16(acc[1][2 * p + 1], al1, bh[2], bh[3]);
        }
    }

    int grp = lane >> 2, tig = lane & 3;
    #pragma unroll
    for (int mt = 0; mt < 2; mt++) {
        #pragma unroll
        for (int half = 0; half < 2; half++) {
            int node = m0 + mb + mt * 16 + grp + half * 8;
            if (node < NN) {
                size_t nrow = (size_t)node * ACOLS;
                #pragma unroll
                for (int n8 = 0; n8 < 8; n8++) {
                    int col = n0 + nb + n8 * 8 + tig * 2;
                    if (col < ACOLS) {
                        float v0 = acc[mt][n8][half * 2];
                        float v1 = acc[mt][n8][half * 2 + 1];
                        unsigned short h0, l0, h1, l1;
                        bfsplit(v0, h0, l0);
                        bfsplit(v1, h1, l1);
                        *(unsigned*)&g_Ah[nrow + col] = ((unsigned)h1 << 16) | h0;
                        *(unsigned*)&g_Al[nrow + col] = ((unsigned)l1 << 16) | l0;
                    }
                }
            }
        }
    }
}

// persistent fused M(tensor-core) + coord-MLP + scatter.
// 512 threads, 64-edge batches: 16 warps = 4 m-tiles x 2 n-tiles x 2 k-halves.
__global__ void __launch_bounds__(512, 1) k_m(const float* __restrict__ cm1w,
                                              const float* __restrict__ cm1b,
                                              const float* __restrict__ cm2w,
                                              const float* __restrict__ cm2b) {
    extern __shared__ unsigned short smu[];
    unsigned short* Ahs = smu;                         // 257*AST (row 256 = bias)
    unsigned short* Als = Ahs + 257 * AST;             // 257*AST
    unsigned short* K2b = Als + 257 * AST;             // 2 buffers x (h,l) x 64*KSB
    float* Ms = (float*)(K2b + 4 * 64 * KSB);          // 64*MST
    __shared__ int nsS, neS;
    int tid = threadIdx.x;
    int b = blockIdx.x;
    if (tid == 0) {
        long long t1 = (long long)b * EE;
        int lo = 0, hi = NN;
        while (lo < hi) {
            int mid = (lo + hi) >> 1;
            if ((long long)g_coloff[mid] * NBLK >= t1) hi = mid; else lo = mid + 1;
        }
        nsS = lo;
        long long t2 = (long long)(b + 1) * EE;
        hi = NN;
        while (lo < hi) {
            int mid = (lo + hi) >> 1;
            if ((long long)g_coloff[mid] * NBLK >= t2) hi = mid; else lo = mid + 1;
        }
        neS = lo;
    }
    __syncthreads();
    int ns = nsS, ne = neS;

    int n = ns;
    int begN = (n < ne) ? g_coloff[n] : 0, endN = begN;
    while (n < ne) {
        endN = g_coloff[n + 1];
        if (endN > begN) break;
        n++; begN = endN;
    }
    if (n >= ne) return;

    int lane = tid & 31, warp = tid >> 5;
    int mtile = warp & 3, ntile = (warp >> 2) & 1, khalf = warp >> 3;
    float c1r[32];
    #pragma unroll
    for (int j = 0; j < 32; j++) c1r[j] = cm1w[j * 32 + lane];
    float cbv = cm1b[lane], cwv = cm2w[lane], c2bv = cm2b[0];

    // prologue: A(n) slab + first K batch
    {
        const char* sH = (const char*)(g_Ah + (size_t)n * ACOLS);
        const char* sL = (const char*)(g_Al + (size_t)n * ACOLS);
        for (int i = tid; i < 1028; i += 512) {
            int srcoff, dstoff;
            if (i < 1024) { srcoff = i * 16; dstoff = (i >> 2) * 80 + (i & 3) * 16; }
            else { int q = i - 1024; srcoff = 16384 + q * 16; dstoff = 256 * 80 + q * 16; }
            cpa16((char*)Ahs + dstoff, sH + srcoff);
            cpa16((char*)Als + dstoff, sL + srcoff);
        }
        cpa_commit();
        int cnt0 = min(64, endN - begN);
        const char* kh = (const char*)(g_K2h + (size_t)begN * 256);
        const char* kl = (const char*)(g_K2l + (size_t)begN * 256);
        unsigned short* Kh = K2b;
        unsigned short* Kl = K2b + 64 * KSB;
        for (int i = tid; i < cnt0 * 32; i += 512) {
            int dstoff = (i >> 5) * KSB * 2 + (i & 31) * 16;
            cpa16((char*)Kh + dstoff, kh + i * 16);
            cpa16((char*)Kl + dstoff, kl + i * 16);
        }
        cpa_commit();
    }

    int base = 0, kpar = 0, prevn = n;
    while (n < ne) {
        int nE = endN - begN;
        int cnt = min(64, nE - base);
        if (n != prevn) {
            const char* sH = (const char*)(g_Ah + (size_t)n * ACOLS);
            const char* sL = (const char*)(g_Al + (size_t)n * ACOLS);
            for (int i = tid; i < 1028; i += 512) {
                int srcoff, dstoff;
                if (i < 1024) { srcoff = i * 16; dstoff = (i >> 2) * 80 + (i & 3) * 16; }
                else { int q = i - 1024; srcoff = 16384 + q * 16; dstoff = 256 * 80 + q * 16; }
                cpa16((char*)Ahs + dstoff, sH + srcoff);
                cpa16((char*)Als + dstoff, sL + srcoff);
            }
            cpa_commit();
            prevn = n;
        }
        int n2 = n, base2 = base + 64, beg2 = begN, end2 = endN;
        if (base2 >= nE) {
            base2 = 0; n2 = n + 1; beg2 = endN;
            while (n2 < ne) {
                end2 = g_coloff[n2 + 1];
                if (end2 > beg2) break;
                n2++; beg2 = end2;
            }
        }
        if (n2 < ne) {
            int cnt2 = min(64, end2 - beg2 - base2);
            const char* kh = (const char*)(g_K2h + (size_t)(beg2 + base2) * 256);
            const char* kl = (const char*)(g_K2l + (size_t)(beg2 + base2) * 256);
            unsigned short* Kh = K2b + (kpar ^ 1) * 2 * 64 * KSB;
            unsigned short* Kl = Kh + 64 * KSB;
            for (int i = tid; i < cnt2 * 32; i += 512) {
                int dstoff = (i >> 5) * KSB * 2 + (i & 31) * 16;
                cpa16((char*)Kh + dstoff, kh + i * 16);
                cpa16((char*)Kl + dstoff, kl + i * 16);
            }
        }
        cpa_commit();
        cpa_wait1();
        __syncthreads();

        // ---- tensor-core GEMM: M[64x32] = K2[64x256] @ A[256x32] (3-term split) ----
        unsigned short* Kh = K2b + kpar * 2 * 64 * KSB;
        unsigned short* Kl = Kh + 64 * KSB;
        unsigned aH = sptr(Kh + (mtile * 16 + (lane & 15)) * KSB) + (lane >> 4) * 16 + khalf * 256;
        unsigned aL = sptr(Kl + (mtile * 16 + (lane & 15)) * KSB) + (lane >> 4) * 16 + khalf * 256;
        unsigned bHa = sptr(Ahs + (khalf * 128 + (lane & 15)) * AST + ntile * 16 + (lane >> 4) * 8);
        unsigned bLa = sptr(Als + (khalf * 128 + (lane & 15)) * AST + ntile * 16 + (lane >> 4) * 8);
        float acc0[4] = {0.f, 0.f, 0.f, 0.f};
        float acc1[4] = {0.f, 0.f, 0.f, 0.f};
        #pragma unroll
        for (int ks = 0; ks < 8; ks++) {
            unsigned ah[4], al[4], bh[4], bl[4];
            ldsm4(ah, aH + ks * 32);
            ldsm4(al, aL + ks * 32);
            ldsm4t(bh, bHa + ks * 1280);
            ldsm4t(bl, bLa + ks * 1280);
            mma_bf16(acc0, ah, bh[0], bh[1]);
            mma_bf16(acc0, ah, bl[0], bl[1]);
            mma_bf16(acc0, al, bh[0], bh[1]);
            mma_bf16(acc1, ah, bh[2], bh[3]);
            mma_bf16(acc1, ah, bl[2], bl[3]);
            mma_bf16(acc1, al, bh[2], bh[3]);
        }
        int grp = lane >> 2, tig = lane & 3;
        int r0 = mtile * 16 + grp, r1 = r0 + 8;
        int col0 = ntile * 16 + tig * 2, col1 = col0 + 8;
        if (khalf == 0) {
            float b00 = bf2f(Ahs[256 * AST + col0]) + bf2f(Als[256 * AST + col0]);
            float b01 = bf2f(Ahs[256 * AST + col0 + 1]) + bf2f(Als[256 * AST + col0 + 1]);
            float b10 = bf2f(Ahs[256 * AST + col1]) + bf2f(Als[256 * AST + col1]);
            float b11 = bf2f(Ahs[256 * AST + col1 + 1]) + bf2f(Als[256 * AST + col1 + 1]);
            Ms[r0 * MST + col0]     = acc0[0] + b00;
            Ms[r0 * MST + col0 + 1] = acc0[1] + b01;
            Ms[r1 * MST + col0]     = acc0[2] + b00;
            Ms[r1 * MST + col0 + 1] = acc0[3] + b01;
            Ms[r0 * MST + col1]     = acc1[0] + b10;
            Ms[r0 * MST + col1 + 1] = acc1[1] + b11;
            Ms[r1 * MST + col1]     = acc1[2] + b10;
            Ms[r1 * MST + col1 + 1] = acc1[3] + b11;
        }
        __syncthreads();
        if (khalf == 1) {
            Ms[r0 * MST + col0]     += acc0[0];
            Ms[r0 * MST + col0 + 1] += acc0[1];
            Ms[r1 * MST + col0]     += acc0[2];
            Ms[r1 * MST + col0 + 1] += acc0[3];
            Ms[r0 * MST + col1]     += acc1[0];
            Ms[r0 * MST + col1 + 1] += acc1[1];
            Ms[r1 * MST + col1]     += acc1[2];
            Ms[r1 * MST + col1 + 1] += acc1[3];
        }
        __syncthreads();

        // ---- MLP + scatter: 16 warps x 4 edges ----
        #pragma unroll
        for (int q = 0; q < 4; q++) {
            int es = warp * 4 + q;
            if (es < cnt) {
                const float* mrow = &Ms[es * MST];
                float t0 = 0.f, t1 = 0.f, t2 = 0.f, t3 = 0.f;
                #pragma unroll
                for (int j = 0; j < 32; j += 4) {
                    t0 += mrow[j]     * c1r[j];
                    t1 += mrow[j + 1] * c1r[j + 1];
                    t2 += mrow[j + 2] * c1r[j + 2];
                    t3 += mrow[j + 3] * c1r[j + 3];
                }
                float t = fmaxf(cbv + ((t0 + t1) + (t2 + t3)), 0.f);
                float p = t * cwv;
                #pragma unroll
                for (int off = 16; off > 0; off >>= 1)
                    p += __shfl_xor_sync(0xffffffffu, p, off);
                float we = p + c2bv;
                int row = g_rows[begN + base + es];
                atomicAdd(&g_AGG[row * 32 + lane], mrow[lane]);
                if (lane < 3) {
                    float d = g_COORD[row * 3 + lane] - g_COORD[n * 3 + lane];
                    atomicAdd(&g_CD[row * 3 + lane], d * we);
                }
            }
        }
        n = n2; base = base2; begN = beg2; endN = end2;
        kpar ^= 1;
    }
}

__global__ void k_update() {
    int i = blockIdx.x * blockDim.x + threadIdx.x;
    if (i < NN * WD) {
        int n = i >> 5;
        float inv = 1.f / g_CNT[n];
        g_H[i] = fmaxf(g_H[i] + g_AGG[i] * inv, 0.f);
        g_AGG[i] = 0.f;
    }
    if (i < NN * 3) {
        int n = i / 3;
        g_COORD[i] += g_CD[i] / g_CNT[n];
        g_CD[i] = 0.f;
    }
}

__global__ void k_final(const float* __restrict__ f2aw, const float* __restrict__ f2ab,
                        const float* __restrict__ f2bw, const float* __restrict__ f2bb,
                        float* __restrict__ out) {
    __shared__ float wa[2048];
    __shared__ float ba[64];
    __shared__ float wb[64];
    int tid = threadIdx.x;
    for (int i = tid; i < 2048; i += 256) wa[i] = f2aw[i];
    if (tid < 64) { ba[tid] = f2ab[tid]; wb[tid] = f2bw[tid]; }
    __syncthreads();
    int n = blockIdx.x * blockDim.x + tid;
    if (n < NN) {
        float h[32];
        #pragma unroll
        for (int j = 0; j < 32; j++) h[j] = g_H[n * 32 + j];
        float o = f2bb[0];
        #pragma unroll 4
        for (int u = 0; u < 64; u++) {
            float s = ba[u];
            #pragma unroll
            for (int j = 0; j < 32; j++) s += h[j] * wa[j * 64 + u];
            o += fmaxf(s, 0.f) * wb[u];
        }
        out[n] = o;
    }
    int tot = gridDim.x * blockDim.x;
    for (int i = n; i < NN * 3; i += tot) out[NN + i] = g_COORD[i];
}

// ---------------- host ----------------
extern "C" void kernel_launch(void* const* d_in, const int* in_sizes, int n_in,
                              void* d_out, int out_size) {
    const float* x      = (const float*)d_in[0];
    const int*   ei     = (const int*)d_in[1];     // int32 (JAX x64 disabled)
    const float* ea     = (const float*)d_in[2];
    const float* coords = (const float*)d_in[3];
    const float* fc1w   = (const float*)d_in[4];
    const float* fc1b   = (const float*)d_in[5];
    const float* k1w    = (const float*)d_in[6];
    const float* k1b    = (const float*)d_in[7];
    const float* k2w    = (const float*)d_in[8];
    const float* k2b    = (const float*)d_in[9];
    const float* k3w    = (const float*)d_in[10];
    const float* k3b    = (const float*)d_in[11];
    const float* cm1w   = (const float*)d_in[12];
    const float* cm1b   = (const float*)d_in[13];
    const float* cm2w   = (const float*)d_in[14];
    const float* cm2b   = (const float*)d_in[15];
    const float* f2aw   = (const float*)d_in[16];
    const float* f2ab   = (const float*)d_in[17];
    const float* f2bw   = (const float*)d_in[18];
    const float* f2bb   = (const float*)d_in[19];

    const int smemM  = (2 * 257 * AST + 4 * 64 * KSB) * 2 + 64 * MST * 4;  // 184992 B
    const int smemG2 = (2 * 64 * RST + 2 * 128 * WST) * 2 + 256 * 4;       // 171008 B
    cudaFuncSetAttribute(k_m, cudaFuncAttributeMaxDynamicSharedMemorySize, smemM);
    cudaFuncSetAttribute(k_gemm2, cudaFuncAttributeMaxDynamicSharedMemorySize, smemG2);

    // slot 4 = k_gemmA (profiler capture target)
    k_init<<<(NN * WD + 255) / 256, 256>>>(x, coords, fc1w, fc1b);      // 1
    k_aw<<<(32 * ACOLS + 255) / 256, 256>>>(k3w, k3b);                  // 2
    k_hist<<<(EE + 255) / 256, 256>>>(ei);                              // 3
    k_gemmA<<<dim3((ACOLS + 255) / 256, (NN + 63) / 64), 256>>>();      // 4 (layer 0)
    k_scan<<<1, 1024>>>();                                              // 5
    k_scatter<<<(EE + 255) / 256, 256>>>(ei);                           // 6
    k_gemm2<<<(EE + 63) / 64, 256, smemG2>>>(ea, k1w, k1b, k2w, k2b);   // 7

    for (int d = 0; d < DEPTH; d++) {
        if (d > 0)
            k_gemmA<<<dim3((ACOLS + 255) / 256, (NN + 63) / 64), 256>>>();
        k_m<<<NBLK, 512, smemM>>>(cm1w, cm1b, cm2w, cm2b);
        k_update<<<(NN * WD + 255) / 256, 256>>>();
    }
    k_final<<<(NN + 255) / 256, 256>>>(f2aw, f2ab, f2bw, f2bb, (float*)d_out);
    k_cleanup<<<(NN + 255) / 256, 256>>>();
}

// round 15
// speedup vs baseline: 1.5945x; 1.0398x over previous
#include <cuda_runtime.h>
#include <cuda_bf16.h>
#include <cstdint>

#define NN 10000
#define EE 300000
#define WD 32
#define DEPTH 4
#define ACOLS 8224           // 8192 (A) + 32 (bias part)
#define NBLK 148             // persistent k_m blocks (1 per SM)
#define RST 136              // R1 bf16 smem row stride (ushort)
#define WST 264              // W2/AW bf16 smem row stride (ushort)
#define KSB 264              // k_m K2 smem row stride (ushort)
#define AST 40               // k_m A-slab smem row stride (ushort)
#define MST 34               // Ms row stride (float)

// ---------------- scratch (static __device__) ----------------
__device__ __align__(16) unsigned short g_K2h[(size_t)EE * 256];  // K2 split hi, PERMUTED
__device__ __align__(16) unsigned short g_K2l[(size_t)EE * 256];  // K2 split lo
__device__ __align__(16) unsigned short g_Ah[(size_t)NN * ACOLS]; // A slab split hi
__device__ __align__(16) unsigned short g_Al[(size_t)NN * ACOLS]; // A slab split lo
__device__ __align__(16) unsigned short g_AWhi[32 * ACOLS];
__device__ __align__(16) unsigned short g_AWlo[32 * ACOLS];
__device__ __align__(16) unsigned short g_W2h[128 * 256];
__device__ __align__(16) unsigned short g_W2l[128 * 256];
__device__ __align__(16) float g_H[NN * WD];
__device__ __align__(16) float g_AGG[NN * WD];
__device__ __align__(16) float g_COORD[NN * 3];
__device__ __align__(16) float g_CD[NN * 3];
__device__ float g_CNT[NN];
__device__ int   g_colcnt[NN];
__device__ int   g_rowcnt[NN];
__device__ int   g_coloff[NN + 1];
__device__ int   g_cur[NN];
__device__ int   g_pos[EE];
__device__ int   g_rows[EE];

// ---------------- helpers ----------------
__device__ __forceinline__ void cpa16(void* smem_dst, const void* gsrc) {
    unsigned s = (unsigned)__cvta_generic_to_shared(smem_dst);
    asm volatile("cp.async.cg.shared.global [%0], [%1], 16;\n" :: "r"(s), "l"(gsrc));
}
__device__ __forceinline__ void cpa_commit() { asm volatile("cp.async.commit_group;\n"); }
__device__ __forceinline__ void cpa_wait1()  { asm volatile("cp.async.wait_group 1;\n"); }
__device__ __forceinline__ void cpa_wait0()  { asm volatile("cp.async.wait_group 0;\n"); }

__device__ __forceinline__ void bfsplit(float x, unsigned short& h, unsigned short& l) {
    __nv_bfloat16 bh = __float2bfloat16(x);
    h = *reinterpret_cast<unsigned short*>(&bh);
    float r = x - __bfloat162float(bh);
    __nv_bfloat16 bl = __float2bfloat16(r);
    l = *reinterpret_cast<unsigned short*>(&bl);
}
__device__ __forceinline__ float bf2f(unsigned short u) {
    __nv_bfloat16 b = *reinterpret_cast<__nv_bfloat16*>(&u);
    return __bfloat162float(b);
}
__device__ __forceinline__ unsigned sptr(const void* p) {
    return (unsigned)__cvta_generic_to_shared(p);
}
__device__ __forceinline__ void ldsm4(unsigned* r, unsigned a) {
    asm volatile("ldmatrix.sync.aligned.m8n8.x4.shared.b16 {%0,%1,%2,%3}, [%4];"
        : "=r"(r[0]), "=r"(r[1]), "=r"(r[2]), "=r"(r[3]) : "r"(a));
}
__device__ __forceinline__ void ldsm4t(unsigned* r, unsigned a) {
    asm volatile("ldmatrix.sync.aligned.m8n8.x4.trans.shared.b16 {%0,%1,%2,%3}, [%4];"
        : "=r"(r[0]), "=r"(r[1]), "=r"(r[2]), "=r"(r[3]) : "r"(a));
}
__device__ __forceinline__ void mma_bf16(float* c, const unsigned* a, unsigned b0, unsigned b1) {
    asm volatile("mma.sync.aligned.m16n8k16.row.col.f32.bf16.bf16.f32 "
        "{%0,%1,%2,%3},{%4,%5,%6,%7},{%8,%9},{%0,%1,%2,%3};"
        : "+f"(c[0]), "+f"(c[1]), "+f"(c[2]), "+f"(c[3])
        : "r"(a[0]), "r"(a[1]), "r"(a[2]), "r"(a[3]), "r"(b0), "r"(b1));
}

// ---------------- setup ----------------
__global__ void k_init(const float* __restrict__ x, const float* __restrict__ coords,
                       const float* __restrict__ fc1w, const float* __restrict__ fc1b) {
    int i = blockIdx.x * blockDim.x + threadIdx.x;
    if (i < NN * 3) g_COORD[i] = coords[i];
    if (i < NN * WD) {
        int n = i / WD, o = i % WD;
        float a = fc1b[o];
        #pragma unroll
        for (int j = 0; j < 3; j++) a += x[n * 3 + j] * fc1w[j * WD + o];
        g_H[i] = a;
    }
}

__global__ void k_hist(const int* __restrict__ ei) {
    int e = blockIdx.x * blockDim.x + threadIdx.x;
    if (e < EE) {
        atomicAdd(&g_rowcnt[ei[e]], 1);
        atomicAdd(&g_colcnt[ei[EE + e]], 1);
    }
}

__global__ void k_scan() {
    __shared__ int sh[1024];
    __shared__ int carry;
    int t = threadIdx.x;
    if (t == 0) carry = 0;
    __syncthreads();
    for (int base = 0; base < NN; base += 1024) {
        int v = (base + t < NN) ? g_colcnt[base + t] : 0;
        sh[t] = v;
        __syncthreads();
        for (int off = 1; off < 1024; off <<= 1) {
            int y = (t >= off) ? sh[t - off] : 0;
            __syncthreads();
            sh[t] += y;
            __syncthreads();
        }
        int incl = sh[t];
        if (base + t < NN) {
            int ex = carry + incl - v;
            g_coloff[base + t] = ex;
            g_cur[base + t] = ex;
            g_CNT[base + t] = fmaxf(1.f, (float)g_rowcnt[base + t]);
        }
        int tot = sh[1023];
        __syncthreads();
        if (t == 0) carry += tot;
        __syncthreads();
    }
    if (t == 0) g_coloff[NN] = carry;
}

__global__ void k_scatter(const int* __restrict__ ei) {
    int e = blockIdx.x * blockDim.x + threadIdx.x;
    if (e < EE) {
        int r = ei[e], c = ei[EE + e];
        int p = atomicAdd(&g_cur[c], 1);
        g_pos[e] = p;
        g_rows[p] = r;
    }
}

__global__ void k_cleanup() {
    int i = blockIdx.x * blockDim.x + threadIdx.x;
    if (i < NN) { g_colcnt[i] = 0; g_rowcnt[i] = 0; }
}

// W2 split once
__global__ void k_w2(const float* __restrict__ w2) {
    int i = blockIdx.x * blockDim.x + threadIdx.x;
    if (i < 128 * 256) {
        unsigned short h, l;
        bfsplit(w2[i], h, l);
        g_W2h[i] = h;
        g_W2l[i] = l;
    }
}

// ---------------- gemm2: K2 = relu(relu(ea@W1+b1)@W2+b2), 3-term split-bf16 mma ------
__global__ void __launch_bounds__(256) k_gemm2(const float* __restrict__ ea,
                                               const float* __restrict__ w1,
                                               const float* __restrict__ b1,
                                               const float* __restrict__ b2) {
    extern __shared__ unsigned short s2u[];
    unsigned short* R1h = s2u;
    unsigned short* R1l = s2u + 64 * RST;
    unsigned short* W2h = s2u + 2 * 64 * RST;
    unsigned short* W2l = W2h + 128 * WST;
    float* b2s = (float*)(W2l + 128 * WST);
    __shared__ float eas[64 * 6];
    __shared__ float w1s[6 * 128];
    __shared__ float b1s[128];
    int tid = threadIdx.x;
    int m0 = blockIdx.x * 64;

    // async stage pre-split W2 (overlapped with R1 compute below)
    {
        const char* sh_ = (const char*)g_W2h;
        const char* sl_ = (const char*)g_W2l;
        for (int i = tid; i < 4096; i += 256) {
            int dst = (i >> 5) * (WST * 2) + (i & 31) * 16;
            cpa16((char*)W2h + dst, sh_ + i * 16);
            cpa16((char*)W2l + dst, sl_ + i * 16);
        }
        cpa_commit();
    }
    for (int i = tid; i < 64 * 6; i += 256) {
        int g = m0 * 6 + i;
        eas[i] = (g < EE * 6) ? ea[g] : 0.f;
    }
    for (int i = tid; i < 768; i += 256) w1s[i] = w1[i];
    if (tid < 128) b1s[tid] = b1[tid];
    b2s[tid] = b2[tid];
    __syncthreads();

    {
        int r = tid & 63, kg = tid >> 6;
        float ev[6];
        #pragma unroll
        for (int j = 0; j < 6; j++) ev[j] = eas[r * 6 + j];
        #pragma unroll
        for (int q = 0; q < 32; q += 2) {
            int k0 = kg * 32 + q;
            float a0 = b1s[k0], a1 = b1s[k0 + 1];
            #pragma unroll
            for (int j = 0; j < 6; j++) {
                a0 += ev[j] * w1s[j * 128 + k0];
                a1 += ev[j] * w1s[j * 128 + k0 + 1];
            }
            a0 = fmaxf(a0, 0.f); a1 = fmaxf(a1, 0.f);
            unsigned short h0, l0, h1, l1;
            bfsplit(a0, h0, l0);
            bfsplit(a1, h1, l1);
            *(unsigned*)&R1h[r * RST + k0] = ((unsigned)h1 << 16) | h0;
            *(unsigned*)&R1l[r * RST + k0] = ((unsigned)l1 << 16) | l0;
        }
    }
    cpa_wait0();
    __syncthreads();

    int lane = tid & 31, warp = tid >> 5;
    int mb = (warp >> 2) * 32, nb = (warp & 3) * 64;
    unsigned aH0 = sptr(&R1h[(mb + (lane & 15)) * RST]) + (lane >> 4) * 16;
    unsigned aH1 = aH0 + 16 * RST * 2;
    unsigned aL0 = sptr(&R1l[(mb + (lane & 15)) * RST]) + (lane >> 4) * 16;
    unsigned aL1 = aL0 + 16 * RST * 2;
    unsigned bH  = sptr(&W2h[(lane & 15) * WST + nb + (lane >> 4) * 8]);
    unsigned bL  = sptr(&W2l[(lane & 15) * WST + nb + (lane >> 4) * 8]);
    float acc[2][8][4];
    #pragma unroll
    for (int i = 0; i < 2; i++)
        #pragma unroll
        for (int j = 0; j < 8; j++)
            #pragma unroll
            for (int q = 0; q < 4; q++) acc[i][j][q] = 0.f;

    #pragma unroll
    for (int ks = 0; ks < 8; ks++) {
        unsigned ah0[4], ah1[4], al0[4], al1[4];
        ldsm4(ah0, aH0 + ks * 32);
        ldsm4(ah1, aH1 + ks * 32);
        ldsm4(al0, aL0 + ks * 32);
        ldsm4(al1, aL1 + ks * 32);
        unsigned bHA = bH + ks * 16 * WST * 2;
        unsigned bLA = bL + ks * 16 * WST * 2;
        #pragma unroll
        for (int p = 0; p < 4; p++) {
            unsigned bh[4], bl[4];
            ldsm4t(bh, bHA + p * 32);
            ldsm4t(bl, bLA + p * 32);
            mma_bf16(acc[0][2 * p],     ah0, bh[0], bh[1]);
            mma_bf16(acc[0][2 * p],     ah0, bl[0], bl[1]);
            mma_bf16(acc[0][2 * p],     al0, bh[0], bh[1]);
            mma_bf16(acc[0][2 * p + 1], ah0, bh[2], bh[3]);
            mma_bf16(acc[0][2 * p + 1], ah0, bl[2], bl[3]);
            mma_bf16(acc[0][2 * p + 1], al0, bh[2], bh[3]);
            mma_bf16(acc[1][2 * p],     ah1, bh[0], bh[1]);
            mma_bf16(acc[1][2 * p],     ah1, bl[0], bl[1]);
            mma_bf16(acc[1][2 * p],     al1, bh[0], bh[1]);
            mma_bf16(acc[1][2 * p + 1], ah1, bh[2], bh[3]);
            mma_bf16(acc[1][2 * p + 1], ah1, bl[2], bl[3]);
            mma_bf16(acc[1][2 * p + 1], al1, bh[2], bh[3]);
        }
    }

    int grp = lane >> 2, tig = lane & 3;
    #pragma unroll
    for (int mt = 0; mt < 2; mt++) {
        #pragma unroll
        for (int half = 0; half < 2; half++) {
            int e = m0 + mb + mt * 16 + grp + half * 8;
            if (e < EE) {
                size_t prow = (size_t)g_pos[e] * 256;
                #pragma unroll
                for (int n8 = 0; n8 < 8; n8++) {
                    int col = nb + n8 * 8 + tig * 2;
                    float v0 = fmaxf(acc[mt][n8][half * 2]     + b2s[col],     0.f);
                    float v1 = fmaxf(acc[mt][n8][half * 2 + 1] + b2s[col + 1], 0.f);
                    unsigned short h0, l0, h1, l1;
                    bfsplit(v0, h0, l0);
                    bfsplit(v1, h1, l1);
                    *(unsigned*)&g_K2h[prow + col] = ((unsigned)h1 << 16) | h0;
                    *(unsigned*)&g_K2l[prow + col] = ((unsigned)l1 << 16) | l0;
                }
            }
        }
    }
}

// AW split bf16
__global__ void k_aw(const float* __restrict__ w3, const float* __restrict__ b3) {
    int idx = blockIdx.x * blockDim.x + threadIdx.x;
    if (idx >= 32 * ACOLS) return;
    int j = idx / ACOLS, r = idx % ACOLS;
    float v;
    if (r < 8192) {
        int c = r >> 5, i = r & 31;
        v = w3[c * 1024 + i * 32 + j];
    } else {
        v = b3[(r - 8192) * 32 + j];
    }
    unsigned short h, l;
    bfsplit(v, h, l);
    g_AWhi[idx] = h;
    g_AWlo[idx] = l;
}

// A = H @ AW via 3-term split-bf16 mma — outputs split bf16 g_Ah/g_Al
__global__ void __launch_bounds__(256) k_gemmA() {
    __shared__ unsigned short Hh[64 * 40];
    __shared__ unsigned short Hl[64 * 40];
    __shared__ unsigned short AWh[32 * WST];
    __shared__ unsigned short AWl[32 * WST];
    int tid = threadIdx.x;
    int m0 = blockIdx.y * 64;
    int n0 = blockIdx.x * 256;

    for (int i = tid; i < 1024; i += 256) {
        int node = i >> 4, kp = i & 15;
        float2 v = make_float2(0.f, 0.f);
        if (m0 + node < NN) v = *(const float2*)&g_H[(m0 + node) * 32 + kp * 2];
        unsigned short hx, lx, hy, ly;
        bfsplit(v.x, hx, lx);
        bfsplit(v.y, hy, ly);
        *(unsigned*)&Hh[node * 40 + kp * 2] = ((unsigned)hy << 16) | hx;
        *(unsigned*)&Hl[node * 40 + kp * 2] = ((unsigned)ly << 16) | lx;
    }
    const unsigned* awh = (const unsigned*)g_AWhi;
    const unsigned* awl = (const unsigned*)g_AWlo;
    for (int i = tid; i < 4096; i += 256) {
        int j = i >> 7, n2 = i & 127;
        int col = n0 + n2 * 2;
        unsigned vh = 0u, vl = 0u;
        if (col < ACOLS) {
            vh = awh[j * (ACOLS / 2) + (col >> 1)];
            vl = awl[j * (ACOLS / 2) + (col >> 1)];
        }
        *(unsigned*)&AWh[j * WST + n2 * 2] = vh;
        *(unsigned*)&AWl[j * WST + n2 * 2] = vl;
    }
    __syncthreads();

    int lane = tid & 31, warp = tid >> 5;
    int mb = (warp >> 2) * 32, nb = (warp & 3) * 64;
    unsigned aH0 = sptr(&Hh[(mb + (lane & 15)) * 40]) + (lane >> 4) * 16;
    unsigned aH1 = aH0 + 16 * 40 * 2;
    unsigned aL0 = sptr(&Hl[(mb + (lane & 15)) * 40]) + (lane >> 4) * 16;
    unsigned aL1 = aL0 + 16 * 40 * 2;
    unsigned bH  = sptr(&AWh[(lane & 15) * WST + nb + (lane >> 4) * 8]);
    unsigned bL  = sptr(&AWl[(lane & 15) * WST + nb + (lane >> 4) * 8]);
    float acc[2][8][4];
    #pragma unroll
    for (int i = 0; i < 2; i++)
        #pragma unroll
        for (int j = 0; j < 8; j++)
            #pragma unroll
            for (int q = 0; q < 4; q++) acc[i][j][q] = 0.f;

    #pragma unroll
    for (int ks = 0; ks < 2; ks++) {
        unsigned ah0[4], ah1[4], al0[4], al1[4];
        ldsm4(ah0, aH0 + ks * 32);
        ldsm4(ah1, aH1 + ks * 32);
        ldsm4(al0, aL0 + ks * 32);
        ldsm4(al1, aL1 + ks * 32);
        unsigned bHA = bH + ks * 16 * WST * 2;
        unsigned bLA = bL + ks * 16 * WST * 2;
        #pragma unroll
        for (int p = 0; p < 4; p++) {
            unsigned bh[4], bl[4];
            ldsm4t(bh, bHA + p * 32);
            ldsm4t(bl, bLA + p * 32);
            mma_bf16(acc[0][2 * p],     ah0, bh[0], bh[1]);
            mma_bf16(acc[0][2 * p],     ah0, bl[0], bl[1]);
            mma_bf16(acc[0][2 * p],     al0, bh[0], bh[1]);
            mma_bf16(acc[0][2 * p + 1], ah0, bh[2], bh[3]);
            mma_bf16(acc[0][2 * p + 1], ah0, bl[2], bl[3]);
            mma_bf16(acc[0][2 * p + 1], al0, bh[2], bh[3]);
            mma_bf16(acc[1][2 * p],     ah1, bh[0], bh[1]);
            mma_bf16(acc[1][2 * p],     ah1, bl[0], bl[1]);
            mma_bf16(acc[1][2 * p],     al1, bh[0], bh[1]);
            mma_bf16(acc[1][2 * p + 1], ah1, bh[2], bh[3]);
            mma_bf16(acc[1][2 * p + 1], ah1, bl[2], bl[3]);
            mma_bf16(acc[1][2 * p + 1], al1, bh[2], bh[3]);
        }
    }

    int grp = lane >> 2, tig = lane & 3;
    #pragma unroll
    for (int mt = 0; mt < 2; mt++) {
        #pragma unroll
        for (int half = 0; half < 2; half++) {
            int node = m0 + mb + mt * 16 + grp + half * 8;
            if (node < NN) {
                size_t nrow = (size_t)node * ACOLS;
                #pragma unroll
                for (int n8 = 0; n8 < 8; n8++) {
                    int col = n0 + nb + n8 * 8 + tig * 2;
                    if (col < ACOLS) {
                        float v0 = acc[mt][n8][half * 2];
                        float v1 = acc[mt][n8][half * 2 + 1];
                        unsigned short h0, l0, h1, l1;
                        bfsplit(v0, h0, l0);
                        bfsplit(v1, h1, l1);
                        *(unsigned*)&g_Ah[nrow + col] = ((unsigned)h1 << 16) | h0;
                        *(unsigned*)&g_Al[nrow + col] = ((unsigned)l1 << 16) | l0;
                    }
                }
            }
        }
    }
}

// persistent fused M(tensor-core) + coord-MLP + scatter.
// 512 threads, 64-edge batches: 16 warps = 4 m-tiles x 2 n-tiles x 2 k-halves.
__global__ void __launch_bounds__(512, 1) k_m(const float* __restrict__ cm1w,
                                              const float* __restrict__ cm1b,
                                              const float* __restrict__ cm2w,
                                              const float* __restrict__ cm2b) {
    extern __shared__ unsigned short smu[];
    unsigned short* Ahs = smu;                         // 257*AST (row 256 = bias)
    unsigned short* Als = Ahs + 257 * AST;             // 257*AST
    unsigned short* K2b = Als + 257 * AST;             // 2 buffers x (h,l) x 64*KSB
    float* Ms = (float*)(K2b + 4 * 64 * KSB);          // 64*MST
    __shared__ int nsS, neS;
    int tid = threadIdx.x;
    int b = blockIdx.x;
    if (tid == 0) {
        long long t1 = (long long)b * EE;
        int lo = 0, hi = NN;
        while (lo < hi) {
            int mid = (lo + hi) >> 1;
            if ((long long)g_coloff[mid] * NBLK >= t1) hi = mid; else lo = mid + 1;
        }
        nsS = lo;
        long long t2 = (long long)(b + 1) * EE;
        hi = NN;
        while (lo < hi) {
            int mid = (lo + hi) >> 1;
            if ((long long)g_coloff[mid] * NBLK >= t2) hi = mid; else lo = mid + 1;
        }
        neS = lo;
    }
    __syncthreads();
    int ns = nsS, ne = neS;

    int n = ns;
    int begN = (n < ne) ? g_coloff[n] : 0, endN = begN;
    while (n < ne) {
        endN = g_coloff[n + 1];
        if (endN > begN) break;
        n++; begN = endN;
    }
    if (n >= ne) return;

    int lane = tid & 31, warp = tid >> 5;
    int mtile = warp & 3, ntile = (warp >> 2) & 1, khalf = warp >> 3;
    float c1r[32];
    #pragma unroll
    for (int j = 0; j < 32; j++) c1r[j] = cm1w[j * 32 + lane];
    float cbv = cm1b[lane], cwv = cm2w[lane], c2bv = cm2b[0];

    // prologue: A(n) slab + first K batch
    {
        const char* sH = (const char*)(g_Ah + (size_t)n * ACOLS);
        const char* sL = (const char*)(g_Al + (size_t)n * ACOLS);
        for (int i = tid; i < 1028; i += 512) {
            int srcoff, dstoff;
            if (i < 1024) { srcoff = i * 16; dstoff = (i >> 2) * 80 + (i & 3) * 16; }
            else { int q = i - 1024; srcoff = 16384 + q * 16; dstoff = 256 * 80 + q * 16; }
            cpa16((char*)Ahs + dstoff, sH + srcoff);
            cpa16((char*)Als + dstoff, sL + srcoff);
        }
        cpa_commit();
        int cnt0 = min(64, endN - begN);
        const char* kh = (const char*)(g_K2h + (size_t)begN * 256);
        const char* kl = (const char*)(g_K2l + (size_t)begN * 256);
        unsigned short* Kh = K2b;
        unsigned short* Kl = K2b + 64 * KSB;
        for (int i = tid; i < cnt0 * 32; i += 512) {
            int dstoff = (i >> 5) * KSB * 2 + (i & 31) * 16;
            cpa16((char*)Kh + dstoff, kh + i * 16);
            cpa16((char*)Kl + dstoff, kl + i * 16);
        }
        cpa_commit();
    }

    int base = 0, kpar = 0, prevn = n;
    while (n < ne) {
        int nE = endN - begN;
        int cnt = min(64, nE - base);
        if (n != prevn) {
            const char* sH = (const char*)(g_Ah + (size_t)n * ACOLS);
            const char* sL = (const char*)(g_Al + (size_t)n * ACOLS);
            for (int i = tid; i < 1028; i += 512) {
                int srcoff, dstoff;
                if (i < 1024) { srcoff = i * 16; dstoff = (i >> 2) * 80 + (i & 3) * 16; }
                else { int q = i - 1024; srcoff = 16384 + q * 16; dstoff = 256 * 80 + q * 16; }
                cpa16((char*)Ahs + dstoff, sH + srcoff);
                cpa16((char*)Als + dstoff, sL + srcoff);
            }
            cpa_commit();
            prevn = n;
        }
        int n2 = n, base2 = base + 64, beg2 = begN, end2 = endN;
        if (base2 >= nE) {
            base2 = 0; n2 = n + 1; beg2 = endN;
            while (n2 < ne) {
                end2 = g_coloff[n2 + 1];
                if (end2 > beg2) break;
                n2++; beg2 = end2;
            }
        }
        if (n2 < ne) {
            int cnt2 = min(64, end2 - beg2 - base2);
            const char* kh = (const char*)(g_K2h + (size_t)(beg2 + base2) * 256);
            const char* kl = (const char*)(g_K2l + (size_t)(beg2 + base2) * 256);
            unsigned short* Kh = K2b + (kpar ^ 1) * 2 * 64 * KSB;
            unsigned short* Kl = Kh + 64 * KSB;
            for (int i = tid; i < cnt2 * 32; i += 512) {
                int dstoff = (i >> 5) * KSB * 2 + (i & 31) * 16;
                cpa16((char*)Kh + dstoff, kh + i * 16);
                cpa16((char*)Kl + dstoff, kl + i * 16);
            }
        }
        cpa_commit();
        cpa_wait1();
        __syncthreads();

        // ---- tensor-core GEMM: M[64x32] = K2[64x256] @ A[256x32] (3-term split) ----
        unsigned short* Kh = K2b + kpar * 2 * 64 * KSB;
        unsigned short* Kl = Kh + 64 * KSB;
        unsigned aH = sptr(Kh + (mtile * 16 + (lane & 15)) * KSB) + (lane >> 4) * 16 + khalf * 256;
        unsigned aL = sptr(Kl + (mtile * 16 + (lane & 15)) * KSB) + (lane >> 4) * 16 + khalf * 256;
        unsigned bHa = sptr(Ahs + (khalf * 128 + (lane & 15)) * AST + ntile * 16 + (lane >> 4) * 8);
        unsigned bLa = sptr(Als + (khalf * 128 + (lane & 15)) * AST + ntile * 16 + (lane >> 4) * 8);
        float acc0[4] = {0.f, 0.f, 0.f, 0.f};
        float acc1[4] = {0.f, 0.f, 0.f, 0.f};
        #pragma unroll
        for (int ks = 0; ks < 8; ks++) {
            unsigned ah[4], al[4], bh[4], bl[4];
            ldsm4(ah, aH + ks * 32);
            ldsm4(al, aL + ks * 32);
            ldsm4t(bh, bHa + ks * 1280);
            ldsm4t(bl, bLa + ks * 1280);
            mma_bf16(acc0, ah, bh[0], bh[1]);
            mma_bf16(acc0, ah, bl[0], bl[1]);
            mma_bf16(acc0, al, bh[0], bh[1]);
            mma_bf16(acc1, ah, bh[2], bh[3]);
            mma_bf16(acc1, ah, bl[2], bl[3]);
            mma_bf16(acc1, al, bh[2], bh[3]);
        }
        int grp = lane >> 2, tig = lane & 3;
        int r0 = mtile * 16 + grp, r1 = r0 + 8;
        int col0 = ntile * 16 + tig * 2, col1 = col0 + 8;
        if (khalf == 0) {
            float b00 = bf2f(Ahs[256 * AST + col0]) + bf2f(Als[256 * AST + col0]);
            float b01 = bf2f(Ahs[256 * AST + col0 + 1]) + bf2f(Als[256 * AST + col0 + 1]);
            float b10 = bf2f(Ahs[256 * AST + col1]) + bf2f(Als[256 * AST + col1]);
            float b11 = bf2f(Ahs[256 * AST + col1 + 1]) + bf2f(Als[256 * AST + col1 + 1]);
            Ms[r0 * MST + col0]     = acc0[0] + b00;
            Ms[r0 * MST + col0 + 1] = acc0[1] + b01;
            Ms[r1 * MST + col0]     = acc0[2] + b00;
            Ms[r1 * MST + col0 + 1] = acc0[3] + b01;
            Ms[r0 * MST + col1]     = acc1[0] + b10;
            Ms[r0 * MST + col1 + 1] = acc1[1] + b11;
            Ms[r1 * MST + col1]     = acc1[2] + b10;
            Ms[r1 * MST + col1 + 1] = acc1[3] + b11;
        }
        __syncthreads();
        if (khalf == 1) {
            Ms[r0 * MST + col0]     += acc0[0];
            Ms[r0 * MST + col0 + 1] += acc0[1];
            Ms[r1 * MST + col0]     += acc0[2];
            Ms[r1 * MST + col0 + 1] += acc0[3];
            Ms[r0 * MST + col1]     += acc1[0];
            Ms[r0 * MST + col1 + 1] += acc1[1];
            Ms[r1 * MST + col1]     += acc1[2];
            Ms[r1 * MST + col1 + 1] += acc1[3];
        }
        __syncthreads();

        // ---- MLP + scatter: 16 warps x 4 edges ----
        #pragma unroll
        for (int q = 0; q < 4; q++) {
            int es = warp * 4 + q;
            if (es < cnt) {
                const float* mrow = &Ms[es * MST];
                float t0 = 0.f, t1 = 0.f, t2 = 0.f, t3 = 0.f;
                #pragma unroll
                for (int j = 0; j < 32; j += 4) {
                    t0 += mrow[j]     * c1r[j];
                    t1 += mrow[j + 1] * c1r[j + 1];
                    t2 += mrow[j + 2] * c1r[j + 2];
                    t3 += mrow[j + 3] * c1r[j + 3];
                }
                float t = fmaxf(cbv + ((t0 + t1) + (t2 + t3)), 0.f);
                float p = t * cwv;
                #pragma unroll
                for (int off = 16; off > 0; off >>= 1)
                    p += __shfl_xor_sync(0xffffffffu, p, off);
                float we = p + c2bv;
                int row = g_rows[begN + base + es];
                atomicAdd(&g_AGG[row * 32 + lane], mrow[lane]);
                if (lane < 3) {
                    float d = g_COORD[row * 3 + lane] - g_COORD[n * 3 + lane];
                    atomicAdd(&g_CD[row * 3 + lane], d * we);
                }
            }
        }
        n = n2; base = base2; begN = beg2; endN = end2;
        kpar ^= 1;
    }
}

__global__ void k_update() {
    int i = blockIdx.x * blockDim.x + threadIdx.x;
    if (i < NN * WD) {
        int n = i >> 5;
        float inv = 1.f / g_CNT[n];
        g_H[i] = fmaxf(g_H[i] + g_AGG[i] * inv, 0.f);
        g_AGG[i] = 0.f;
    }
    if (i < NN * 3) {
        int n = i / 3;
        g_COORD[i] += g_CD[i] / g_CNT[n];
        g_CD[i] = 0.f;
    }
}

__global__ void k_final(const float* __restrict__ f2aw, const float* __restrict__ f2ab,
                        const float* __restrict__ f2bw, const float* __restrict__ f2bb,
                        float* __restrict__ out) {
    __shared__ float wa[2048];
    __shared__ float ba[64];
    __shared__ float wb[64];
    int tid = threadIdx.x;
    for (int i = tid; i < 2048; i += 256) wa[i] = f2aw[i];
    if (tid < 64) { ba[tid] = f2ab[tid]; wb[tid] = f2bw[tid]; }
    __syncthreads();
    int n = blockIdx.x * blockDim.x + tid;
    if (n < NN) {
        float h[32];
        #pragma unroll
        for (int j = 0; j < 32; j++) h[j] = g_H[n * 32 + j];
        float o = f2bb[0];
        #pragma unroll 4
        for (int u = 0; u < 64; u++) {
            float s = ba[u];
            #pragma unroll
            for (int j = 0; j < 32; j++) s += h[j] * wa[j * 64 + u];
            o += fmaxf(s, 0.f) * wb[u];
        }
        out[n] = o;
    }
    int tot = gridDim.x * blockDim.x;
    for (int i = n; i < NN * 3; i += tot) out[NN + i] = g_COORD[i];
}

// ---------------- host ----------------
extern "C" void kernel_launch(void* const* d_in, const int* in_sizes, int n_in,
                              void* d_out, int out_size) {
    const float* x      = (const float*)d_in[0];
    const int*   ei     = (const int*)d_in[1];     // int32 (JAX x64 disabled)
    const float* ea     = (const float*)d_in[2];
    const float* coords = (const float*)d_in[3];
    const float* fc1w   = (const float*)d_in[4];
    const float* fc1b   = (const float*)d_in[5];
    const float* k1w    = (const float*)d_in[6];
    const float* k1b    = (const float*)d_in[7];
    const float* k2w    = (const float*)d_in[8];
    const float* k2b    = (const float*)d_in[9];
    const float* k3w    = (const float*)d_in[10];
    const float* k3b    = (const float*)d_in[11];
    const float* cm1w   = (const float*)d_in[12];
    const float* cm1b   = (const float*)d_in[13];
    const float* cm2w   = (const float*)d_in[14];
    const float* cm2b   = (const float*)d_in[15];
    const float* f2aw   = (const float*)d_in[16];
    const float* f2ab   = (const float*)d_in[17];
    const float* f2bw   = (const float*)d_in[18];
    const float* f2bb   = (const float*)d_in[19];

    const int smemM  = (2 * 257 * AST + 4 * 64 * KSB) * 2 + 64 * MST * 4;  // 184992 B
    const int smemG2 = (2 * 64 * RST + 2 * 128 * WST) * 2 + 256 * 4;       // 171008 B
    cudaFuncSetAttribute(k_m, cudaFuncAttributeMaxDynamicSharedMemorySize, smemM);
    cudaFuncSetAttribute(k_gemm2, cudaFuncAttributeMaxDynamicSharedMemorySize, smemG2);

    // slot 4 = k_gemmA (profiler capture target)
    k_init<<<(NN * WD + 255) / 256, 256>>>(x, coords, fc1w, fc1b);      // 1
    k_aw<<<(32 * ACOLS + 255) / 256, 256>>>(k3w, k3b);                  // 2
    k_hist<<<(EE + 255) / 256, 256>>>(ei);                              // 3
    k_gemmA<<<dim3((ACOLS + 255) / 256, (NN + 63) / 64), 256>>>();      // 4 (layer 0)
    k_scan<<<1, 1024>>>();                                              // 5
    k_w2<<<(128 * 256 + 255) / 256, 256>>>(k2w);                        // 6
    k_scatter<<<(EE + 255) / 256, 256>>>(ei);                           // 7
    k_gemm2<<<(EE + 63) / 64, 256, smemG2>>>(ea, k1w, k1b, k2b);        // 8

    for (int d = 0; d < DEPTH; d++) {
        if (d > 0)
            k_gemmA<<<dim3((ACOLS + 255) / 256, (NN + 63) / 64), 256>>>();
        k_m<<<NBLK, 512, smemM>>>(cm1w, cm1b, cm2w, cm2b);
        k_update<<<(NN * WD + 255) / 256, 256>>>();
    }
    k_final<<<(NN + 255) / 256, 256>>>(f2aw, f2ab, f2bw, f2bb, (float*)d_out);
    k_cleanup<<<(NN + 255) / 256, 256>>>();
}

// round 16
// speedup vs baseline: 2.1166x; 1.3274x over previous
#include <cuda_runtime.h>
#include <cuda_bf16.h>
#include <cuda_fp16.h>
#include <cstdint>

#define NN 10000
#define EE 300000
#define WD 32
#define DEPTH 4
#define ACOLS 8224           // 8192 (A) + 32 (bias part)
#define NBLK 296             // persistent k_m blocks (2 per SM)
#define RST 136              // R1 bf16 smem row stride (ushort)
#define WST 264              // W2/AW bf16 smem row stride (ushort)
#define KSB 264              // k_m K2 smem row stride (ushort)
#define AST 40               // k_m A-slab smem row stride (ushort)
#define MST 34               // Ms row stride (float)

// ---------------- scratch (static __device__) ----------------
__device__ __align__(16) unsigned short g_K2[(size_t)EE * 256];   // K2 fp16, PERMUTED
__device__ __align__(16) unsigned short g_A16[(size_t)NN * ACOLS]; // A slab fp16
__device__ __align__(16) unsigned short g_AWhi[32 * ACOLS];
__device__ __align__(16) unsigned short g_AWlo[32 * ACOLS];
__device__ __align__(16) unsigned short g_W2h[128 * 256];
__device__ __align__(16) unsigned short g_W2l[128 * 256];
__device__ __align__(16) float g_H[NN * WD];
__device__ __align__(16) float g_AGG[NN * WD];
__device__ __align__(16) float g_COORD[NN * 3];
__device__ __align__(16) float g_CD[NN * 3];
__device__ float g_CNT[NN];
__device__ int   g_colcnt[NN];
__device__ int   g_rowcnt[NN];
__device__ int   g_coloff[NN + 1];
__device__ int   g_cur[NN];
__device__ int   g_pos[EE];
__device__ int   g_rows[EE];

// ---------------- helpers ----------------
__device__ __forceinline__ void cpa16(void* smem_dst, const void* gsrc) {
    unsigned s = (unsigned)__cvta_generic_to_shared(smem_dst);
    asm volatile("cp.async.cg.shared.global [%0], [%1], 16;\n" :: "r"(s), "l"(gsrc));
}
__device__ __forceinline__ void cpa_commit() { asm volatile("cp.async.commit_group;\n"); }
__device__ __forceinline__ void cpa_wait1()  { asm volatile("cp.async.wait_group 1;\n"); }
__device__ __forceinline__ void cpa_wait0()  { asm volatile("cp.async.wait_group 0;\n"); }

__device__ __forceinline__ void bfsplit(float x, unsigned short& h, unsigned short& l) {
    __nv_bfloat16 bh = __float2bfloat16(x);
    h = *reinterpret_cast<unsigned short*>(&bh);
    float r = x - __bfloat162float(bh);
    __nv_bfloat16 bl = __float2bfloat16(r);
    l = *reinterpret_cast<unsigned short*>(&bl);
}
__device__ __forceinline__ unsigned short f2h(float x) {
    __half h = __float2half(x);
    return *reinterpret_cast<unsigned short*>(&h);
}
__device__ __forceinline__ float h2f(unsigned short u) {
    __half h = *reinterpret_cast<__half*>(&u);
    return __half2float(h);
}
__device__ __forceinline__ unsigned sptr(const void* p) {
    return (unsigned)__cvta_generic_to_shared(p);
}
__device__ __forceinline__ void ldsm4(unsigned* r, unsigned a) {
    asm volatile("ldmatrix.sync.aligned.m8n8.x4.shared.b16 {%0,%1,%2,%3}, [%4];"
        : "=r"(r[0]), "=r"(r[1]), "=r"(r[2]), "=r"(r[3]) : "r"(a));
}
__device__ __forceinline__ void ldsm4t(unsigned* r, unsigned a) {
    asm volatile("ldmatrix.sync.aligned.m8n8.x4.trans.shared.b16 {%0,%1,%2,%3}, [%4];"
        : "=r"(r[0]), "=r"(r[1]), "=r"(r[2]), "=r"(r[3]) : "r"(a));
}
__device__ __forceinline__ void mma_bf16(float* c, const unsigned* a, unsigned b0, unsigned b1) {
    asm volatile("mma.sync.aligned.m16n8k16.row.col.f32.bf16.bf16.f32 "
        "{%0,%1,%2,%3},{%4,%5,%6,%7},{%8,%9},{%0,%1,%2,%3};"
        : "+f"(c[0]), "+f"(c[1]), "+f"(c[2]), "+f"(c[3])
        : "r"(a[0]), "r"(a[1]), "r"(a[2]), "r"(a[3]), "r"(b0), "r"(b1));
}
__device__ __forceinline__ void mma_f16(float* c, const unsigned* a, unsigned b0, unsigned b1) {
    asm volatile("mma.sync.aligned.m16n8k16.row.col.f32.f16.f16.f32 "
        "{%0,%1,%2,%3},{%4,%5,%6,%7},{%8,%9},{%0,%1,%2,%3};"
        : "+f"(c[0]), "+f"(c[1]), "+f"(c[2]), "+f"(c[3])
        : "r"(a[0]), "r"(a[1]), "r"(a[2]), "r"(a[3]), "r"(b0), "r"(b1));
}

// ---------------- setup ----------------
__global__ void k_init(const float* __restrict__ x, const float* __restrict__ coords,
                       const float* __restrict__ fc1w, const float* __restrict__ fc1b) {
    int i = blockIdx.x * blockDim.x + threadIdx.x;
    if (i < NN * 3) g_COORD[i] = coords[i];
    if (i < NN * WD) {
        int n = i / WD, o = i % WD;
        float a = fc1b[o];
        #pragma unroll
        for (int j = 0; j < 3; j++) a += x[n * 3 + j] * fc1w[j * WD + o];
        g_H[i] = a;
    }
}

__global__ void k_hist(const int* __restrict__ ei) {
    int e = blockIdx.x * blockDim.x + threadIdx.x;
    if (e < EE) {
        atomicAdd(&g_rowcnt[ei[e]], 1);
        atomicAdd(&g_colcnt[ei[EE + e]], 1);
    }
}

__global__ void k_scan() {
    __shared__ int sh[1024];
    __shared__ int carry;
    int t = threadIdx.x;
    if (t == 0) carry = 0;
    __syncthreads();
    for (int base = 0; base < NN; base += 1024) {
        int v = (base + t < NN) ? g_colcnt[base + t] : 0;
        sh[t] = v;
        __syncthreads();
        for (int off = 1; off < 1024; off <<= 1) {
            int y = (t >= off) ? sh[t - off] : 0;
            __syncthreads();
            sh[t] += y;
            __syncthreads();
        }
        int incl = sh[t];
        if (base + t < NN) {
            int ex = carry + incl - v;
            g_coloff[base + t] = ex;
            g_cur[base + t] = ex;
            g_CNT[base + t] = fmaxf(1.f, (float)g_rowcnt[base + t]);
        }
        int tot = sh[1023];
        __syncthreads();
        if (t == 0) carry += tot;
        __syncthreads();
    }
    if (t == 0) g_coloff[NN] = carry;
}

__global__ void k_scatter(const int* __restrict__ ei) {
    int e = blockIdx.x * blockDim.x + threadIdx.x;
    if (e < EE) {
        int r = ei[e], c = ei[EE + e];
        int p = atomicAdd(&g_cur[c], 1);
        g_pos[e] = p;
        g_rows[p] = r;
    }
}

__global__ void k_cleanup() {
    int i = blockIdx.x * blockDim.x + threadIdx.x;
    if (i < NN) { g_colcnt[i] = 0; g_rowcnt[i] = 0; }
}

// W2 split once
__global__ void k_w2(const float* __restrict__ w2) {
    int i = blockIdx.x * blockDim.x + threadIdx.x;
    if (i < 128 * 256) {
        unsigned short h, l;
        bfsplit(w2[i], h, l);
        g_W2h[i] = h;
        g_W2l[i] = l;
    }
}

// ---------------- gemm2: K2 = relu(relu(ea@W1+b1)@W2+b2), 3-term split-bf16 mma ------
__global__ void __launch_bounds__(256) k_gemm2(const float* __restrict__ ea,
                                               const float* __restrict__ w1,
                                               const float* __restrict__ b1,
                                               const float* __restrict__ b2) {
    extern __shared__ unsigned short s2u[];
    unsigned short* R1h = s2u;
    unsigned short* R1l = s2u + 64 * RST;
    unsigned short* W2h = s2u + 2 * 64 * RST;
    unsigned short* W2l = W2h + 128 * WST;
    float* b2s = (float*)(W2l + 128 * WST);
    __shared__ float eas[64 * 6];
    __shared__ float w1s[6 * 128];
    __shared__ float b1s[128];
    int tid = threadIdx.x;
    int m0 = blockIdx.x * 64;

    // async stage pre-split W2 (overlapped with R1 compute below)
    {
        const char* sh_ = (const char*)g_W2h;
        const char* sl_ = (const char*)g_W2l;
        for (int i = tid; i < 4096; i += 256) {
            int dst = (i >> 5) * (WST * 2) + (i & 31) * 16;
            cpa16((char*)W2h + dst, sh_ + i * 16);
            cpa16((char*)W2l + dst, sl_ + i * 16);
        }
        cpa_commit();
    }
    for (int i = tid; i < 64 * 6; i += 256) {
        int g = m0 * 6 + i;
        eas[i] = (g < EE * 6) ? ea[g] : 0.f;
    }
    for (int i = tid; i < 768; i += 256) w1s[i] = w1[i];
    if (tid < 128) b1s[tid] = b1[tid];
    b2s[tid] = b2[tid];
    __syncthreads();

    {
        int r = tid & 63, kg = tid >> 6;
        float ev[6];
        #pragma unroll
        for (int j = 0; j < 6; j++) ev[j] = eas[r * 6 + j];
        #pragma unroll
        for (int q = 0; q < 32; q += 2) {
            int k0 = kg * 32 + q;
            float a0 = b1s[k0], a1 = b1s[k0 + 1];
            #pragma unroll
            for (int j = 0; j < 6; j++) {
                a0 += ev[j] * w1s[j * 128 + k0];
                a1 += ev[j] * w1s[j * 128 + k0 + 1];
            }
            a0 = fmaxf(a0, 0.f); a1 = fmaxf(a1, 0.f);
            unsigned short h0, l0, h1, l1;
            bfsplit(a0, h0, l0);
            bfsplit(a1, h1, l1);
            *(unsigned*)&R1h[r * RST + k0] = ((unsigned)h1 << 16) | h0;
            *(unsigned*)&R1l[r * RST + k0] = ((unsigned)l1 << 16) | l0;
        }
    }
    cpa_wait0();
    __syncthreads();

    int lane = tid & 31, warp = tid >> 5;
    int mb = (warp >> 2) * 32, nb = (warp & 3) * 64;
    unsigned aH0 = sptr(&R1h[(mb + (lane & 15)) * RST]) + (lane >> 4) * 16;
    unsigned aH1 = aH0 + 16 * RST * 2;
    unsigned aL0 = sptr(&R1l[(mb + (lane & 15)) * RST]) + (lane >> 4) * 16;
    unsigned aL1 = aL0 + 16 * RST * 2;
    unsigned bH  = sptr(&W2h[(lane & 15) * WST + nb + (lane >> 4) * 8]);
    unsigned bL  = sptr(&W2l[(lane & 15) * WST + nb + (lane >> 4) * 8]);
    float acc[2][8][4];
    #pragma unroll
    for (int i = 0; i < 2; i++)
        #pragma unroll
        for (int j = 0; j < 8; j++)
            #pragma unroll
            for (int q = 0; q < 4; q++) acc[i][j][q] = 0.f;

    #pragma unroll
    for (int ks = 0; ks < 8; ks++) {
        unsigned ah0[4], ah1[4], al0[4], al1[4];
        ldsm4(ah0, aH0 + ks * 32);
        ldsm4(ah1, aH1 + ks * 32);
        ldsm4(al0, aL0 + ks * 32);
        ldsm4(al1, aL1 + ks * 32);
        unsigned bHA = bH + ks * 16 * WST * 2;
        unsigned bLA = bL + ks * 16 * WST * 2;
        #pragma unroll
        for (int p = 0; p < 4; p++) {
            unsigned bh[4], bl[4];
            ldsm4t(bh, bHA + p * 32);
            ldsm4t(bl, bLA + p * 32);
            mma_bf16(acc[0][2 * p],     ah0, bh[0], bh[1]);
            mma_bf16(acc[0][2 * p],     ah0, bl[0], bl[1]);
            mma_bf16(acc[0][2 * p],     al0, bh[0], bh[1]);
            mma_bf16(acc[0][2 * p + 1], ah0, bh[2], bh[3]);
            mma_bf16(acc[0][2 * p + 1], ah0, bl[2], bl[3]);
            mma_bf16(acc[0][2 * p + 1], al0, bh[2], bh[3]);
            mma_bf16(acc[1][2 * p],     ah1, bh[0], bh[1]);
            mma_bf16(acc[1][2 * p],     ah1, bl[0], bl[1]);
            mma_bf16(acc[1][2 * p],     al1, bh[0], bh[1]);
            mma_bf16(acc[1][2 * p + 1], ah1, bh[2], bh[3]);
            mma_bf16(acc[1][2 * p + 1], ah1, bl[2], bl[3]);
            mma_bf16(acc[1][2 * p + 1], al1, bh[2], bh[3]);
        }
    }

    int grp = lane >> 2, tig = lane & 3;
    #pragma unroll
    for (int mt = 0; mt < 2; mt++) {
        #pragma unroll
        for (int half = 0; half < 2; half++) {
            int e = m0 + mb + mt * 16 + grp + half * 8;
            if (e < EE) {
                size_t prow = (size_t)g_pos[e] * 256;
                #pragma unroll
                for (int n8 = 0; n8 < 8; n8++) {
                    int col = nb + n8 * 8 + tig * 2;
                    float v0 = fmaxf(acc[mt][n8][half * 2]     + b2s[col],     0.f);
                    float v1 = fmaxf(acc[mt][n8][half * 2 + 1] + b2s[col + 1], 0.f);
                    unsigned short h0 = f2h(v0), h1 = f2h(v1);
                    *(unsigned*)&g_K2[prow + col] = ((unsigned)h1 << 16) | h0;
                }
            }
        }
    }
}

// AW split bf16
__global__ void k_aw(const float* __restrict__ w3, const float* __restrict__ b3) {
    int idx = blockIdx.x * blockDim.x + threadIdx.x;
    if (idx >= 32 * ACOLS) return;
    int j = idx / ACOLS, r = idx % ACOLS;
    float v;
    if (r < 8192) {
        int c = r >> 5, i = r & 31;
        v = w3[c * 1024 + i * 32 + j];
    } else {
        v = b3[(r - 8192) * 32 + j];
    }
    unsigned short h, l;
    bfsplit(v, h, l);
    g_AWhi[idx] = h;
    g_AWlo[idx] = l;
}

// A = H @ AW via 3-term split-bf16 mma — outputs fp16 g_A16
__global__ void __launch_bounds__(256) k_gemmA() {
    __shared__ unsigned short Hh[64 * 40];
    __shared__ unsigned short Hl[64 * 40];
    __shared__ unsigned short AWh[32 * WST];
    __shared__ unsigned short AWl[32 * WST];
    int tid = threadIdx.x;
    int m0 = blockIdx.y * 64;
    int n0 = blockIdx.x * 256;

    for (int i = tid; i < 1024; i += 256) {
        int node = i >> 4, kp = i & 15;
        float2 v = make_float2(0.f, 0.f);
        if (m0 + node < NN) v = *(const float2*)&g_H[(m0 + node) * 32 + kp * 2];
        unsigned short hx, lx, hy, ly;
        bfsplit(v.x, hx, lx);
        bfsplit(v.y, hy, ly);
        *(unsigned*)&Hh[node * 40 + kp * 2] = ((unsigned)hy << 16) | hx;
        *(unsigned*)&Hl[node * 40 + kp * 2] = ((unsigned)ly << 16) | lx;
    }
    const unsigned* awh = (const unsigned*)g_AWhi;
    const unsigned* awl = (const unsigned*)g_AWlo;
    for (int i = tid; i < 4096; i += 256) {
        int j = i >> 7, n2 = i & 127;
        int col = n0 + n2 * 2;
        unsigned vh = 0u, vl = 0u;
        if (col < ACOLS) {
            vh = awh[j * (ACOLS / 2) + (col >> 1)];
            vl = awl[j * (ACOLS / 2) + (col >> 1)];
        }
        *(unsigned*)&AWh[j * WST + n2 * 2] = vh;
        *(unsigned*)&AWl[j * WST + n2 * 2] = vl;
    }
    __syncthreads();

    int lane = tid & 31, warp = tid >> 5;
    int mb = (warp >> 2) * 32, nb = (warp & 3) * 64;
    unsigned aH0 = sptr(&Hh[(mb + (lane & 15)) * 40]) + (lane >> 4) * 16;
    unsigned aH1 = aH0 + 16 * 40 * 2;
    unsigned aL0 = sptr(&Hl[(mb + (lane & 15)) * 40]) + (lane >> 4) * 16;
    unsigned aL1 = aL0 + 16 * 40 * 2;
    unsigned bH  = sptr(&AWh[(lane & 15) * WST + nb + (lane >> 4) * 8]);
    unsigned bL  = sptr(&AWl[(lane & 15) * WST + nb + (lane >> 4) * 8]);
    float acc[2][8][4];
    #pragma unroll
    for (int i = 0; i < 2; i++)
        #pragma unroll
        for (int j = 0; j < 8; j++)
            #pragma unroll
            for (int q = 0; q < 4; q++) acc[i][j][q] = 0.f;

    #pragma unroll
    for (int ks = 0; ks < 2; ks++) {
        unsigned ah0[4], ah1[4], al0[4], al1[4];
        ldsm4(ah0, aH0 + ks * 32);
        ldsm4(ah1, aH1 + ks * 32);
        ldsm4(al0, aL0 + ks * 32);
        ldsm4(al1, aL1 + ks * 32);
        unsigned bHA = bH + ks * 16 * WST * 2;
        unsigned bLA = bL + ks * 16 * WST * 2;
        #pragma unroll
        for (int p = 0; p < 4; p++) {
            unsigned bh[4], bl[4];
            ldsm4t(bh, bHA + p * 32);
            ldsm4t(bl, bLA + p * 32);
            mma_bf16(acc[0][2 * p],     ah0, bh[0], bh[1]);
            mma_bf16(acc[0][2 * p],     ah0, bl[0], bl[1]);
            mma_bf16(acc[0][2 * p],     al0, bh[0], bh[1]);
            mma_bf16(acc[0][2 * p + 1], ah0, bh[2], bh[3]);
            mma_bf16(acc[0][2 * p + 1], ah0, bl[2], bl[3]);
            mma_bf16(acc[0][2 * p + 1], al0, bh[2], bh[3]);
            mma_bf16(acc[1][2 * p],     ah1, bh[0], bh[1]);
            mma_bf16(acc[1][2 * p],     ah1, bl[0], bl[1]);
            mma_bf16(acc[1][2 * p],     al1, bh[0], bh[1]);
            mma_bf16(acc[1][2 * p + 1], ah1, bh[2], bh[3]);
            mma_bf16(acc[1][2 * p + 1], ah1, bl[2], bl[3]);
            mma_bf16(acc[1][2 * p + 1], al1, bh[2], bh[3]);
        }
    }

    int grp = lane >> 2, tig = lane & 3;
    #pragma unroll
    for (int mt = 0; mt < 2; mt++) {
        #pragma unroll
        for (int half = 0; half < 2; half++) {
            int node = m0 + mb + mt * 16 + grp + half * 8;
            if (node < NN) {
                size_t nrow = (size_t)node * ACOLS;
                #pragma unroll
                for (int n8 = 0; n8 < 8; n8++) {
                    int col = n0 + nb + n8 * 8 + tig * 2;
                    if (col < ACOLS) {
                        unsigned short h0 = f2h(acc[mt][n8][half * 2]);
                        unsigned short h1 = f2h(acc[mt][n8][half * 2 + 1]);
                        *(unsigned*)&g_A16[nrow + col] = ((unsigned)h1 << 16) | h0;
                    }
                }
            }
        }
    }
}

// persistent fused M(fp16 tensor-core) + coord-MLP + scatter.
// 256 threads, 2 CTAs/SM, 64-edge batches: 8 warps = 4 m-tiles x 2 n-tiles, full K.
__global__ void __launch_bounds__(256, 2) k_m(const float* __restrict__ cm1w,
                                              const float* __restrict__ cm1b,
                                              const float* __restrict__ cm2w,
                                              const float* __restrict__ cm2b) {
    extern __shared__ unsigned short smu[];
    unsigned short* Ahs = smu;                         // 257*AST (row 256 = bias)
    unsigned short* K2b = Ahs + 257 * AST;             // 2 buffers x 64*KSB
    float* Ms = (float*)(K2b + 2 * 64 * KSB);          // 64*MST
    __shared__ float c1s[1024];
    __shared__ float c1bs[32], c2s[32];
    __shared__ float cm2bv;
    __shared__ int nsS, neS;
    int tid = threadIdx.x;
    int b = blockIdx.x;
    if (tid == 0) {
        long long t1 = (long long)b * EE;
        int lo = 0, hi = NN;
        while (lo < hi) {
            int mid = (lo + hi) >> 1;
            if ((long long)g_coloff[mid] * NBLK >= t1) hi = mid; else lo = mid + 1;
        }
        nsS = lo;
        long long t2 = (long long)(b + 1) * EE;
        hi = NN;
        while (lo < hi) {
            int mid = (lo + hi) >> 1;
            if ((long long)g_coloff[mid] * NBLK >= t2) hi = mid; else lo = mid + 1;
        }
        neS = lo;
        cm2bv = cm2b[0];
    }
    for (int i = tid; i < 1024; i += 256) c1s[i] = cm1w[i];
    if (tid < 32) { c1bs[tid] = cm1b[tid]; c2s[tid] = cm2w[tid]; }
    __syncthreads();
    int ns = nsS, ne = neS;

    int n = ns;
    int begN = (n < ne) ? g_coloff[n] : 0, endN = begN;
    while (n < ne) {
        endN = g_coloff[n + 1];
        if (endN > begN) break;
        n++; begN = endN;
    }
    if (n >= ne) return;

    int lane = tid & 31, warp = tid >> 5;
    int mtile = warp & 3, ntile = warp >> 2;

    // prologue: A(n) slab + first K batch
    {
        const char* sA = (const char*)(g_A16 + (size_t)n * ACOLS);
        for (int i = tid; i < 1028; i += 256) {
            int srcoff, dstoff;
            if (i < 1024) { srcoff = i * 16; dstoff = (i >> 2) * 80 + (i & 3) * 16; }
            else { int q = i - 1024; srcoff = 16384 + q * 16; dstoff = 256 * 80 + q * 16; }
            cpa16((char*)Ahs + dstoff, sA + srcoff);
        }
        cpa_commit();
        int cnt0 = min(64, endN - begN);
        const char* kp = (const char*)(g_K2 + (size_t)begN * 256);
        for (int i = tid; i < cnt0 * 32; i += 256)
            cpa16((char*)K2b + (i >> 5) * KSB * 2 + (i & 31) * 16, kp + i * 16);
        cpa_commit();
    }

    int base = 0, kpar = 0, prevn = n;
    while (n < ne) {
        int nE = endN - begN;
        int cnt = min(64, nE - base);
        if (n != prevn) {
            const char* sA = (const char*)(g_A16 + (size_t)n * ACOLS);
            for (int i = tid; i < 1028; i += 256) {
                int srcoff, dstoff;
                if (i < 1024) { srcoff = i * 16; dstoff = (i >> 2) * 80 + (i & 3) * 16; }
                else { int q = i - 1024; srcoff = 16384 + q * 16; dstoff = 256 * 80 + q * 16; }
                cpa16((char*)Ahs + dstoff, sA + srcoff);
            }
            cpa_commit();
            prevn = n;
        }
        int n2 = n, base2 = base + 64, beg2 = begN, end2 = endN;
        if (base2 >= nE) {
            base2 = 0; n2 = n + 1; beg2 = endN;
            while (n2 < ne) {
                end2 = g_coloff[n2 + 1];
                if (end2 > beg2) break;
                n2++; beg2 = end2;
            }
        }
        if (n2 < ne) {
            int cnt2 = min(64, end2 - beg2 - base2);
            const char* kp = (const char*)(g_K2 + (size_t)(beg2 + base2) * 256);
            unsigned short* Kn = K2b + (kpar ^ 1) * 64 * KSB;
            for (int i = tid; i < cnt2 * 32; i += 256)
                cpa16((char*)Kn + (i >> 5) * KSB * 2 + (i & 31) * 16, kp + i * 16);
        }
        cpa_commit();
        cpa_wait1();
        __syncthreads();

        // ---- fp16 tensor-core GEMM: M[64x32] = K2[64x256] @ A[256x32] ----
        unsigned short* Kc = K2b + kpar * 64 * KSB;
        unsigned aK = sptr(Kc + (mtile * 16 + (lane & 15)) * KSB) + (lane >> 4) * 16;
        unsigned bA = sptr(Ahs + (lane & 15) * AST + ntile * 16 + (lane >> 4) * 8);
        float acc0[4] = {0.f, 0.f, 0.f, 0.f};
        float acc1[4] = {0.f, 0.f, 0.f, 0.f};
        #pragma unroll
        for (int ks = 0; ks < 16; ks++) {
            unsigned a[4], bf[4];
            ldsm4(a, aK + ks * 32);
            ldsm4t(bf, bA + ks * 1280);
            mma_f16(acc0, a, bf[0], bf[1]);
            mma_f16(acc1, a, bf[2], bf[3]);
        }
        int grp = lane >> 2, tig = lane & 3;
        int r0 = mtile * 16 + grp, r1 = r0 + 8;
        int col0 = ntile * 16 + tig * 2, col1 = col0 + 8;
        {
            float b00 = h2f(Ahs[256 * AST + col0]);
            float b01 = h2f(Ahs[256 * AST + col0 + 1]);
            float b10 = h2f(Ahs[256 * AST + col1]);
            float b11 = h2f(Ahs[256 * AST + col1 + 1]);
            Ms[r0 * MST + col0]     = acc0[0] + b00;
            Ms[r0 * MST + col0 + 1] = acc0[1] + b01;
            Ms[r1 * MST + col0]     = acc0[2] + b00;
            Ms[r1 * MST + col0 + 1] = acc0[3] + b01;
            Ms[r0 * MST + col1]     = acc1[0] + b10;
            Ms[r0 * MST + col1 + 1] = acc1[1] + b11;
            Ms[r1 * MST + col1]     = acc1[2] + b10;
            Ms[r1 * MST + col1 + 1] = acc1[3] + b11;
        }
        __syncthreads();

        // ---- MLP + scatter: 8 warps x 8 edges ----
        #pragma unroll 2
        for (int q = 0; q < 8; q++) {
            int es = warp * 8 + q;
            if (es < cnt) {
                const float* mrow = &Ms[es * MST];
                float t0 = 0.f, t1 = 0.f, t2 = 0.f, t3 = 0.f;
                #pragma unroll
                for (int j = 0; j < 32; j += 4) {
                    t0 += mrow[j]     * c1s[j * 32 + lane];
                    t1 += mrow[j + 1] * c1s[(j + 1) * 32 + lane];
                    t2 += mrow[j + 2] * c1s[(j + 2) * 32 + lane];
                    t3 += mrow[j + 3] * c1s[(j + 3) * 32 + lane];
                }
                float t = fmaxf(c1bs[lane] + ((t0 + t1) + (t2 + t3)), 0.f);
                float p = t * c2s[lane];
                #pragma unroll
                for (int off = 16; off > 0; off >>= 1)
                    p += __shfl_xor_sync(0xffffffffu, p, off);
                float we = p + cm2bv;
                int row = g_rows[begN + base + es];
                atomicAdd(&g_AGG[row * 32 + lane], mrow[lane]);
                if (lane < 3) {
                    float d = g_COORD[row * 3 + lane] - g_COORD[n * 3 + lane];
                    atomicAdd(&g_CD[row * 3 + lane], d * we);
                }
            }
        }
        __syncthreads();
        n = n2; base = base2; begN = beg2; endN = end2;
        kpar ^= 1;
    }
}

__global__ void k_update() {
    int i = blockIdx.x * blockDim.x + threadIdx.x;
    if (i < NN * WD) {
        int n = i >> 5;
        float inv = 1.f / g_CNT[n];
        g_H[i] = fmaxf(g_H[i] + g_AGG[i] * inv, 0.f);
        g_AGG[i] = 0.f;
    }
    if (i < NN * 3) {
        int n = i / 3;
        g_COORD[i] += g_CD[i] / g_CNT[n];
        g_CD[i] = 0.f;
    }
}

__global__ void k_final(const float* __restrict__ f2aw, const float* __restrict__ f2ab,
                        const float* __restrict__ f2bw, const float* __restrict__ f2bb,
                        float* __restrict__ out) {
    __shared__ float wa[2048];
    __shared__ float ba[64];
    __shared__ float wb[64];
    int tid = threadIdx.x;
    for (int i = tid; i < 2048; i += 256) wa[i] = f2aw[i];
    if (tid < 64) { ba[tid] = f2ab[tid]; wb[tid] = f2bw[tid]; }
    __syncthreads();
    int n = blockIdx.x * blockDim.x + tid;
    if (n < NN) {
        float h[32];
        #pragma unroll
        for (int j = 0; j < 32; j++) h[j] = g_H[n * 32 + j];
        float o = f2bb[0];
        #pragma unroll 4
        for (int u = 0; u < 64; u++) {
            float s = ba[u];
            #pragma unroll
            for (int j = 0; j < 32; j++) s += h[j] * wa[j * 64 + u];
            o += fmaxf(s, 0.f) * wb[u];
        }
        out[n] = o;
    }
    int tot = gridDim.x * blockDim.x;
    for (int i = n; i < NN * 3; i += tot) out[NN + i] = g_COORD[i];
}

// ---------------- host ----------------
extern "C" void kernel_launch(void* const* d_in, const int* in_sizes, int n_in,
                              void* d_out, int out_size) {
    const float* x      = (const float*)d_in[0];
    const int*   ei     = (const int*)d_in[1];     // int32 (JAX x64 disabled)
    const float* ea     = (const float*)d_in[2];
    const float* coords = (const float*)d_in[3];
    const float* fc1w   = (const float*)d_in[4];
    const float* fc1b   = (const float*)d_in[5];
    const float* k1w    = (const float*)d_in[6];
    const float* k1b    = (const float*)d_in[7];
    const float* k2w    = (const float*)d_in[8];
    const float* k2b    = (const float*)d_in[9];
    const float* k3w    = (const float*)d_in[10];
    const float* k3b    = (const float*)d_in[11];
    const float* cm1w   = (const float*)d_in[12];
    const float* cm1b   = (const float*)d_in[13];
    const float* cm2w   = (const float*)d_in[14];
    const float* cm2b   = (const float*)d_in[15];
    const float* f2aw   = (const float*)d_in[16];
    const float* f2ab   = (const float*)d_in[17];
    const float* f2bw   = (const float*)d_in[18];
    const float* f2bb   = (const float*)d_in[19];

    const int smemM  = (257 * AST + 2 * 64 * KSB) * 2 + 64 * MST * 4;      // 96848 B
    const int smemG2 = (2 * 64 * RST + 2 * 128 * WST) * 2 + 256 * 4;       // 171008 B
    cudaFuncSetAttribute(k_m, cudaFuncAttributeMaxDynamicSharedMemorySize, smemM);
    cudaFuncSetAttribute(k_gemm2, cudaFuncAttributeMaxDynamicSharedMemorySize, smemG2);

    // slot 4 = k_gemmA (profiler capture target)
    k_init<<<(NN * WD + 255) / 256, 256>>>(x, coords, fc1w, fc1b);      // 1
    k_aw<<<(32 * ACOLS + 255) / 256, 256>>>(k3w, k3b);                  // 2
    k_hist<<<(EE + 255) / 256, 256>>>(ei);                              // 3
    k_gemmA<<<dim3((ACOLS + 255) / 256, (NN + 63) / 64), 256>>>();      // 4 (layer 0)
    k_scan<<<1, 1024>>>();                                              // 5
    k_w2<<<(128 * 256 + 255) / 256, 256>>>(k2w);                        // 6
    k_scatter<<<(EE + 255) / 256, 256>>>(ei);                           // 7
    k_gemm2<<<(EE + 63) / 64, 256, smemG2>>>(ea, k1w, k1b, k2b);        // 8

    for (int d = 0; d < DEPTH; d++) {
        if (d > 0)
            k_gemmA<<<dim3((ACOLS + 255) / 256, (NN + 63) / 64), 256>>>();
        k_m<<<NBLK, 256, smemM>>>(cm1w, cm1b, cm2w, cm2b);
        k_update<<<(NN * WD + 255) / 256, 256>>>();
    }
    k_final<<<(NN + 255) / 256, 256>>>(f2aw, f2ab, f2bw, f2bb, (float*)d_out);
    k_cleanup<<<(NN + 255) / 256, 256>>>();
}

// round 17
// speedup vs baseline: 2.4549x; 1.1598x over previous
#include <cuda_runtime.h>
#include <cuda_bf16.h>
#include <cuda_fp16.h>
#include <cstdint>

#define NN 10000
#define EE 300000
#define WD 32
#define DEPTH 4
#define ACOLS 8224           // 8192 (A) + 32 (bias part)
#define NBLK 296             // persistent k_m blocks (2 per SM)
#define RST 136              // R1 smem row stride (ushort)
#define WST 264              // W2/AW smem row stride (ushort)
#define KSB 264              // k_m K2 smem row stride (ushort)
#define AST 40               // k_m A-slab smem row stride (ushort)
#define MST 34               // Ms row stride (float)

// ---------------- scratch (static __device__) ----------------
__device__ __align__(16) unsigned short g_K2[(size_t)EE * 256];    // K2 fp16, PERMUTED
__device__ __align__(16) unsigned short g_A16[(size_t)NN * ACOLS]; // A slab fp16
__device__ __align__(16) unsigned short g_AWhi[32 * ACOLS];
__device__ __align__(16) unsigned short g_AWlo[32 * ACOLS];
__device__ __align__(16) unsigned short g_W2f[128 * 256];          // W2 fp16
__device__ __align__(16) float g_H[NN * WD];
__device__ __align__(16) float g_AGG[NN * WD];
__device__ __align__(16) float g_COORD[NN * 3];
__device__ __align__(16) float g_CD[NN * 3];
__device__ float g_CNT[NN];
__device__ int   g_colcnt[NN];
__device__ int   g_rowcnt[NN];
__device__ int   g_coloff[NN + 1];
__device__ int   g_cur[NN];
__device__ int   g_pos[EE];
__device__ int   g_rows[EE];

// ---------------- helpers ----------------
__device__ __forceinline__ void cpa16(void* smem_dst, const void* gsrc) {
    unsigned s = (unsigned)__cvta_generic_to_shared(smem_dst);
    asm volatile("cp.async.cg.shared.global [%0], [%1], 16;\n" :: "r"(s), "l"(gsrc));
}
__device__ __forceinline__ void cpa_commit() { asm volatile("cp.async.commit_group;\n"); }
__device__ __forceinline__ void cpa_wait1()  { asm volatile("cp.async.wait_group 1;\n"); }
__device__ __forceinline__ void cpa_wait0()  { asm volatile("cp.async.wait_group 0;\n"); }

__device__ __forceinline__ void bfsplit(float x, unsigned short& h, unsigned short& l) {
    __nv_bfloat16 bh = __float2bfloat16(x);
    h = *reinterpret_cast<unsigned short*>(&bh);
    float r = x - __bfloat162float(bh);
    __nv_bfloat16 bl = __float2bfloat16(r);
    l = *reinterpret_cast<unsigned short*>(&bl);
}
__device__ __forceinline__ unsigned short f2h(float x) {
    __half h = __float2half(x);
    return *reinterpret_cast<unsigned short*>(&h);
}
__device__ __forceinline__ float h2f(unsigned short u) {
    __half h = *reinterpret_cast<__half*>(&u);
    return __half2float(h);
}
__device__ __forceinline__ unsigned sptr(const void* p) {
    return (unsigned)__cvta_generic_to_shared(p);
}
__device__ __forceinline__ void ldsm4(unsigned* r, unsigned a) {
    asm volatile("ldmatrix.sync.aligned.m8n8.x4.shared.b16 {%0,%1,%2,%3}, [%4];"
        : "=r"(r[0]), "=r"(r[1]), "=r"(r[2]), "=r"(r[3]) : "r"(a));
}
__device__ __forceinline__ void ldsm4t(unsigned* r, unsigned a) {
    asm volatile("ldmatrix.sync.aligned.m8n8.x4.trans.shared.b16 {%0,%1,%2,%3}, [%4];"
        : "=r"(r[0]), "=r"(r[1]), "=r"(r[2]), "=r"(r[3]) : "r"(a));
}
__device__ __forceinline__ void mma_bf16(float* c, const unsigned* a, unsigned b0, unsigned b1) {
    asm volatile("mma.sync.aligned.m16n8k16.row.col.f32.bf16.bf16.f32 "
        "{%0,%1,%2,%3},{%4,%5,%6,%7},{%8,%9},{%0,%1,%2,%3};"
        : "+f"(c[0]), "+f"(c[1]), "+f"(c[2]), "+f"(c[3])
        : "r"(a[0]), "r"(a[1]), "r"(a[2]), "r"(a[3]), "r"(b0), "r"(b1));
}
__device__ __forceinline__ void mma_f16(float* c, const unsigned* a, unsigned b0, unsigned b1) {
    asm volatile("mma.sync.aligned.m16n8k16.row.col.f32.f16.f16.f32 "
        "{%0,%1,%2,%3},{%4,%5,%6,%7},{%8,%9},{%0,%1,%2,%3};"
        : "+f"(c[0]), "+f"(c[1]), "+f"(c[2]), "+f"(c[3])
        : "r"(a[0]), "r"(a[1]), "r"(a[2]), "r"(a[3]), "r"(b0), "r"(b1));
}

// ---------------- setup ----------------
__global__ void k_init(const float* __restrict__ x, const float* __restrict__ coords,
                       const float* __restrict__ fc1w, const float* __restrict__ fc1b) {
    int i = blockIdx.x * blockDim.x + threadIdx.x;
    if (i < NN * 3) g_COORD[i] = coords[i];
    if (i < NN * WD) {
        int n = i / WD, o = i % WD;
        float a = fc1b[o];
        #pragma unroll
        for (int j = 0; j < 3; j++) a += x[n * 3 + j] * fc1w[j * WD + o];
        g_H[i] = a;
    }
}

__global__ void k_hist(const int* __restrict__ ei) {
    int e = blockIdx.x * blockDim.x + threadIdx.x;
    if (e < EE) {
        atomicAdd(&g_rowcnt[ei[e]], 1);
        atomicAdd(&g_colcnt[ei[EE + e]], 1);
    }
}

__global__ void k_scan() {
    __shared__ int sh[1024];
    __shared__ int carry;
    int t = threadIdx.x;
    if (t == 0) carry = 0;
    __syncthreads();
    for (int base = 0; base < NN; base += 1024) {
        int v = (base + t < NN) ? g_colcnt[base + t] : 0;
        sh[t] = v;
        __syncthreads();
        for (int off = 1; off < 1024; off <<= 1) {
            int y = (t >= off) ? sh[t - off] : 0;
            __syncthreads();
            sh[t] += y;
            __syncthreads();
        }
        int incl = sh[t];
        if (base + t < NN) {
            int ex = carry + incl - v;
            g_coloff[base + t] = ex;
            g_cur[base + t] = ex;
            g_CNT[base + t] = fmaxf(1.f, (float)g_rowcnt[base + t]);
        }
        int tot = sh[1023];
        __syncthreads();
        if (t == 0) carry += tot;
        __syncthreads();
    }
    if (t == 0) g_coloff[NN] = carry;
}

__global__ void k_scatter(const int* __restrict__ ei) {
    int e = blockIdx.x * blockDim.x + threadIdx.x;
    if (e < EE) {
        int r = ei[e], c = ei[EE + e];
        int p = atomicAdd(&g_cur[c], 1);
        g_pos[e] = p;
        g_rows[p] = r;
    }
}

__global__ void k_cleanup() {
    int i = blockIdx.x * blockDim.x + threadIdx.x;
    if (i < NN) { g_colcnt[i] = 0; g_rowcnt[i] = 0; }
}

// W2 -> fp16 once
__global__ void k_w2(const float* __restrict__ w2) {
    int i = blockIdx.x * blockDim.x + threadIdx.x;
    if (i < 128 * 256) g_W2f[i] = f2h(w2[i]);
}

// ---------------- gemm2: K2 = relu(relu(ea@W1+b1)@W2+b2), single fp16 mma ------
__global__ void __launch_bounds__(256, 2) k_gemm2(const float* __restrict__ ea,
                                                  const float* __restrict__ w1,
                                                  const float* __restrict__ b1,
                                                  const float* __restrict__ b2) {
    extern __shared__ unsigned short s2u[];
    unsigned short* R1f = s2u;                  // [64][RST]
    unsigned short* W2f = s2u + 64 * RST;       // [128][WST]
    float* b2s = (float*)(W2f + 128 * WST);     // [256]
    __shared__ float eas[64 * 6];
    __shared__ float w1s[6 * 128];
    __shared__ float b1s[128];
    int tid = threadIdx.x;
    int m0 = blockIdx.x * 64;

    // async stage W2 fp16 (overlapped with R1 compute below)
    {
        const char* src = (const char*)g_W2f;
        for (int i = tid; i < 4096; i += 256) {
            int dst = (i >> 5) * (WST * 2) + (i & 31) * 16;
            cpa16((char*)W2f + dst, src + i * 16);
        }
        cpa_commit();
    }
    for (int i = tid; i < 64 * 6; i += 256) {
        int g = m0 * 6 + i;
        eas[i] = (g < EE * 6) ? ea[g] : 0.f;
    }
    for (int i = tid; i < 768; i += 256) w1s[i] = w1[i];
    if (tid < 128) b1s[tid] = b1[tid];
    b2s[tid] = b2[tid];
    __syncthreads();

    {
        int r = tid & 63, kg = tid >> 6;
        float ev[6];
        #pragma unroll
        for (int j = 0; j < 6; j++) ev[j] = eas[r * 6 + j];
        #pragma unroll
        for (int q = 0; q < 32; q += 2) {
            int k0 = kg * 32 + q;
            float a0 = b1s[k0], a1 = b1s[k0 + 1];
            #pragma unroll
            for (int j = 0; j < 6; j++) {
                a0 += ev[j] * w1s[j * 128 + k0];
                a1 += ev[j] * w1s[j * 128 + k0 + 1];
            }
            a0 = fmaxf(a0, 0.f); a1 = fmaxf(a1, 0.f);
            *(unsigned*)&R1f[r * RST + k0] = ((unsigned)f2h(a1) << 16) | f2h(a0);
        }
    }
    cpa_wait0();
    __syncthreads();

    int lane = tid & 31, warp = tid >> 5;
    int mb = (warp >> 2) * 32, nb = (warp & 3) * 64;
    unsigned aF0 = sptr(&R1f[(mb + (lane & 15)) * RST]) + (lane >> 4) * 16;
    unsigned aF1 = aF0 + 16 * RST * 2;
    unsigned bF  = sptr(&W2f[(lane & 15) * WST + nb + (lane >> 4) * 8]);
    float acc[2][8][4];
    #pragma unroll
    for (int i = 0; i < 2; i++)
        #pragma unroll
        for (int j = 0; j < 8; j++)
            #pragma unroll
            for (int q = 0; q < 4; q++) acc[i][j][q] = 0.f;

    #pragma unroll
    for (int ks = 0; ks < 8; ks++) {
        unsigned a0[4], a1[4];
        ldsm4(a0, aF0 + ks * 32);
        ldsm4(a1, aF1 + ks * 32);
        unsigned bA = bF + ks * 16 * WST * 2;
        #pragma unroll
        for (int p = 0; p < 4; p++) {
            unsigned bf[4];
            ldsm4t(bf, bA + p * 32);
            mma_f16(acc[0][2 * p],     a0, bf[0], bf[1]);
            mma_f16(acc[0][2 * p + 1], a0, bf[2], bf[3]);
            mma_f16(acc[1][2 * p],     a1, bf[0], bf[1]);
            mma_f16(acc[1][2 * p + 1], a1, bf[2], bf[3]);
        }
    }

    int grp = lane >> 2, tig = lane & 3;
    #pragma unroll
    for (int mt = 0; mt < 2; mt++) {
        #pragma unroll
        for (int half = 0; half < 2; half++) {
            int e = m0 + mb + mt * 16 + grp + half * 8;
            if (e < EE) {
                size_t prow = (size_t)g_pos[e] * 256;
                #pragma unroll
                for (int n8 = 0; n8 < 8; n8++) {
                    int col = nb + n8 * 8 + tig * 2;
                    float v0 = fmaxf(acc[mt][n8][half * 2]     + b2s[col],     0.f);
                    float v1 = fmaxf(acc[mt][n8][half * 2 + 1] + b2s[col + 1], 0.f);
                    *(unsigned*)&g_K2[prow + col] = ((unsigned)f2h(v1) << 16) | f2h(v0);
                }
            }
        }
    }
}

// AW split bf16
__global__ void k_aw(const float* __restrict__ w3, const float* __restrict__ b3) {
    int idx = blockIdx.x * blockDim.x + threadIdx.x;
    if (idx >= 32 * ACOLS) return;
    int j = idx / ACOLS, r = idx % ACOLS;
    float v;
    if (r < 8192) {
        int c = r >> 5, i = r & 31;
        v = w3[c * 1024 + i * 32 + j];
    } else {
        v = b3[(r - 8192) * 32 + j];
    }
    unsigned short h, l;
    bfsplit(v, h, l);
    g_AWhi[idx] = h;
    g_AWlo[idx] = l;
}

// A = H @ AW via 3-term split-bf16 mma — persistent n-loop, AW double-buffered.
// grid (2, 157): y = 64-node m-tile; x = n-half (tiles 0..16 / 17..32).
__global__ void __launch_bounds__(256) k_gemmA() {
    __shared__ unsigned short Hh[64 * 40];
    __shared__ unsigned short Hl[64 * 40];
    extern __shared__ unsigned short awbuf[];   // 2 bufs x (AWh|AWl) x [32][WST]
    int tid = threadIdx.x;
    int m0 = blockIdx.y * 64;
    int t0 = blockIdx.x * 17;
    int nt = (blockIdx.x == 0) ? 17 : 16;

    // stage H (split bf16)
    for (int i = tid; i < 1024; i += 256) {
        int node = i >> 4, kp = i & 15;
        float2 v = make_float2(0.f, 0.f);
        if (m0 + node < NN) v = *(const float2*)&g_H[(m0 + node) * 32 + kp * 2];
        unsigned short hx, lx, hy, ly;
        bfsplit(v.x, hx, lx);
        bfsplit(v.y, hy, ly);
        *(unsigned*)&Hh[node * 40 + kp * 2] = ((unsigned)hy << 16) | hx;
        *(unsigned*)&Hl[node * 40 + kp * 2] = ((unsigned)ly << 16) | lx;
    }

    // prologue: stage first AW tile into buf 0
    {
        int n0 = t0 * 256;
        for (int i = tid; i < 2048; i += 256) {
            int comp = i >> 10, rem = i & 1023, row = rem >> 5, c16 = rem & 31;
            int col = n0 + c16 * 8;
            if (col < ACOLS) {
                const unsigned short* src =
                    (comp ? g_AWlo : g_AWhi) + (size_t)row * ACOLS + col;
                cpa16(awbuf + comp * (32 * WST) + row * WST + c16 * 8, src);
            }
        }
        cpa_commit();
    }

    int lane = tid & 31, warp = tid >> 5;
    int mb = (warp >> 2) * 32, nb = (warp & 3) * 64;
    int grp = lane >> 2, tig = lane & 3;
    unsigned aH0 = sptr(&Hh[(mb + (lane & 15)) * 40]) + (lane >> 4) * 16;
    unsigned aH1 = aH0 + 16 * 40 * 2;
    unsigned aL0 = sptr(&Hl[(mb + (lane & 15)) * 40]) + (lane >> 4) * 16;
    unsigned aL1 = aL0 + 16 * 40 * 2;

    for (int t = 0; t < nt; t++) {
        if (t + 1 < nt) {
            int n0 = (t0 + t + 1) * 256;
            unsigned short* dstb = awbuf + ((t + 1) & 1) * (2 * 32 * WST);
            for (int i = tid; i < 2048; i += 256) {
                int comp = i >> 10, rem = i & 1023, row = rem >> 5, c16 = rem & 31;
                int col = n0 + c16 * 8;
                if (col < ACOLS) {
                    const unsigned short* src =
                        (comp ? g_AWlo : g_AWhi) + (size_t)row * ACOLS + col;
                    cpa16(dstb + comp * (32 * WST) + row * WST + c16 * 8, src);
                }
            }
        }
        cpa_commit();
        cpa_wait1();
        __syncthreads();

        unsigned short* AWh = awbuf + (t & 1) * (2 * 32 * WST);
        unsigned short* AWl = AWh + 32 * WST;
        unsigned bH = sptr(&AWh[(lane & 15) * WST + nb + (lane >> 4) * 8]);
        unsigned bL = sptr(&AWl[(lane & 15) * WST + nb + (lane >> 4) * 8]);
        float acc[2][8][4];
        #pragma unroll
        for (int i = 0; i < 2; i++)
            #pragma unroll
            for (int j = 0; j < 8; j++)
                #pragma unroll
                for (int q = 0; q < 4; q++) acc[i][j][q] = 0.f;

        #pragma unroll
        for (int ks = 0; ks < 2; ks++) {
            unsigned ah0[4], ah1[4], al0[4], al1[4];
            ldsm4(ah0, aH0 + ks * 32);
            ldsm4(ah1, aH1 + ks * 32);
            ldsm4(al0, aL0 + ks * 32);
            ldsm4(al1, aL1 + ks * 32);
            unsigned bHA = bH + ks * 16 * WST * 2;
            unsigned bLA = bL + ks * 16 * WST * 2;
            #pragma unroll
            for (int p = 0; p < 4; p++) {
                unsigned bh[4], bl[4];
                ldsm4t(bh, bHA + p * 32);
                ldsm4t(bl, bLA + p * 32);
                mma_bf16(acc[0][2 * p],     ah0, bh[0], bh[1]);
                mma_bf16(acc[0][2 * p],     ah0, bl[0], bl[1]);
                mma_bf16(acc[0][2 * p],     al0, bh[0], bh[1]);
                mma_bf16(acc[0][2 * p + 1], ah0, bh[2], bh[3]);
                mma_bf16(acc[0][2 * p + 1], ah0, bl[2], bl[3]);
                mma_bf16(acc[0][2 * p + 1], al0, bh[2], bh[3]);
                mma_bf16(acc[1][2 * p],     ah1, bh[0], bh[1]);
                mma_bf16(acc[1][2 * p],     ah1, bl[0], bl[1]);
                mma_bf16(acc[1][2 * p],     al1, bh[0], bh[1]);
                mma_bf16(acc[1][2 * p + 1], ah1, bh[2], bh[3]);
                mma_bf16(acc[1][2 * p + 1], ah1, bl[2], bl[3]);
                mma_bf16(acc[1][2 * p + 1], al1, bh[2], bh[3]);
            }
        }

        int n0 = (t0 + t) * 256;
        #pragma unroll
        for (int mt = 0; mt < 2; mt++) {
            #pragma unroll
            for (int half = 0; half < 2; half++) {
                int node = m0 + mb + mt * 16 + grp + half * 8;
                if (node < NN) {
                    size_t nrow = (size_t)node * ACOLS;
                    #pragma unroll
                    for (int n8 = 0; n8 < 8; n8++) {
                        int col = n0 + nb + n8 * 8 + tig * 2;
                        if (col < ACOLS) {
                            unsigned short h0 = f2h(acc[mt][n8][half * 2]);
                            unsigned short h1 = f2h(acc[mt][n8][half * 2 + 1]);
                            *(unsigned*)&g_A16[nrow + col] = ((unsigned)h1 << 16) | h0;
                        }
                    }
                }
            }
        }
        __syncthreads();
    }
}

// persistent fused M(fp16 tensor-core) + coord-MLP + scatter. (unchanged from R16)
__global__ void __launch_bounds__(256, 2) k_m(const float* __restrict__ cm1w,
                                              const float* __restrict__ cm1b,
                                              const float* __restrict__ cm2w,
                                              const float* __restrict__ cm2b) {
    extern __shared__ unsigned short smu[];
    unsigned short* Ahs = smu;                         // 257*AST (row 256 = bias)
    unsigned short* K2b = Ahs + 257 * AST;             // 2 buffers x 64*KSB
    float* Ms = (float*)(K2b + 2 * 64 * KSB);          // 64*MST
    __shared__ float c1s[1024];
    __shared__ float c1bs[32], c2s[32];
    __shared__ float cm2bv;
    __shared__ int nsS, neS;
    int tid = threadIdx.x;
    int b = blockIdx.x;
    if (tid == 0) {
        long long t1 = (long long)b * EE;
        int lo = 0, hi = NN;
        while (lo < hi) {
            int mid = (lo + hi) >> 1;
            if ((long long)g_coloff[mid] * NBLK >= t1) hi = mid; else lo = mid + 1;
        }
        nsS = lo;
        long long t2 = (long long)(b + 1) * EE;
        hi = NN;
        while (lo < hi) {
            int mid = (lo + hi) >> 1;
            if ((long long)g_coloff[mid] * NBLK >= t2) hi = mid; else lo = mid + 1;
        }
        neS = lo;
        cm2bv = cm2b[0];
    }
    for (int i = tid; i < 1024; i += 256) c1s[i] = cm1w[i];
    if (tid < 32) { c1bs[tid] = cm1b[tid]; c2s[tid] = cm2w[tid]; }
    __syncthreads();
    int ns = nsS, ne = neS;

    int n = ns;
    int begN = (n < ne) ? g_coloff[n] : 0, endN = begN;
    while (n < ne) {
        endN = g_coloff[n + 1];
        if (endN > begN) break;
        n++; begN = endN;
    }
    if (n >= ne) return;

    int lane = tid & 31, warp = tid >> 5;
    int mtile = warp & 3, ntile = warp >> 2;

    {
        const char* sA = (const char*)(g_A16 + (size_t)n * ACOLS);
        for (int i = tid; i < 1028; i += 256) {
            int srcoff, dstoff;
            if (i < 1024) { srcoff = i * 16; dstoff = (i >> 2) * 80 + (i & 3) * 16; }
            else { int q = i - 1024; srcoff = 16384 + q * 16; dstoff = 256 * 80 + q * 16; }
            cpa16((char*)Ahs + dstoff, sA + srcoff);
        }
        cpa_commit();
        int cnt0 = min(64, endN - begN);
        const char* kp = (const char*)(g_K2 + (size_t)begN * 256);
        for (int i = tid; i < cnt0 * 32; i += 256)
            cpa16((char*)K2b + (i >> 5) * KSB * 2 + (i & 31) * 16, kp + i * 16);
        cpa_commit();
    }

    int base = 0, kpar = 0, prevn = n;
    while (n < ne) {
        int nE = endN - begN;
        int cnt = min(64, nE - base);
        if (n != prevn) {
            const char* sA = (const char*)(g_A16 + (size_t)n * ACOLS);
            for (int i = tid; i < 1028; i += 256) {
                int srcoff, dstoff;
                if (i < 1024) { srcoff = i * 16; dstoff = (i >> 2) * 80 + (i & 3) * 16; }
                else { int q = i - 1024; srcoff = 16384 + q * 16; dstoff = 256 * 80 + q * 16; }
                cpa16((char*)Ahs + dstoff, sA + srcoff);
            }
            cpa_commit();
            prevn = n;
        }
        int n2 = n, base2 = base + 64, beg2 = begN, end2 = endN;
        if (base2 >= nE) {
            base2 = 0; n2 = n + 1; beg2 = endN;
            while (n2 < ne) {
                end2 = g_coloff[n2 + 1];
                if (end2 > beg2) break;
                n2++; beg2 = end2;
            }
        }
        if (n2 < ne) {
            int cnt2 = min(64, end2 - beg2 - base2);
            const char* kp = (const char*)(g_K2 + (size_t)(beg2 + base2) * 256);
            unsigned short* Kn = K2b + (kpar ^ 1) * 64 * KSB;
            for (int i = tid; i < cnt2 * 32; i += 256)
                cpa16((char*)Kn + (i >> 5) * KSB * 2 + (i & 31) * 16, kp + i * 16);
        }
        cpa_commit();
        cpa_wait1();
        __syncthreads();

        unsigned short* Kc = K2b + kpar * 64 * KSB;
        unsigned aK = sptr(Kc + (mtile * 16 + (lane & 15)) * KSB) + (lane >> 4) * 16;
        unsigned bA = sptr(Ahs + (lane & 15) * AST + ntile * 16 + (lane >> 4) * 8);
        float acc0[4] = {0.f, 0.f, 0.f, 0.f};
        float acc1[4] = {0.f, 0.f, 0.f, 0.f};
        #pragma unroll
        for (int ks = 0; ks < 16; ks++) {
            unsigned a[4], bf[4];
            ldsm4(a, aK + ks * 32);
            ldsm4t(bf, bA + ks * 1280);
            mma_f16(acc0, a, bf[0], bf[1]);
            mma_f16(acc1, a, bf[2], bf[3]);
        }
        int grp = lane >> 2, tig = lane & 3;
        int r0 = mtile * 16 + grp, r1 = r0 + 8;
        int col0 = ntile * 16 + tig * 2, col1 = col0 + 8;
        {
            float b00 = h2f(Ahs[256 * AST + col0]);
            float b01 = h2f(Ahs[256 * AST + col0 + 1]);
            float b10 = h2f(Ahs[256 * AST + col1]);
            float b11 = h2f(Ahs[256 * AST + col1 + 1]);
            Ms[r0 * MST + col0]     = acc0[0] + b00;
            Ms[r0 * MST + col0 + 1] = acc0[1] + b01;
            Ms[r1 * MST + col0]     = acc0[2] + b00;
            Ms[r1 * MST + col0 + 1] = acc0[3] + b01;
            Ms[r0 * MST + col1]     = acc1[0] + b10;
            Ms[r0 * MST + col1 + 1] = acc1[1] + b11;
            Ms[r1 * MST + col1]     = acc1[2] + b10;
            Ms[r1 * MST + col1 + 1] = acc1[3] + b11;
        }
        __syncthreads();

        #pragma unroll 2
        for (int q = 0; q < 8; q++) {
            int es = warp * 8 + q;
            if (es < cnt) {
                const float* mrow = &Ms[es * MST];
                float t0 = 0.f, t1 = 0.f, t2 = 0.f, t3 = 0.f;
                #pragma unroll
                for (int j = 0; j < 32; j += 4) {
                    t0 += mrow[j]     * c1s[j * 32 + lane];
                    t1 += mrow[j + 1] * c1s[(j + 1) * 32 + lane];
                    t2 += mrow[j + 2] * c1s[(j + 2) * 32 + lane];
                    t3 += mrow[j + 3] * c1s[(j + 3) * 32 + lane];
                }
                float t = fmaxf(c1bs[lane] + ((t0 + t1) + (t2 + t3)), 0.f);
                float p = t * c2s[lane];
                #pragma unroll
                for (int off = 16; off > 0; off >>= 1)
                    p += __shfl_xor_sync(0xffffffffu, p, off);
                float we = p + cm2bv;
                int row = g_rows[begN + base + es];
                atomicAdd(&g_AGG[row * 32 + lane], mrow[lane]);
                if (lane < 3) {
                    float d = g_COORD[row * 3 + lane] - g_COORD[n * 3 + lane];
                    atomicAdd(&g_CD[row * 3 + lane], d * we);
                }
            }
        }
        __syncthreads();
        n = n2; base = base2; begN = beg2; endN = end2;
        kpar ^= 1;
    }
}

__global__ void k_update() {
    int i = blockIdx.x * blockDim.x + threadIdx.x;
    if (i < NN * WD) {
        int n = i >> 5;
        float inv = 1.f / g_CNT[n];
        g_H[i] = fmaxf(g_H[i] + g_AGG[i] * inv, 0.f);
        g_AGG[i] = 0.f;
    }
    if (i < NN * 3) {
        int n = i / 3;
        g_COORD[i] += g_CD[i] / g_CNT[n];
        g_CD[i] = 0.f;
    }
}

__global__ void k_final(const float* __restrict__ f2aw, const float* __restrict__ f2ab,
                        const float* __restrict__ f2bw, const float* __restrict__ f2bb,
                        float* __restrict__ out) {
    __shared__ float wa[2048];
    __shared__ float ba[64];
    __shared__ float wb[64];
    int tid = threadIdx.x;
    for (int i = tid; i < 2048; i += 256) wa[i] = f2aw[i];
    if (tid < 64) { ba[tid] = f2ab[tid]; wb[tid] = f2bw[tid]; }
    __syncthreads();
    int n = blockIdx.x * blockDim.x + tid;
    if (n < NN) {
        float h[32];
        #pragma unroll
        for (int j = 0; j < 32; j++) h[j] = g_H[n * 32 + j];
        float o = f2bb[0];
        #pragma unroll 4
        for (int u = 0; u < 64; u++) {
            float s = ba[u];
            #pragma unroll
            for (int j = 0; j < 32; j++) s += h[j] * wa[j * 64 + u];
            o += fmaxf(s, 0.f) * wb[u];
        }
        out[n] = o;
    }
    int tot = gridDim.x * blockDim.x;
    for (int i = n; i < NN * 3; i += tot) out[NN + i] = g_COORD[i];
}

// ---------------- host ----------------
extern "C" void kernel_launch(void* const* d_in, const int* in_sizes, int n_in,
                              void* d_out, int out_size) {
    const float* x      = (const float*)d_in[0];
    const int*   ei     = (const int*)d_in[1];     // int32 (JAX x64 disabled)
    const float* ea     = (const float*)d_in[2];
    const float* coords = (const float*)d_in[3];
    const float* fc1w   = (const float*)d_in[4];
    const float* fc1b   = (const float*)d_in[5];
    const float* k1w    = (const float*)d_in[6];
    const float* k1b    = (const float*)d_in[7];
    const float* k2w    = (const float*)d_in[8];
    const float* k2b    = (const float*)d_in[9];
    const float* k3w    = (const float*)d_in[10];
    const float* k3b    = (const float*)d_in[11];
    const float* cm1w   = (const float*)d_in[12];
    const float* cm1b   = (const float*)d_in[13];
    const float* cm2w   = (const float*)d_in[14];
    const float* cm2b   = (const float*)d_in[15];
    const float* f2aw   = (const float*)d_in[16];
    const float* f2ab   = (const float*)d_in[17];
    const float* f2bw   = (const float*)d_in[18];
    const float* f2bb   = (const float*)d_in[19];

    const int smemM  = (257 * AST + 2 * 64 * KSB) * 2 + 64 * MST * 4;  // 96848 B
    const int smemG2 = (64 * RST + 128 * WST) * 2 + 256 * 4;           // 86016 B
    const int smemGA = 2 * 2 * 32 * WST * 2;                           // 67584 B
    cudaFuncSetAttribute(k_m, cudaFuncAttributeMaxDynamicSharedMemorySize, smemM);
    cudaFuncSetAttribute(k_gemm2, cudaFuncAttributeMaxDynamicSharedMemorySize, smemG2);
    cudaFuncSetAttribute(k_gemmA, cudaFuncAttributeMaxDynamicSharedMemorySize, smemGA);

    // slot 4 = k_gemmA (profiler capture target)
    k_init<<<(NN * WD + 255) / 256, 256>>>(x, coords, fc1w, fc1b);      // 1
    k_aw<<<(32 * ACOLS + 255) / 256, 256>>>(k3w, k3b);                  // 2
    k_hist<<<(EE + 255) / 256, 256>>>(ei);                              // 3
    k_gemmA<<<dim3(2, (NN + 63) / 64), 256, smemGA>>>();                // 4 (layer 0)
    k_scan<<<1, 1024>>>();                                              // 5
    k_w2<<<(128 * 256 + 255) / 256, 256>>>(k2w);                        // 6
    k_scatter<<<(EE + 255) / 256, 256>>>(ei);                           // 7
    k_gemm2<<<(EE + 63) / 64, 256, smemG2>>>(ea, k1w, k1b, k2b);        // 8

    for (int d = 0; d < DEPTH; d++) {
        if (d > 0)
            k_gemmA<<<dim3(2, (NN + 63) / 64), 256, smemGA>>>();
        k_m<<<NBLK, 256, smemM>>>(cm1w, cm1b, cm2w, cm2b);
        k_update<<<(NN * WD + 255) / 256, 256>>>();
    }
    k_final<<<(NN + 255) / 256, 256>>>(f2aw, f2ab, f2bw, f2bb, (float*)d_out);
    k_cleanup<<<(NN + 255) / 256, 256>>>();
}